// round 8
// baseline (speedup 1.0000x reference)
#include <cuda_runtime.h>
#include <math.h>
#include <stdint.h>
#include <stddef.h>

// ---------------- problem dims ----------------
#define B_    64
#define N_    4096
#define DIN_  256
#define K_    8
#define D_    256
#define H_    512
#define BK_   512
#define SCALE_ 0.0625f
#define EPSLN 1e-5f
#define EPSA  1e-8f

typedef unsigned long long u64;

// ---------------- device scratch ----------------
__device__ __align__(16) float g_slots[BK_ * D_];
__device__ __align__(16) float g_gq[BK_ * D_];      // g ⊙ qt
__device__ float g_C1[BK_];
__device__ float g_C2[BK_];
__device__ __align__(16) float g_P[BK_ * D_];       // Σ a*rs*v
__device__ float g_SA[BK_];
__device__ float g_SW[BK_];
__device__ __align__(16) float g_Wqk[D_ * D_];
__device__ float g_bqk[D_];
__device__ float g_wb[D_];
__device__ float g_c0;
__device__ __align__(16) float g_WihT[D_ * 3 * D_];
__device__ __align__(16) float g_WhhT[D_ * 3 * D_];
__device__ __align__(16) float g_WvT[D_ * D_];
__device__ __align__(16) float g_W1T[D_ * H_];
__device__ __align__(16) float g_W2T[H_ * D_];

// ---------------- f32x2 packed helpers ----------------
__device__ __forceinline__ u64 pk2(float x, float y) {
    u64 r; asm("mov.b64 %0, {%1, %2};" : "=l"(r) : "f"(x), "f"(y)); return r;
}
__device__ __forceinline__ void upk2(u64 v, float& x, float& y) {
    asm("mov.b64 {%0, %1}, %2;" : "=f"(x), "=f"(y) : "l"(v));
}
__device__ __forceinline__ void fma2(u64& d, u64 a, u64 b) {
    asm("fma.rn.f32x2 %0, %1, %2, %0;" : "+l"(d) : "l"(a), "l"(b));
}

// ---------------- block reduce (2 values, 256 threads) ----------------
__device__ __forceinline__ void blockReduce2(float& a, float& b) {
    #pragma unroll
    for (int o = 16; o; o >>= 1) {
        a += __shfl_xor_sync(0xffffffffu, a, o);
        b += __shfl_xor_sync(0xffffffffu, b, o);
    }
    __shared__ float sa[8], sb[8];
    __syncthreads();
    int w = threadIdx.x >> 5;
    if ((threadIdx.x & 31) == 0) { sa[w] = a; sb[w] = b; }
    __syncthreads();
    a = sa[threadIdx.x & 7];
    b = sb[threadIdx.x & 7];
    #pragma unroll
    for (int o = 4; o; o >>= 1) {
        a += __shfl_xor_sync(0xffffffffu, a, o);
        b += __shfl_xor_sync(0xffffffffu, b, o);
    }
}

// ---------------- direct-LDG GEMV: acc[r] += s_in[r][k] * W[k][col_off+j] ----------------
// No barriers. Coalesced LDG per thread-column, LDS.128 input broadcast.
__device__ __forceinline__ void gemvDirect(const float* __restrict__ W, int rstride, int col_off, int K,
                                           const float* s_in, int in_stride, int j, float acc[4]) {
    const float* p = W + col_off + j;
    #pragma unroll 2
    for (int k0 = 0; k0 < K; k0 += 4) {
        float w0 = p[0];
        float w1 = p[rstride];
        float w2 = p[2 * rstride];
        float w3 = p[3 * rstride];
        p += 4 * rstride;
        #pragma unroll
        for (int r = 0; r < 4; r++) {
            float4 x = *(const float4*)(s_in + r * in_stride + k0);
            acc[r] = fmaf(x.x, w0, acc[r]);
            acc[r] = fmaf(x.y, w1, acc[r]);
            acc[r] = fmaf(x.z, w2, acc[r]);
            acc[r] = fmaf(x.w, w3, acc[r]);
        }
    }
}

// ---------------- slot-A body: qt GEMV + gq/C1/C2 + zero P/SA/SW ----------------
__device__ __forceinline__ void slotABody(const float (*s_sn)[256], int r0, int j,
                                          const float* __restrict__ gg, const float* __restrict__ gb) {
    float acc[4] = {0.f, 0.f, 0.f, 0.f};
    gemvDirect(g_Wqk, 256, 0, 256, &s_sn[0][0], 256, j, acc);
    float bqk = g_bqk[j], wbj = g_wb[j], ggj = gg[j], gbj = gb[j], c0 = g_c0;
    #pragma unroll
    for (int r = 0; r < 4; r++) {
        int row = r0 + r;
        float qt = acc[r] + bqk;
        float gq = ggj * qt;
        g_gq[(size_t)row * 256 + j] = gq;
        float c1 = gq;
        float c2 = fmaf(qt, gbj, s_sn[r][j] * wbj);
        blockReduce2(c1, c2);
        if (j == 0) { g_C1[row] = c1; g_C2[row] = c2 + c0; }
        g_P[(size_t)row * 256 + j] = 0.f;
        if (j == 0) { g_SA[row] = 0.f; g_SW[row] = 0.f; }
    }
}

// =================== SETUP: transposes + slot init + Wqk/bqk/wb/c0, ONE launch ===================
__device__ __forceinline__ void tTile(const float* __restrict__ src, float* __restrict__ dst,
                                      int R, int C, int bx, int by) {
    __shared__ float t[32][33];
    int tx = threadIdx.x & 31, ty = threadIdx.x >> 5;
    int c = bx * 32 + tx;
    int r = by * 32 + ty;
    #pragma unroll
    for (int k = 0; k < 32; k += 8)
        t[ty + k][tx] = src[(size_t)(r + k) * C + c];
    __syncthreads();
    int cc = bx * 32 + ty;
    int rr = by * 32 + tx;
    #pragma unroll
    for (int k = 0; k < 32; k += 8)
        dst[(size_t)(cc + k) * R + rr] = t[tx][ty + k];
}

__global__ void __launch_bounds__(256) kSetup(const float* __restrict__ W_ih, const float* __restrict__ W_hh,
                                              const float* __restrict__ Wv, const float* __restrict__ W1,
                                              const float* __restrict__ W2, const float* __restrict__ noise,
                                              const float* __restrict__ mu, const float* __restrict__ ls,
                                              const float* __restrict__ Wq, const float* __restrict__ Wk,
                                              const float* __restrict__ bq, const float* __restrict__ bk) {
    int t = blockIdx.x;
    int i = threadIdx.x;
    if (t < 192)       tTile(W_ih, g_WihT, 768, 256, t & 7, t >> 3);
    else if (t < 384)  { int u = t - 192; tTile(W_hh, g_WhhT, 768, 256, u & 7, u >> 3); }
    else if (t < 448)  { int u = t - 384; tTile(Wv,   g_WvT,  256, 256, u & 7, u >> 3); }
    else if (t < 576)  { int u = t - 448; tTile(W1,   g_W1T,  512, 256, u & 7, u >> 3); }
    else if (t < 704)  { int u = t - 576; tTile(W2,   g_W2T,  256, 512, u & 15, u >> 4); }
    else if (t < 1216) {
        int idx = (t - 704) * 256 + i;
        int d = idx & 255;
        g_slots[idx] = mu[d] + __expf(ls[d]) * noise[idx];
    } else if (t < 1472) {
        int jj = t - 1216;
        float acc[8] = {0.f,0.f,0.f,0.f,0.f,0.f,0.f,0.f};
        #pragma unroll 4
        for (int d = 0; d < 256; d += 8) {
            #pragma unroll
            for (int u = 0; u < 8; u++)
                acc[u] = fmaf(Wq[(d + u) * 256 + jj], Wk[(d + u) * 256 + i], acc[u]);
        }
        g_Wqk[jj * 256 + i] =
            (((acc[0] + acc[1]) + (acc[2] + acc[3])) + ((acc[4] + acc[5]) + (acc[6] + acc[7]))) * SCALE_;
    } else if (t == 1472) {
        float a = 0.f;
        #pragma unroll 8
        for (int d = 0; d < 256; d++) a = fmaf(bq[d], Wk[d * 256 + i], a);
        g_bqk[i] = a * SCALE_;
    } else if (t == 1473) {
        float a = 0.f;
        #pragma unroll 8
        for (int d = 0; d < 256; d++) a = fmaf(Wq[d * 256 + i], bk[d], a);
        g_wb[i] = a * SCALE_;
    } else {
        float a = bq[i] * bk[i], dm = 0.f;
        blockReduce2(a, dm);
        if (i == 0) g_c0 = a * SCALE_;
    }
}

// =================== kSlotA (iteration 0 only) ===================
__global__ void __launch_bounds__(256) kSlotA(const float* __restrict__ ls_g, const float* __restrict__ ls_b,
                                              const float* __restrict__ gg, const float* __restrict__ gb) {
    __shared__ float s_sn[4][256];
    int j = threadIdx.x;
    int r0 = blockIdx.x * 4;
    float lsg = ls_g[j], lsb = ls_b[j];
    #pragma unroll
    for (int r = 0; r < 4; r++) {
        float v = g_slots[(size_t)(r0 + r) * 256 + j];
        float a = v, b = v * v;
        blockReduce2(a, b);
        float m = a * (1.0f / 256.0f);
        float var = b * (1.0f / 256.0f) - m * m;
        float rs = rsqrtf(var + EPSLN);
        s_sn[r][j] = (v - m) * rs * lsg + lsb;
    }
    __syncthreads();
    slotABody(s_sn, r0, j, gg, gb);
}

// ============ kFA: LN + dots + softmax + P/SA/SW accumulation (distributed reductions) ============
// grid (16, 64), block 128 (4 warps), each warp 64 rows.
__global__ void __launch_bounds__(128) kFA(const float* __restrict__ inputs,
                                           int last, float* __restrict__ out_attn) {
    int b = blockIdx.y;
    int warp = threadIdx.x >> 5, lane = threadIdx.x & 31;
    int row0 = blockIdx.x * 256 + warp * 64;
    int r8 = b * 8;
    int slane = ((lane & 1) << 2) | (lane & 2) | ((lane >> 2) & 1);

    u64 gq[8][4];
    #pragma unroll
    for (int k = 0; k < 8; k++) {
        const float* gp = g_gq + (size_t)(r8 + k) * 256;
        float2 q0 = *(const float2*)(gp + 4 * lane);
        float2 q1 = *(const float2*)(gp + 4 * lane + 2);
        float2 q2 = *(const float2*)(gp + 128 + 4 * lane);
        float2 q3 = *(const float2*)(gp + 128 + 4 * lane + 2);
        gq[k][0] = pk2(q0.x, q0.y); gq[k][1] = pk2(q1.x, q1.y);
        gq[k][2] = pk2(q2.x, q2.y); gq[k][3] = pk2(q3.x, q3.y);
    }
    float C1s = g_C1[r8 + slane], C2s = g_C2[r8 + slane];

    u64 zero2 = pk2(0.f, 0.f);
    u64 P[8][4];
    #pragma unroll
    for (int k = 0; k < 8; k++) { P[k][0] = zero2; P[k][1] = zero2; P[k][2] = zero2; P[k][3] = zero2; }
    float SAl = 0.f, SWl = 0.f;

    const float4* vp = (const float4*)(inputs + ((size_t)b * N_ + row0) * 256);
    float4 a0 = vp[lane], a1 = vp[lane + 32];

    for (int r = 0; r < 64; r++) {
        int n = row0 + r;
        float4 b0v, b1v;
        if (r < 63) {
            const float4* vn = vp + (size_t)(r + 1) * 64;
            b0v = vn[lane]; b1v = vn[lane + 32];
        }
        float s  = ((a0.x + a0.y) + (a0.z + a0.w)) + ((a1.x + a1.y) + (a1.z + a1.w));
        float ss = fmaf(a0.x, a0.x, fmaf(a0.y, a0.y, fmaf(a0.z, a0.z, fmaf(a0.w, a0.w,
                   fmaf(a1.x, a1.x, fmaf(a1.y, a1.y, fmaf(a1.z, a1.z, a1.w * a1.w)))))));
        {
            bool odd = lane & 1;
            float send = odd ? s : ss;
            float rcv = __shfl_xor_sync(0xffffffffu, send, 1);
            float v = odd ? (ss + rcv) : (s + rcv);
            v += __shfl_xor_sync(0xffffffffu, v, 2);
            v += __shfl_xor_sync(0xffffffffu, v, 4);
            v += __shfl_xor_sync(0xffffffffu, v, 8);
            v += __shfl_xor_sync(0xffffffffu, v, 16);
            float o = __shfl_xor_sync(0xffffffffu, v, 1);
            s  = odd ? o : v;
            ss = odd ? v : o;
        }
        float m   = s * (1.0f / 256.0f);
        float var = fmaf(ss, 1.0f / 256.0f, -m * m);
        float rs  = rsqrtf(var + EPSLN);
        float w   = m * rs;

        u64 x01 = pk2(a0.x, a0.y), x23 = pk2(a0.z, a0.w);
        u64 x45 = pk2(a1.x, a1.y), x67 = pk2(a1.z, a1.w);

        float dt[8];
        #pragma unroll
        for (int k = 0; k < 8; k++) {
            u64 d2 = zero2;
            fma2(d2, x01, gq[k][0]); fma2(d2, x23, gq[k][1]);
            fma2(d2, x45, gq[k][2]); fma2(d2, x67, gq[k][3]);
            float lo, hi; upk2(d2, lo, hi);
            dt[k] = lo + hi;
        }
        float vdot;
        {
            bool c0 = lane & 1;
            float t0 = c0 ? dt[0] : dt[4];
            float t1 = c0 ? dt[1] : dt[5];
            float t2 = c0 ? dt[2] : dt[6];
            float t3 = c0 ? dt[3] : dt[7];
            t0 = __shfl_xor_sync(0xffffffffu, t0, 1);
            t1 = __shfl_xor_sync(0xffffffffu, t1, 1);
            t2 = __shfl_xor_sync(0xffffffffu, t2, 1);
            t3 = __shfl_xor_sync(0xffffffffu, t3, 1);
            float u0 = (c0 ? dt[4] : dt[0]) + t0;
            float u1 = (c0 ? dt[5] : dt[1]) + t1;
            float u2 = (c0 ? dt[6] : dt[2]) + t2;
            float u3 = (c0 ? dt[7] : dt[3]) + t3;
            bool c1 = lane & 2;
            float s0 = c1 ? u0 : u2;
            float s1 = c1 ? u1 : u3;
            s0 = __shfl_xor_sync(0xffffffffu, s0, 2);
            s1 = __shfl_xor_sync(0xffffffffu, s1, 2);
            float w0 = (c1 ? u2 : u0) + s0;
            float w1 = (c1 ? u3 : u1) + s1;
            bool c2 = lane & 4;
            float s2 = c2 ? w0 : w1;
            s2 = __shfl_xor_sync(0xffffffffu, s2, 4);
            vdot = (c2 ? w1 : w0) + s2;
            vdot += __shfl_xor_sync(0xffffffffu, vdot, 8);
            vdot += __shfl_xor_sync(0xffffffffu, vdot, 16);
        }
        float lg = fmaf(rs, vdot, fmaf(-w, C1s, C2s));
        float mx = lg;
        mx = fmaxf(mx, __shfl_xor_sync(0xffffffffu, mx, 1));
        mx = fmaxf(mx, __shfl_xor_sync(0xffffffffu, mx, 2));
        mx = fmaxf(mx, __shfl_xor_sync(0xffffffffu, mx, 4));
        float e = __expf(lg - mx);
        float sm = e;
        sm += __shfl_xor_sync(0xffffffffu, sm, 1);
        sm += __shfl_xor_sync(0xffffffffu, sm, 2);
        sm += __shfl_xor_sync(0xffffffffu, sm, 4);
        float a = __fdividef(e, sm);
        SAl += a;
        SWl = fmaf(a, w, SWl);
        if (last && lane < 8)
            out_attn[(size_t)(r8 + slane) * N_ + n] = a;

        int gbase = lane & 24;
        float ak[8];
        ak[0] = __shfl_sync(0xffffffffu, a, gbase | 0);
        ak[1] = __shfl_sync(0xffffffffu, a, gbase | 4);
        ak[2] = __shfl_sync(0xffffffffu, a, gbase | 2);
        ak[3] = __shfl_sync(0xffffffffu, a, gbase | 6);
        ak[4] = __shfl_sync(0xffffffffu, a, gbase | 1);
        ak[5] = __shfl_sync(0xffffffffu, a, gbase | 5);
        ak[6] = __shfl_sync(0xffffffffu, a, gbase | 3);
        ak[7] = __shfl_sync(0xffffffffu, a, gbase | 7);

        #pragma unroll
        for (int k = 0; k < 8; k++) {
            float ar = ak[k] * rs;
            u64 ap = pk2(ar, ar);
            fma2(P[k][0], ap, x01); fma2(P[k][1], ap, x23);
            fma2(P[k][2], ap, x45); fma2(P[k][3], ap, x67);
        }
        a0 = b0v; a1 = b1v;
    }

    __shared__ float sP[4][8][256];
    __shared__ float sSA[4][8], sSW[4][8];
    #pragma unroll
    for (int k = 0; k < 8; k++) {
        float x, y;
        upk2(P[k][0], x, y); sP[warp][k][4 * lane] = x;       sP[warp][k][4 * lane + 1] = y;
        upk2(P[k][1], x, y); sP[warp][k][4 * lane + 2] = x;   sP[warp][k][4 * lane + 3] = y;
        upk2(P[k][2], x, y); sP[warp][k][128 + 4 * lane] = x; sP[warp][k][128 + 4 * lane + 1] = y;
        upk2(P[k][3], x, y); sP[warp][k][128 + 4 * lane + 2] = x; sP[warp][k][128 + 4 * lane + 3] = y;
    }
    if (lane < 8) { sSA[warp][slane] = SAl; sSW[warp][slane] = SWl; }
    __syncthreads();
    for (int t = threadIdx.x; t < 2048; t += 128) {
        int k = t >> 8, d = t & 255;
        float v = (sP[0][k][d] + sP[1][k][d]) + (sP[2][k][d] + sP[3][k][d]);
        atomicAdd(&g_P[(size_t)(r8 + k) * 256 + d], v);
    }
    if (threadIdx.x < 8) {
        int k = threadIdx.x;
        atomicAdd(&g_SA[r8 + k], (sSA[0][k] + sSA[1][k]) + (sSA[2][k] + sSA[3][k]));
    } else if (threadIdx.x < 16) {
        int k = threadIdx.x - 8;
        atomicAdd(&g_SW[r8 + k], (sSW[0][k] + sSW[1][k]) + (sSW[2][k] + sSW[3][k]));
    }
}

// =================== kSlotB: un -> updates -> GRU -> LN -> FF -> slots (+ fused next slotA) ===================
// grid 128, block 256, 4 rows per block. Direct-LDG GEMV stages, no tile barriers.
__global__ void __launch_bounds__(256) kSlotB(const float* __restrict__ gg, const float* __restrict__ gb,
                                              const float* __restrict__ bv,
                                              const float* __restrict__ b_ih, const float* __restrict__ b_hh,
                                              const float* __restrict__ lnf_g, const float* __restrict__ lnf_b,
                                              const float* __restrict__ b1, const float* __restrict__ b2,
                                              const float* __restrict__ ls_g, const float* __restrict__ ls_b,
                                              int last, float* __restrict__ out_slots) {
    __shared__ float sA[4][256];    // un -> ff
    __shared__ float sB[4][256];    // updates(x) -> sn
    __shared__ float sSL[4][256];   // prev slots
    __shared__ float sF1[4][512];
    int j = threadIdx.x;
    int r0 = blockIdx.x * 4;
    float snorm[4];

    // stage 1: un & slots
    float ggj = gg[j], gbj = gb[j];
    #pragma unroll
    for (int r = 0; r < 4; r++) {
        int row = r0 + r;
        float SA = g_SA[row], SW = g_SW[row];
        float inv = 1.0f / (SA + EPSA);
        float Pv = g_P[(size_t)row * 256 + j];
        sA[r][j] = (ggj * (Pv - SW) + gbj * SA) * inv;
        sSL[r][j] = g_slots[(size_t)row * 256 + j];
        snorm[r] = SA * inv;
    }
    __syncthreads();

    // stage 2: x = un @ WvT + snorm*bv
    {
        float acc[4] = {0.f, 0.f, 0.f, 0.f};
        gemvDirect(g_WvT, 256, 0, 256, &sA[0][0], 256, j, acc);
        float bvj = bv[j];
        #pragma unroll
        for (int r = 0; r < 4; r++) sB[r][j] = fmaf(snorm[r], bvj, acc[r]);
    }
    __syncthreads();

    // stage 3: GRU gates — all 6 GEMVs fused in one k-loop
    float air[4] = {}, aiz[4] = {}, ain[4] = {}, ahr[4] = {}, ahz[4] = {}, ahn[4] = {};
    {
        const float* pi = g_WihT + j;
        const float* ph = g_WhhT + j;
        #pragma unroll 2
        for (int k0 = 0; k0 < 256; k0 += 2) {
            float wr0 = pi[0],   wr1 = pi[768];
            float wz0 = pi[256], wz1 = pi[768 + 256];
            float wn0 = pi[512], wn1 = pi[768 + 512];
            float vr0 = ph[0],   vr1 = ph[768];
            float vz0 = ph[256], vz1 = ph[768 + 256];
            float vn0 = ph[512], vn1 = ph[768 + 512];
            pi += 1536; ph += 1536;
            #pragma unroll
            for (int r = 0; r < 4; r++) {
                float2 x  = *(const float2*)(&sB[r][k0]);
                float2 sl = *(const float2*)(&sSL[r][k0]);
                air[r] = fmaf(x.x, wr0, fmaf(x.y, wr1, air[r]));
                aiz[r] = fmaf(x.x, wz0, fmaf(x.y, wz1, aiz[r]));
                ain[r] = fmaf(x.x, wn0, fmaf(x.y, wn1, ain[r]));
                ahr[r] = fmaf(sl.x, vr0, fmaf(sl.y, vr1, ahr[r]));
                ahz[r] = fmaf(sl.x, vz0, fmaf(sl.y, vz1, ahz[r]));
                ahn[r] = fmaf(sl.x, vn0, fmaf(sl.y, vn1, ahn[r]));
            }
        }
    }

    // stage 4: GRU combine + ln_ff (ff -> sA)
    float h_reg[4];
    {
        float bir = b_ih[j], biz = b_ih[256 + j], bin = b_ih[512 + j];
        float bhr = b_hh[j], bhz = b_hh[256 + j], bhn = b_hh[512 + j];
        float lgj = lnf_g[j], lbj = lnf_b[j];
        __syncthreads();   // everyone done reading sA (stage2) before overwrite below
        #pragma unroll
        for (int r = 0; r < 4; r++) {
            float rr = 1.0f / (1.0f + __expf(-(air[r] + bir + ahr[r] + bhr)));
            float zz = 1.0f / (1.0f + __expf(-(aiz[r] + biz + ahz[r] + bhz)));
            float nn = tanhf(ain[r] + bin + rr * (ahn[r] + bhn));
            float h = (1.0f - zz) * nn + zz * sSL[r][j];
            h_reg[r] = h;
            float a = h, bb = h * h;
            blockReduce2(a, bb);
            float m = a * (1.0f / 256.0f);
            float var = bb * (1.0f / 256.0f) - m * m;
            float rs = rsqrtf(var + EPSLN);
            sA[r][j] = (h - m) * rs * lgj + lbj;
        }
    }
    __syncthreads();

    // stage 5: f1 = relu(ff @ W1T + b1) — both 256-col halves fused in one k-loop
    {
        float f0[4] = {}, f1v[4] = {};
        const float* p1 = g_W1T + j;
        #pragma unroll 2
        for (int k0 = 0; k0 < 256; k0 += 2) {
            float wa0 = p1[0],   wa1 = p1[512];
            float wb0 = p1[256], wb1 = p1[256 + 512];
            p1 += 1024;
            #pragma unroll
            for (int r = 0; r < 4; r++) {
                float2 x = *(const float2*)(&sA[r][k0]);
                f0[r]  = fmaf(x.x, wa0, fmaf(x.y, wa1, f0[r]));
                f1v[r] = fmaf(x.x, wb0, fmaf(x.y, wb1, f1v[r]));
            }
        }
        float b1a = b1[j], b1b = b1[256 + j];
        #pragma unroll
        for (int r = 0; r < 4; r++) {
            sF1[r][j]       = fmaxf(f0[r]  + b1a, 0.f);
            sF1[r][256 + j] = fmaxf(f1v[r] + b1b, 0.f);
        }
    }
    __syncthreads();

    // stage 6: new slots = h + f1 @ W2T + b2
    float ns[4];
    {
        float o[4] = {};
        gemvDirect(g_W2T, 256, 0, 512, &sF1[0][0], 512, j, o);
        float b2j = b2[j];
        #pragma unroll
        for (int r = 0; r < 4; r++) {
            ns[r] = h_reg[r] + o[r] + b2j;
            g_slots[(size_t)(r0 + r) * 256 + j] = ns[r];
            if (last) out_slots[(size_t)(r0 + r) * 256 + j] = ns[r];
        }
    }

    // fused next-iteration slotA (skip on last iter)
    if (!last) {
        float lsg = ls_g[j], lsb = ls_b[j];
        #pragma unroll
        for (int r = 0; r < 4; r++) {
            float v = ns[r];
            float a = v, bb = v * v;
            blockReduce2(a, bb);
            float m = a * (1.0f / 256.0f);
            float var = bb * (1.0f / 256.0f) - m * m;
            float rs = rsqrtf(var + EPSLN);
            sB[r][j] = (v - m) * rs * lsg + lsb;
        }
        __syncthreads();
        slotABody((const float (*)[256])sB, r0, j, gg, gb);
    }
}

// ---------------- launch ----------------
extern "C" void kernel_launch(void* const* d_in, const int* in_sizes, int n_in,
                              void* d_out, int out_size) {
    (void)in_sizes; (void)n_in; (void)out_size;
    const float* inputs  = (const float*)d_in[0];
    const float* noise   = (const float*)d_in[1];
    const float* slot_mu = (const float*)d_in[2];
    const float* slot_ls = (const float*)d_in[3];
    const float* Wq      = (const float*)d_in[4];
    const float* bq      = (const float*)d_in[5];
    const float* Wk      = (const float*)d_in[6];
    const float* bk      = (const float*)d_in[7];
    const float* Wv      = (const float*)d_in[8];
    const float* bv      = (const float*)d_in[9];
    const float* W_ih    = (const float*)d_in[10];
    const float* b_ih    = (const float*)d_in[11];
    const float* W_hh    = (const float*)d_in[12];
    const float* b_hh    = (const float*)d_in[13];
    const float* ln_in_g = (const float*)d_in[14];
    const float* ln_in_b = (const float*)d_in[15];
    const float* ln_s_g  = (const float*)d_in[16];
    const float* ln_s_b  = (const float*)d_in[17];
    const float* ln_ff_g = (const float*)d_in[18];
    const float* ln_ff_b = (const float*)d_in[19];
    const float* W1      = (const float*)d_in[20];
    const float* b1      = (const float*)d_in[21];
    const float* W2      = (const float*)d_in[22];
    const float* b2      = (const float*)d_in[23];

    float* out = (float*)d_out;
    float* out_slots = out;
    float* out_attn  = out + BK_ * D_;

    kSetup<<<1475, 256>>>(W_ih, W_hh, Wv, W1, W2, noise, slot_mu, slot_ls, Wq, Wk, bq, bk);
    kSlotA<<<128, 256>>>(ln_s_g, ln_s_b, ln_in_g, ln_in_b);

    for (int it = 0; it < 3; it++) {
        int last = (it == 2);
        kFA<<<dim3(16, 64), 128>>>(inputs, last, out_attn);
        kSlotB<<<128, 256>>>(ln_in_g, ln_in_b, bv, b_ih, b_hh,
                             ln_ff_g, ln_ff_b, b1, b2, ln_s_g, ln_s_b,
                             last, out_slots);
    }
}

// round 9
// speedup vs baseline: 1.6163x; 1.6163x over previous
#include <cuda_runtime.h>
#include <math.h>
#include <stdint.h>
#include <stddef.h>

// ---------------- problem dims ----------------
#define B_    64
#define N_    4096
#define DIN_  256
#define K_    8
#define D_    256
#define H_    512
#define BK_   512
#define SCALE_ 0.0625f
#define EPSLN 1e-5f
#define EPSA  1e-8f

typedef unsigned long long u64;

// ---------------- device scratch ----------------
__device__ __align__(16) float g_slots[BK_ * D_];
__device__ __align__(16) float g_gq[BK_ * D_];      // g ⊙ qt
__device__ float g_C1[BK_];
__device__ float g_C2[BK_];
__device__ __align__(16) float g_P[BK_ * D_];       // Σ a*rs*v
__device__ float g_SA[BK_];
__device__ float g_SW[BK_];
__device__ __align__(16) float g_Wqk[D_ * D_];
__device__ float g_bqk[D_];
__device__ float g_wb[D_];
__device__ float g_c0;
__device__ __align__(16) float g_WihT[D_ * 3 * D_];
__device__ __align__(16) float g_WhhT[D_ * 3 * D_];
__device__ __align__(16) float g_WvT[D_ * D_];
__device__ __align__(16) float g_W1T[D_ * H_];
__device__ __align__(16) float g_W2T[H_ * D_];

// ---------------- f32x2 packed helpers ----------------
__device__ __forceinline__ u64 pk2(float x, float y) {
    u64 r; asm("mov.b64 %0, {%1, %2};" : "=l"(r) : "f"(x), "f"(y)); return r;
}
__device__ __forceinline__ void upk2(u64 v, float& x, float& y) {
    asm("mov.b64 {%0, %1}, %2;" : "=f"(x), "=f"(y) : "l"(v));
}
__device__ __forceinline__ void fma2(u64& d, u64 a, u64 b) {
    asm("fma.rn.f32x2 %0, %1, %2, %0;" : "+l"(d) : "l"(a), "l"(b));
}

// ---------------- block reduce (2 values, 256-thread kernels) ----------------
__device__ __forceinline__ void blockReduce2(float& a, float& b) {
    #pragma unroll
    for (int o = 16; o; o >>= 1) {
        a += __shfl_xor_sync(0xffffffffu, a, o);
        b += __shfl_xor_sync(0xffffffffu, b, o);
    }
    __shared__ float sa[8], sb[8];
    __syncthreads();
    int w = threadIdx.x >> 5;
    if ((threadIdx.x & 31) == 0) { sa[w] = a; sb[w] = b; }
    __syncthreads();
    a = sa[threadIdx.x & 7];
    b = sb[threadIdx.x & 7];
    #pragma unroll
    for (int o = 4; o; o >>= 1) {
        a += __shfl_xor_sync(0xffffffffu, a, o);
        b += __shfl_xor_sync(0xffffffffu, b, o);
    }
}

// ---------------- group reduce: 1024 threads, 4 independent groups of 256 ----------------
// Each group q (threads q*256..q*256+255) reduces its own (a,b). All threads get group sums.
__device__ __forceinline__ void grpReduce2(float& a, float& b) {
    #pragma unroll
    for (int o = 16; o; o >>= 1) {
        a += __shfl_xor_sync(0xffffffffu, a, o);
        b += __shfl_xor_sync(0xffffffffu, b, o);
    }
    __shared__ float sa[32], sb[32];
    int w = threadIdx.x >> 5;
    __syncthreads();
    if ((threadIdx.x & 31) == 0) { sa[w] = a; sb[w] = b; }
    __syncthreads();
    int g8 = (threadIdx.x >> 8) << 3;
    float ra = 0.f, rb = 0.f;
    #pragma unroll
    for (int i = 0; i < 8; i++) { ra += sa[g8 + i]; rb += sb[g8 + i]; }
    a = ra; b = rb;
}

// ---------------- partial-k GEMV: acc[r] += sum_{k in [kbase,kbase+L)} s_in[r][k]*W[k][j] ----------------
__device__ __forceinline__ void gemvPart(const float* __restrict__ W, int rstride, int L,
                                         const float* s_in, int in_stride, int j, int kbase,
                                         float acc[4]) {
    const float* p = W + (size_t)kbase * rstride + j;
    #pragma unroll 4
    for (int kk = 0; kk < L; kk += 4) {
        float w0 = p[0];
        float w1 = p[rstride];
        float w2 = p[2 * rstride];
        float w3 = p[3 * rstride];
        p += 4 * rstride;
        #pragma unroll
        for (int r = 0; r < 4; r++) {
            float4 x = *(const float4*)(s_in + r * in_stride + kbase + kk);
            acc[r] = fmaf(x.x, w0, fmaf(x.y, w1, fmaf(x.z, w2, fmaf(x.w, w3, acc[r]))));
        }
    }
}

// ---------------- reduction wave: combine 4 k-quarter partials; thread gets row-q value ----------------
__device__ __forceinline__ float reduceWave(const float part[4], float* sRed, int q, int j) {
    __syncthreads();
    #pragma unroll
    for (int r = 0; r < 4; r++) sRed[((q << 2) + r) * 256 + j] = part[r];
    __syncthreads();
    return (sRed[(0 + q) * 256 + j] + sRed[(4 + q) * 256 + j]) +
           (sRed[(8 + q) * 256 + j] + sRed[(12 + q) * 256 + j]);
}

// ---------------- slot-A body (1024 threads): qt GEMV + gq/C1/C2 + zero P/SA/SW ----------------
__device__ __forceinline__ void slotABody(const float (*s_sn)[256], float* sRed,
                                          int r0, int q, int j,
                                          const float* __restrict__ gg, const float* __restrict__ gb) {
    float acc[4] = {0.f, 0.f, 0.f, 0.f};
    gemvPart(g_Wqk, 256, 64, &s_sn[0][0], 256, j, 64 * q, acc);
    float qt = reduceWave(acc, sRed, q, j) + g_bqk[j];
    int row = r0 + q;
    float gq = gg[j] * qt;
    g_gq[(size_t)row * 256 + j] = gq;
    float c1 = gq;
    float c2 = fmaf(qt, gb[j], s_sn[q][j] * g_wb[j]);
    grpReduce2(c1, c2);
    if (j == 0) { g_C1[row] = c1; g_C2[row] = c2 + g_c0; }
    g_P[(size_t)row * 256 + j] = 0.f;
    if (j == 0) { g_SA[row] = 0.f; g_SW[row] = 0.f; }
}

// =================== SETUP: transposes + slot init + Wqk/bqk/wb/c0, ONE launch ===================
__device__ __forceinline__ void tTile(const float* __restrict__ src, float* __restrict__ dst,
                                      int R, int C, int bx, int by) {
    __shared__ float t[32][33];
    int tx = threadIdx.x & 31, ty = threadIdx.x >> 5;
    int c = bx * 32 + tx;
    int r = by * 32 + ty;
    #pragma unroll
    for (int k = 0; k < 32; k += 8)
        t[ty + k][tx] = src[(size_t)(r + k) * C + c];
    __syncthreads();
    int cc = bx * 32 + ty;
    int rr = by * 32 + tx;
    #pragma unroll
    for (int k = 0; k < 32; k += 8)
        dst[(size_t)(cc + k) * R + rr] = t[tx][ty + k];
}

__global__ void __launch_bounds__(256) kSetup(const float* __restrict__ W_ih, const float* __restrict__ W_hh,
                                              const float* __restrict__ Wv, const float* __restrict__ W1,
                                              const float* __restrict__ W2, const float* __restrict__ noise,
                                              const float* __restrict__ mu, const float* __restrict__ ls,
                                              const float* __restrict__ Wq, const float* __restrict__ Wk,
                                              const float* __restrict__ bq, const float* __restrict__ bk) {
    int t = blockIdx.x;
    int i = threadIdx.x;
    if (t < 192)       tTile(W_ih, g_WihT, 768, 256, t & 7, t >> 3);
    else if (t < 384)  { int u = t - 192; tTile(W_hh, g_WhhT, 768, 256, u & 7, u >> 3); }
    else if (t < 448)  { int u = t - 384; tTile(Wv,   g_WvT,  256, 256, u & 7, u >> 3); }
    else if (t < 576)  { int u = t - 448; tTile(W1,   g_W1T,  512, 256, u & 7, u >> 3); }
    else if (t < 704)  { int u = t - 576; tTile(W2,   g_W2T,  256, 512, u & 15, u >> 4); }
    else if (t < 1216) {
        int idx = (t - 704) * 256 + i;
        int d = idx & 255;
        g_slots[idx] = mu[d] + __expf(ls[d]) * noise[idx];
    } else if (t < 1472) {
        int jj = t - 1216;
        float acc[8] = {0.f,0.f,0.f,0.f,0.f,0.f,0.f,0.f};
        #pragma unroll 4
        for (int d = 0; d < 256; d += 8) {
            #pragma unroll
            for (int u = 0; u < 8; u++)
                acc[u] = fmaf(Wq[(d + u) * 256 + jj], Wk[(d + u) * 256 + i], acc[u]);
        }
        g_Wqk[jj * 256 + i] =
            (((acc[0] + acc[1]) + (acc[2] + acc[3])) + ((acc[4] + acc[5]) + (acc[6] + acc[7]))) * SCALE_;
    } else if (t == 1472) {
        float a = 0.f;
        #pragma unroll 8
        for (int d = 0; d < 256; d++) a = fmaf(bq[d], Wk[d * 256 + i], a);
        g_bqk[i] = a * SCALE_;
    } else if (t == 1473) {
        float a = 0.f;
        #pragma unroll 8
        for (int d = 0; d < 256; d++) a = fmaf(Wq[d * 256 + i], bk[d], a);
        g_wb[i] = a * SCALE_;
    } else {
        float a = bq[i] * bk[i], dm = 0.f;
        blockReduce2(a, dm);
        if (i == 0) g_c0 = a * SCALE_;
    }
}

// =================== kSlotA (iteration 0 only): 1024 threads, 4 rows/block ===================
__global__ void __launch_bounds__(1024) kSlotA(const float* __restrict__ ls_g, const float* __restrict__ ls_b,
                                               const float* __restrict__ gg, const float* __restrict__ gb) {
    __shared__ float sSN[4][256];
    __shared__ float sRed[4096];
    int j = threadIdx.x & 255, q = threadIdx.x >> 8;
    int r0 = blockIdx.x * 4;
    float v = g_slots[(size_t)(r0 + q) * 256 + j];
    float a = v, b = v * v;
    grpReduce2(a, b);
    float m = a * (1.0f / 256.0f);
    float var = b * (1.0f / 256.0f) - m * m;
    float rs = rsqrtf(var + EPSLN);
    sSN[q][j] = (v - m) * rs * ls_g[j] + ls_b[j];
    __syncthreads();
    slotABody(sSN, sRed, r0, q, j, gg, gb);
}

// ============ kFA: LN + dots + softmax + P/SA/SW accumulation (distributed reductions) ============
// grid (16, 64), block 128 (4 warps), each warp 64 rows.
__global__ void __launch_bounds__(128) kFA(const float* __restrict__ inputs,
                                           int last, float* __restrict__ out_attn) {
    int b = blockIdx.y;
    int warp = threadIdx.x >> 5, lane = threadIdx.x & 31;
    int row0 = blockIdx.x * 256 + warp * 64;
    int r8 = b * 8;
    int slane = ((lane & 1) << 2) | (lane & 2) | ((lane >> 2) & 1);

    u64 gq[8][4];
    #pragma unroll
    for (int k = 0; k < 8; k++) {
        const float* gp = g_gq + (size_t)(r8 + k) * 256;
        float2 q0 = *(const float2*)(gp + 4 * lane);
        float2 q1 = *(const float2*)(gp + 4 * lane + 2);
        float2 q2 = *(const float2*)(gp + 128 + 4 * lane);
        float2 q3 = *(const float2*)(gp + 128 + 4 * lane + 2);
        gq[k][0] = pk2(q0.x, q0.y); gq[k][1] = pk2(q1.x, q1.y);
        gq[k][2] = pk2(q2.x, q2.y); gq[k][3] = pk2(q3.x, q3.y);
    }
    float C1s = g_C1[r8 + slane], C2s = g_C2[r8 + slane];

    u64 zero2 = pk2(0.f, 0.f);
    u64 P[8][4];
    #pragma unroll
    for (int k = 0; k < 8; k++) { P[k][0] = zero2; P[k][1] = zero2; P[k][2] = zero2; P[k][3] = zero2; }
    float SAl = 0.f, SWl = 0.f;

    const float4* vp = (const float4*)(inputs + ((size_t)b * N_ + row0) * 256);
    float4 a0 = vp[lane], a1 = vp[lane + 32];

    for (int r = 0; r < 64; r++) {
        int n = row0 + r;
        float4 b0v, b1v;
        if (r < 63) {
            const float4* vn = vp + (size_t)(r + 1) * 64;
            b0v = vn[lane]; b1v = vn[lane + 32];
        }
        float s  = ((a0.x + a0.y) + (a0.z + a0.w)) + ((a1.x + a1.y) + (a1.z + a1.w));
        float ss = fmaf(a0.x, a0.x, fmaf(a0.y, a0.y, fmaf(a0.z, a0.z, fmaf(a0.w, a0.w,
                   fmaf(a1.x, a1.x, fmaf(a1.y, a1.y, fmaf(a1.z, a1.z, a1.w * a1.w)))))));
        {
            bool odd = lane & 1;
            float send = odd ? s : ss;
            float rcv = __shfl_xor_sync(0xffffffffu, send, 1);
            float v = odd ? (ss + rcv) : (s + rcv);
            v += __shfl_xor_sync(0xffffffffu, v, 2);
            v += __shfl_xor_sync(0xffffffffu, v, 4);
            v += __shfl_xor_sync(0xffffffffu, v, 8);
            v += __shfl_xor_sync(0xffffffffu, v, 16);
            float o = __shfl_xor_sync(0xffffffffu, v, 1);
            s  = odd ? o : v;
            ss = odd ? v : o;
        }
        float m   = s * (1.0f / 256.0f);
        float var = fmaf(ss, 1.0f / 256.0f, -m * m);
        float rs  = rsqrtf(var + EPSLN);
        float w   = m * rs;

        u64 x01 = pk2(a0.x, a0.y), x23 = pk2(a0.z, a0.w);
        u64 x45 = pk2(a1.x, a1.y), x67 = pk2(a1.z, a1.w);

        float dt[8];
        #pragma unroll
        for (int k = 0; k < 8; k++) {
            u64 d2 = zero2;
            fma2(d2, x01, gq[k][0]); fma2(d2, x23, gq[k][1]);
            fma2(d2, x45, gq[k][2]); fma2(d2, x67, gq[k][3]);
            float lo, hi; upk2(d2, lo, hi);
            dt[k] = lo + hi;
        }
        float vdot;
        {
            bool c0 = lane & 1;
            float t0 = c0 ? dt[0] : dt[4];
            float t1 = c0 ? dt[1] : dt[5];
            float t2 = c0 ? dt[2] : dt[6];
            float t3 = c0 ? dt[3] : dt[7];
            t0 = __shfl_xor_sync(0xffffffffu, t0, 1);
            t1 = __shfl_xor_sync(0xffffffffu, t1, 1);
            t2 = __shfl_xor_sync(0xffffffffu, t2, 1);
            t3 = __shfl_xor_sync(0xffffffffu, t3, 1);
            float u0 = (c0 ? dt[4] : dt[0]) + t0;
            float u1 = (c0 ? dt[5] : dt[1]) + t1;
            float u2 = (c0 ? dt[6] : dt[2]) + t2;
            float u3 = (c0 ? dt[7] : dt[3]) + t3;
            bool c1 = lane & 2;
            float s0 = c1 ? u0 : u2;
            float s1 = c1 ? u1 : u3;
            s0 = __shfl_xor_sync(0xffffffffu, s0, 2);
            s1 = __shfl_xor_sync(0xffffffffu, s1, 2);
            float w0 = (c1 ? u2 : u0) + s0;
            float w1 = (c1 ? u3 : u1) + s1;
            bool c2 = lane & 4;
            float s2 = c2 ? w0 : w1;
            s2 = __shfl_xor_sync(0xffffffffu, s2, 4);
            vdot = (c2 ? w1 : w0) + s2;
            vdot += __shfl_xor_sync(0xffffffffu, vdot, 8);
            vdot += __shfl_xor_sync(0xffffffffu, vdot, 16);
        }
        float lg = fmaf(rs, vdot, fmaf(-w, C1s, C2s));
        float mx = lg;
        mx = fmaxf(mx, __shfl_xor_sync(0xffffffffu, mx, 1));
        mx = fmaxf(mx, __shfl_xor_sync(0xffffffffu, mx, 2));
        mx = fmaxf(mx, __shfl_xor_sync(0xffffffffu, mx, 4));
        float e = __expf(lg - mx);
        float sm = e;
        sm += __shfl_xor_sync(0xffffffffu, sm, 1);
        sm += __shfl_xor_sync(0xffffffffu, sm, 2);
        sm += __shfl_xor_sync(0xffffffffu, sm, 4);
        float a = __fdividef(e, sm);
        SAl += a;
        SWl = fmaf(a, w, SWl);
        if (last && lane < 8)
            out_attn[(size_t)(r8 + slane) * N_ + n] = a;

        int gbase = lane & 24;
        float ak[8];
        ak[0] = __shfl_sync(0xffffffffu, a, gbase | 0);
        ak[1] = __shfl_sync(0xffffffffu, a, gbase | 4);
        ak[2] = __shfl_sync(0xffffffffu, a, gbase | 2);
        ak[3] = __shfl_sync(0xffffffffu, a, gbase | 6);
        ak[4] = __shfl_sync(0xffffffffu, a, gbase | 1);
        ak[5] = __shfl_sync(0xffffffffu, a, gbase | 5);
        ak[6] = __shfl_sync(0xffffffffu, a, gbase | 3);
        ak[7] = __shfl_sync(0xffffffffu, a, gbase | 7);

        #pragma unroll
        for (int k = 0; k < 8; k++) {
            float ar = ak[k] * rs;
            u64 ap = pk2(ar, ar);
            fma2(P[k][0], ap, x01); fma2(P[k][1], ap, x23);
            fma2(P[k][2], ap, x45); fma2(P[k][3], ap, x67);
        }
        a0 = b0v; a1 = b1v;
    }

    __shared__ float sP[4][8][256];
    __shared__ float sSA[4][8], sSW[4][8];
    #pragma unroll
    for (int k = 0; k < 8; k++) {
        float x, y;
        upk2(P[k][0], x, y); sP[warp][k][4 * lane] = x;       sP[warp][k][4 * lane + 1] = y;
        upk2(P[k][1], x, y); sP[warp][k][4 * lane + 2] = x;   sP[warp][k][4 * lane + 3] = y;
        upk2(P[k][2], x, y); sP[warp][k][128 + 4 * lane] = x; sP[warp][k][128 + 4 * lane + 1] = y;
        upk2(P[k][3], x, y); sP[warp][k][128 + 4 * lane + 2] = x; sP[warp][k][128 + 4 * lane + 3] = y;
    }
    if (lane < 8) { sSA[warp][slane] = SAl; sSW[warp][slane] = SWl; }
    __syncthreads();
    for (int t = threadIdx.x; t < 2048; t += 128) {
        int k = t >> 8, d = t & 255;
        float v = (sP[0][k][d] + sP[1][k][d]) + (sP[2][k][d] + sP[3][k][d]);
        atomicAdd(&g_P[(size_t)(r8 + k) * 256 + d], v);
    }
    if (threadIdx.x < 8) {
        int k = threadIdx.x;
        atomicAdd(&g_SA[r8 + k], (sSA[0][k] + sSA[1][k]) + (sSA[2][k] + sSA[3][k]));
    } else if (threadIdx.x < 16) {
        int k = threadIdx.x - 8;
        atomicAdd(&g_SW[r8 + k], (sSW[0][k] + sSW[1][k]) + (sSW[2][k] + sSW[3][k]));
    }
}

// =================== kSlotB: un -> updates -> GRU -> LN -> FF -> slots (+ fused next slotA) ===================
// grid 128, block 1024 (32 warps). thread (q, j): k-quarter q, output column j, all 4 rows.
__global__ void __launch_bounds__(1024) kSlotB(const float* __restrict__ gg, const float* __restrict__ gb,
                                               const float* __restrict__ bv,
                                               const float* __restrict__ b_ih, const float* __restrict__ b_hh,
                                               const float* __restrict__ lnf_g, const float* __restrict__ lnf_b,
                                               const float* __restrict__ b1, const float* __restrict__ b2,
                                               const float* __restrict__ ls_g, const float* __restrict__ ls_b,
                                               int last, float* __restrict__ out_slots) {
    __shared__ float sA[4][256];    // un -> ff
    __shared__ float sB[4][256];    // updates(x) -> sn
    __shared__ float sSL[4][256];   // prev slots
    __shared__ float sF1[4][512];
    __shared__ float sRed[4096];    // 16KB partial-reduction buffer
    int j = threadIdx.x & 255, q = threadIdx.x >> 8;
    int r0 = blockIdx.x * 4;
    int row = r0 + q;

    // stage 1: un & slots (each group fills its own row)
    float snorm;
    {
        float SA = g_SA[row], SW = g_SW[row];
        float inv = 1.0f / (SA + EPSA);
        float Pv = g_P[(size_t)row * 256 + j];
        sA[q][j] = (gg[j] * (Pv - SW) + gb[j] * SA) * inv;
        sSL[q][j] = g_slots[(size_t)row * 256 + j];
        snorm = SA * inv;
    }
    __syncthreads();

    // stage 2: x = un @ WvT + snorm*bv
    {
        float acc[4] = {0.f, 0.f, 0.f, 0.f};
        gemvPart(g_WvT, 256, 64, &sA[0][0], 256, j, 64 * q, acc);
        float x = reduceWave(acc, sRed, q, j);
        sB[q][j] = fmaf(snorm, bv[j], x);
    }
    __syncthreads();

    // stage 3a: input gates (Wih, reads sB) — 3 gates fused, k-quarter partials
    float ir, iz, inn;
    {
        float pir[4] = {}, piz[4] = {}, pin[4] = {};
        const float* pw = g_WihT + (size_t)(64 * q) * 768 + j;
        #pragma unroll 4
        for (int kk = 0; kk < 64; kk += 2) {
            float wr0 = pw[0],   wz0 = pw[256],       wn0 = pw[512];
            float wr1 = pw[768], wz1 = pw[768 + 256], wn1 = pw[768 + 512];
            pw += 1536;
            #pragma unroll
            for (int r = 0; r < 4; r++) {
                float2 x = *(const float2*)(&sB[r][64 * q + kk]);
                pir[r] = fmaf(x.x, wr0, fmaf(x.y, wr1, pir[r]));
                piz[r] = fmaf(x.x, wz0, fmaf(x.y, wz1, piz[r]));
                pin[r] = fmaf(x.x, wn0, fmaf(x.y, wn1, pin[r]));
            }
        }
        ir  = reduceWave(pir, sRed, q, j);
        iz  = reduceWave(piz, sRed, q, j);
        inn = reduceWave(pin, sRed, q, j);
    }
    // stage 3b: hidden gates (Whh, reads sSL)
    float hr, hz, hn;
    {
        float phr[4] = {}, phz[4] = {}, phn[4] = {};
        const float* pw = g_WhhT + (size_t)(64 * q) * 768 + j;
        #pragma unroll 4
        for (int kk = 0; kk < 64; kk += 2) {
            float vr0 = pw[0],   vz0 = pw[256],       vn0 = pw[512];
            float vr1 = pw[768], vz1 = pw[768 + 256], vn1 = pw[768 + 512];
            pw += 1536;
            #pragma unroll
            for (int r = 0; r < 4; r++) {
                float2 x = *(const float2*)(&sSL[r][64 * q + kk]);
                phr[r] = fmaf(x.x, vr0, fmaf(x.y, vr1, phr[r]));
                phz[r] = fmaf(x.x, vz0, fmaf(x.y, vz1, phz[r]));
                phn[r] = fmaf(x.x, vn0, fmaf(x.y, vn1, phn[r]));
            }
        }
        hr = reduceWave(phr, sRed, q, j);
        hz = reduceWave(phz, sRed, q, j);
        hn = reduceWave(phn, sRed, q, j);
    }

    // stage 4: GRU combine + ln_ff (row q, col j)
    float h_reg;
    {
        float rr = 1.0f / (1.0f + __expf(-(ir + b_ih[j] + hr + b_hh[j])));
        float zz = 1.0f / (1.0f + __expf(-(iz + b_ih[256 + j] + hz + b_hh[256 + j])));
        float nn = tanhf(inn + b_ih[512 + j] + rr * (hn + b_hh[512 + j]));
        float h = (1.0f - zz) * nn + zz * sSL[q][j];
        h_reg = h;
        float a = h, bb = h * h;
        grpReduce2(a, bb);
        float m = a * (1.0f / 256.0f);
        float var = bb * (1.0f / 256.0f) - m * m;
        float rs = rsqrtf(var + EPSLN);
        __syncthreads();   // sA (un) fully consumed before overwrite
        sA[q][j] = (h - m) * rs * lnf_g[j] + lnf_b[j];
    }
    __syncthreads();

    // stage 5: f1 = relu(ff @ W1T + b1), two 256-col halves
    {
        float f0[4] = {}, f1v[4] = {};
        const float* p1 = g_W1T + (size_t)(64 * q) * 512 + j;
        #pragma unroll 4
        for (int kk = 0; kk < 64; kk += 2) {
            float wa0 = p1[0],   wb0 = p1[256];
            float wa1 = p1[512], wb1 = p1[512 + 256];
            p1 += 1024;
            #pragma unroll
            for (int r = 0; r < 4; r++) {
                float2 x = *(const float2*)(&sA[r][64 * q + kk]);
                f0[r]  = fmaf(x.x, wa0, fmaf(x.y, wa1, f0[r]));
                f1v[r] = fmaf(x.x, wb0, fmaf(x.y, wb1, f1v[r]));
            }
        }
        float h0 = reduceWave(f0, sRed, q, j);
        float h1 = reduceWave(f1v, sRed, q, j);
        sF1[q][j]       = fmaxf(h0 + b1[j], 0.f);
        sF1[q][256 + j] = fmaxf(h1 + b1[256 + j], 0.f);
    }
    __syncthreads();

    // stage 6: new slots = h + f1 @ W2T + b2  (k=512, quarter = 128)
    float ns;
    {
        float o[4] = {0.f, 0.f, 0.f, 0.f};
        gemvPart(g_W2T, 256, 128, &sF1[0][0], 512, j, 128 * q, o);
        float oo = reduceWave(o, sRed, q, j);
        ns = h_reg + oo + b2[j];
        g_slots[(size_t)row * 256 + j] = ns;
        if (last) out_slots[(size_t)row * 256 + j] = ns;
    }

    // fused next-iteration slotA
    if (!last) {
        float a = ns, bb = ns * ns;
        grpReduce2(a, bb);
        float m = a * (1.0f / 256.0f);
        float var = bb * (1.0f / 256.0f) - m * m;
        float rs = rsqrtf(var + EPSLN);
        __syncthreads();    // sB fully consumed (stage 3a) before overwrite
        sB[q][j] = (ns - m) * rs * ls_g[j] + ls_b[j];
        __syncthreads();
        slotABody((const float (*)[256])sB, sRed, r0, q, j, gg, gb);
    }
}

// ---------------- launch ----------------
extern "C" void kernel_launch(void* const* d_in, const int* in_sizes, int n_in,
                              void* d_out, int out_size) {
    (void)in_sizes; (void)n_in; (void)out_size;
    const float* inputs  = (const float*)d_in[0];
    const float* noise   = (const float*)d_in[1];
    const float* slot_mu = (const float*)d_in[2];
    const float* slot_ls = (const float*)d_in[3];
    const float* Wq      = (const float*)d_in[4];
    const float* bq      = (const float*)d_in[5];
    const float* Wk      = (const float*)d_in[6];
    const float* bk      = (const float*)d_in[7];
    const float* Wv      = (const float*)d_in[8];
    const float* bv      = (const float*)d_in[9];
    const float* W_ih    = (const float*)d_in[10];
    const float* b_ih    = (const float*)d_in[11];
    const float* W_hh    = (const float*)d_in[12];
    const float* b_hh    = (const float*)d_in[13];
    const float* ln_in_g = (const float*)d_in[14];
    const float* ln_in_b = (const float*)d_in[15];
    const float* ln_s_g  = (const float*)d_in[16];
    const float* ln_s_b  = (const float*)d_in[17];
    const float* ln_ff_g = (const float*)d_in[18];
    const float* ln_ff_b = (const float*)d_in[19];
    const float* W1      = (const float*)d_in[20];
    const float* b1      = (const float*)d_in[21];
    const float* W2      = (const float*)d_in[22];
    const float* b2      = (const float*)d_in[23];

    float* out = (float*)d_out;
    float* out_slots = out;
    float* out_attn  = out + BK_ * D_;

    kSetup<<<1475, 256>>>(W_ih, W_hh, Wv, W1, W2, noise, slot_mu, slot_ls, Wq, Wk, bq, bk);
    kSlotA<<<128, 1024>>>(ln_s_g, ln_s_b, ln_in_g, ln_in_b);

    for (int it = 0; it < 3; it++) {
        int last = (it == 2);
        kFA<<<dim3(16, 64), 128>>>(inputs, last, out_attn);
        kSlotB<<<128, 1024>>>(ln_in_g, ln_in_b, bv, b_ih, b_hh,
                              ln_ff_g, ln_ff_b, b1, b2, ln_s_g, ln_s_b,
                              last, out_slots);
    }
}

// round 10
// speedup vs baseline: 1.7937x; 1.1097x over previous
#include <cuda_runtime.h>
#include <math.h>
#include <stdint.h>
#include <stddef.h>

// ---------------- problem dims ----------------
#define B_    64
#define N_    4096
#define DIN_  256
#define K_    8
#define D_    256
#define H_    512
#define BK_   512
#define SCALE_ 0.0625f
#define EPSLN 1e-5f
#define EPSA  1e-8f

typedef unsigned long long u64;

// ---------------- device scratch ----------------
__device__ __align__(16) float g_slots[BK_ * D_];
__device__ __align__(16) float g_gq[BK_ * D_];      // g ⊙ qt
__device__ float g_C1[BK_];
__device__ float g_C2[BK_];
__device__ __align__(16) float g_P[BK_ * D_];       // Σ a*rs*v
__device__ float g_SA[BK_];
__device__ float g_SW[BK_];
__device__ __align__(16) float g_Wqk[D_ * D_];
__device__ float g_bqk[D_];
__device__ float g_wb[D_];
__device__ float g_c0;
__device__ __align__(16) float g_WihT[D_ * 3 * D_];
__device__ __align__(16) float g_WhhT[D_ * 3 * D_];
__device__ __align__(16) float g_WvT[D_ * D_];
__device__ __align__(16) float g_W1T[D_ * H_];
__device__ __align__(16) float g_W2T[H_ * D_];

// ---------------- f32x2 packed helpers ----------------
__device__ __forceinline__ u64 pk2(float x, float y) {
    u64 r; asm("mov.b64 %0, {%1, %2};" : "=l"(r) : "f"(x), "f"(y)); return r;
}
__device__ __forceinline__ void upk2(u64 v, float& x, float& y) {
    asm("mov.b64 {%0, %1}, %2;" : "=f"(x), "=f"(y) : "l"(v));
}
__device__ __forceinline__ void fma2(u64& d, u64 a, u64 b) {
    asm("fma.rn.f32x2 %0, %1, %2, %0;" : "+l"(d) : "l"(a), "l"(b));
}

// ---------------- block reduce (2 values, 256-thread kernels) ----------------
__device__ __forceinline__ void blockReduce2(float& a, float& b) {
    #pragma unroll
    for (int o = 16; o; o >>= 1) {
        a += __shfl_xor_sync(0xffffffffu, a, o);
        b += __shfl_xor_sync(0xffffffffu, b, o);
    }
    __shared__ float sa[8], sb[8];
    __syncthreads();
    int w = threadIdx.x >> 5;
    if ((threadIdx.x & 31) == 0) { sa[w] = a; sb[w] = b; }
    __syncthreads();
    a = sa[threadIdx.x & 7];
    b = sb[threadIdx.x & 7];
    #pragma unroll
    for (int o = 4; o; o >>= 1) {
        a += __shfl_xor_sync(0xffffffffu, a, o);
        b += __shfl_xor_sync(0xffffffffu, b, o);
    }
}

// ---------------- group reduce: 1024 threads, 4 independent groups of 256 ----------------
__device__ __forceinline__ void grpReduce2(float& a, float& b) {
    #pragma unroll
    for (int o = 16; o; o >>= 1) {
        a += __shfl_xor_sync(0xffffffffu, a, o);
        b += __shfl_xor_sync(0xffffffffu, b, o);
    }
    __shared__ float sa[32], sb[32];
    int w = threadIdx.x >> 5;
    __syncthreads();
    if ((threadIdx.x & 31) == 0) { sa[w] = a; sb[w] = b; }
    __syncthreads();
    int g8 = (threadIdx.x >> 8) << 3;
    float ra = 0.f, rb = 0.f;
    #pragma unroll
    for (int i = 0; i < 8; i++) { ra += sa[g8 + i]; rb += sb[g8 + i]; }
    a = ra; b = rb;
}

// ---------------- partial-k GEMV ----------------
__device__ __forceinline__ void gemvPart(const float* __restrict__ W, int rstride, int L,
                                         const float* s_in, int in_stride, int j, int kbase,
                                         float acc[4]) {
    const float* p = W + (size_t)kbase * rstride + j;
    #pragma unroll 4
    for (int kk = 0; kk < L; kk += 4) {
        float w0 = p[0];
        float w1 = p[rstride];
        float w2 = p[2 * rstride];
        float w3 = p[3 * rstride];
        p += 4 * rstride;
        #pragma unroll
        for (int r = 0; r < 4; r++) {
            float4 x = *(const float4*)(s_in + r * in_stride + kbase + kk);
            acc[r] = fmaf(x.x, w0, fmaf(x.y, w1, fmaf(x.z, w2, fmaf(x.w, w3, acc[r]))));
        }
    }
}

// ---------------- reduction wave ----------------
__device__ __forceinline__ float reduceWave(const float part[4], float* sRed, int q, int j) {
    __syncthreads();
    #pragma unroll
    for (int r = 0; r < 4; r++) sRed[((q << 2) + r) * 256 + j] = part[r];
    __syncthreads();
    return (sRed[(0 + q) * 256 + j] + sRed[(4 + q) * 256 + j]) +
           (sRed[(8 + q) * 256 + j] + sRed[(12 + q) * 256 + j]);
}

// ---------------- slot-A body (1024 threads) ----------------
__device__ __forceinline__ void slotABody(const float (*s_sn)[256], float* sRed,
                                          int r0, int q, int j,
                                          const float* __restrict__ gg, const float* __restrict__ gb) {
    float acc[4] = {0.f, 0.f, 0.f, 0.f};
    gemvPart(g_Wqk, 256, 64, &s_sn[0][0], 256, j, 64 * q, acc);
    float qt = reduceWave(acc, sRed, q, j) + g_bqk[j];
    int row = r0 + q;
    float gq = gg[j] * qt;
    g_gq[(size_t)row * 256 + j] = gq;
    float c1 = gq;
    float c2 = fmaf(qt, gb[j], s_sn[q][j] * g_wb[j]);
    grpReduce2(c1, c2);
    if (j == 0) { g_C1[row] = c1; g_C2[row] = c2 + g_c0; }
    g_P[(size_t)row * 256 + j] = 0.f;
    if (j == 0) { g_SA[row] = 0.f; g_SW[row] = 0.f; }
}

// =================== SETUP ===================
__device__ __forceinline__ void tTile(const float* __restrict__ src, float* __restrict__ dst,
                                      int R, int C, int bx, int by) {
    __shared__ float t[32][33];
    int tx = threadIdx.x & 31, ty = threadIdx.x >> 5;
    int c = bx * 32 + tx;
    int r = by * 32 + ty;
    #pragma unroll
    for (int k = 0; k < 32; k += 8)
        t[ty + k][tx] = src[(size_t)(r + k) * C + c];
    __syncthreads();
    int cc = bx * 32 + ty;
    int rr = by * 32 + tx;
    #pragma unroll
    for (int k = 0; k < 32; k += 8)
        dst[(size_t)(cc + k) * R + rr] = t[tx][ty + k];
}

__global__ void __launch_bounds__(256) kSetup(const float* __restrict__ W_ih, const float* __restrict__ W_hh,
                                              const float* __restrict__ Wv, const float* __restrict__ W1,
                                              const float* __restrict__ W2, const float* __restrict__ noise,
                                              const float* __restrict__ mu, const float* __restrict__ ls,
                                              const float* __restrict__ Wq, const float* __restrict__ Wk,
                                              const float* __restrict__ bq, const float* __restrict__ bk) {
    int t = blockIdx.x;
    int i = threadIdx.x;
    if (t < 192)       tTile(W_ih, g_WihT, 768, 256, t & 7, t >> 3);
    else if (t < 384)  { int u = t - 192; tTile(W_hh, g_WhhT, 768, 256, u & 7, u >> 3); }
    else if (t < 448)  { int u = t - 384; tTile(Wv,   g_WvT,  256, 256, u & 7, u >> 3); }
    else if (t < 576)  { int u = t - 448; tTile(W1,   g_W1T,  512, 256, u & 7, u >> 3); }
    else if (t < 704)  { int u = t - 576; tTile(W2,   g_W2T,  256, 512, u & 15, u >> 4); }
    else if (t < 1216) {
        int idx = (t - 704) * 256 + i;
        int d = idx & 255;
        g_slots[idx] = mu[d] + __expf(ls[d]) * noise[idx];
    } else if (t < 1472) {
        int jj = t - 1216;
        float acc[8] = {0.f,0.f,0.f,0.f,0.f,0.f,0.f,0.f};
        #pragma unroll 4
        for (int d = 0; d < 256; d += 8) {
            #pragma unroll
            for (int u = 0; u < 8; u++)
                acc[u] = fmaf(Wq[(d + u) * 256 + jj], Wk[(d + u) * 256 + i], acc[u]);
        }
        g_Wqk[jj * 256 + i] =
            (((acc[0] + acc[1]) + (acc[2] + acc[3])) + ((acc[4] + acc[5]) + (acc[6] + acc[7]))) * SCALE_;
    } else if (t == 1472) {
        float a = 0.f;
        #pragma unroll 8
        for (int d = 0; d < 256; d++) a = fmaf(bq[d], Wk[d * 256 + i], a);
        g_bqk[i] = a * SCALE_;
    } else if (t == 1473) {
        float a = 0.f;
        #pragma unroll 8
        for (int d = 0; d < 256; d++) a = fmaf(Wq[d * 256 + i], bk[d], a);
        g_wb[i] = a * SCALE_;
    } else {
        float a = bq[i] * bk[i], dm = 0.f;
        blockReduce2(a, dm);
        if (i == 0) g_c0 = a * SCALE_;
    }
}

// =================== kSlotA (iteration 0 only) ===================
__global__ void __launch_bounds__(1024) kSlotA(const float* __restrict__ ls_g, const float* __restrict__ ls_b,
                                               const float* __restrict__ gg, const float* __restrict__ gb) {
    __shared__ float sSN[4][256];
    __shared__ float sRed[4096];
    int j = threadIdx.x & 255, q = threadIdx.x >> 8;
    int r0 = blockIdx.x * 4;
    float v = g_slots[(size_t)(r0 + q) * 256 + j];
    float a = v, b = v * v;
    grpReduce2(a, b);
    float m = a * (1.0f / 256.0f);
    float var = b * (1.0f / 256.0f) - m * m;
    float rs = rsqrtf(var + EPSLN);
    sSN[q][j] = (v - m) * rs * ls_g[j] + ls_b[j];
    __syncthreads();
    slotABody(sSN, sRed, r0, q, j, gg, gb);
}

// ============ kFA: LN + dots + softmax + P/SA/SW accumulation ============
// grid (16, 64), block 128 (4 warps), each warp 64 rows.
// gq in SHARED (8KB, identical for all warps in block) -> regs ~130 -> 4 blocks/SM.
__global__ void __launch_bounds__(128, 4) kFA(const float* __restrict__ inputs,
                                              int last, float* __restrict__ out_attn) {
    int b = blockIdx.y;
    int warp = threadIdx.x >> 5, lane = threadIdx.x & 31;
    int row0 = blockIdx.x * 256 + warp * 64;
    int r8 = b * 8;
    int slane = ((lane & 1) << 2) | (lane & 2) | ((lane >> 2) & 1);

    __shared__ __align__(16) float sGQ[8][256];    // 8KB
    // cooperative load: rows r8..r8+7 of g_gq are contiguous
    {
        const float4* src = (const float4*)(g_gq + (size_t)r8 * 256);
        #pragma unroll
        for (int e = threadIdx.x; e < 512; e += 128)
            ((float4*)sGQ)[e] = src[e];
    }
    float C1s = g_C1[r8 + slane], C2s = g_C2[r8 + slane];
    __syncthreads();

    u64 zero2 = pk2(0.f, 0.f);
    u64 P[8][4];
    #pragma unroll
    for (int k = 0; k < 8; k++) { P[k][0] = zero2; P[k][1] = zero2; P[k][2] = zero2; P[k][3] = zero2; }
    float SAl = 0.f, SWl = 0.f;

    const float4* vp = (const float4*)(inputs + ((size_t)b * N_ + row0) * 256);
    float4 a0 = vp[lane], a1 = vp[lane + 32];

    for (int r = 0; r < 64; r++) {
        int n = row0 + r;
        float4 b0v, b1v;
        if (r < 63) {
            const float4* vn = vp + (size_t)(r + 1) * 64;
            b0v = vn[lane]; b1v = vn[lane + 32];
        }
        // LN stats (distributed reduce)
        float s  = ((a0.x + a0.y) + (a0.z + a0.w)) + ((a1.x + a1.y) + (a1.z + a1.w));
        float ss = fmaf(a0.x, a0.x, fmaf(a0.y, a0.y, fmaf(a0.z, a0.z, fmaf(a0.w, a0.w,
                   fmaf(a1.x, a1.x, fmaf(a1.y, a1.y, fmaf(a1.z, a1.z, a1.w * a1.w)))))));
        {
            bool odd = lane & 1;
            float send = odd ? s : ss;
            float rcv = __shfl_xor_sync(0xffffffffu, send, 1);
            float v = odd ? (ss + rcv) : (s + rcv);
            v += __shfl_xor_sync(0xffffffffu, v, 2);
            v += __shfl_xor_sync(0xffffffffu, v, 4);
            v += __shfl_xor_sync(0xffffffffu, v, 8);
            v += __shfl_xor_sync(0xffffffffu, v, 16);
            float o = __shfl_xor_sync(0xffffffffu, v, 1);
            s  = odd ? o : v;
            ss = odd ? v : o;
        }
        float m   = s * (1.0f / 256.0f);
        float var = fmaf(ss, 1.0f / 256.0f, -m * m);
        float rs  = rsqrtf(var + EPSLN);
        float w   = m * rs;

        u64 x01 = pk2(a0.x, a0.y), x23 = pk2(a0.z, a0.w);
        u64 x45 = pk2(a1.x, a1.y), x67 = pk2(a1.z, a1.w);

        // dots: gq from shared (2x LDS.128 per slot)
        float dt[8];
        #pragma unroll
        for (int k = 0; k < 8; k++) {
            ulonglong2 qa = *(const ulonglong2*)(&sGQ[k][4 * lane]);
            ulonglong2 qb = *(const ulonglong2*)(&sGQ[k][128 + 4 * lane]);
            u64 d2 = zero2;
            fma2(d2, x01, qa.x); fma2(d2, x23, qa.y);
            fma2(d2, x45, qb.x); fma2(d2, x67, qb.y);
            float lo, hi; upk2(d2, lo, hi);
            dt[k] = lo + hi;
        }
        float vdot;
        {
            bool c0 = lane & 1;
            float t0 = c0 ? dt[0] : dt[4];
            float t1 = c0 ? dt[1] : dt[5];
            float t2 = c0 ? dt[2] : dt[6];
            float t3 = c0 ? dt[3] : dt[7];
            t0 = __shfl_xor_sync(0xffffffffu, t0, 1);
            t1 = __shfl_xor_sync(0xffffffffu, t1, 1);
            t2 = __shfl_xor_sync(0xffffffffu, t2, 1);
            t3 = __shfl_xor_sync(0xffffffffu, t3, 1);
            float u0 = (c0 ? dt[4] : dt[0]) + t0;
            float u1 = (c0 ? dt[5] : dt[1]) + t1;
            float u2 = (c0 ? dt[6] : dt[2]) + t2;
            float u3 = (c0 ? dt[7] : dt[3]) + t3;
            bool c1 = lane & 2;
            float s0 = c1 ? u0 : u2;
            float s1 = c1 ? u1 : u3;
            s0 = __shfl_xor_sync(0xffffffffu, s0, 2);
            s1 = __shfl_xor_sync(0xffffffffu, s1, 2);
            float w0 = (c1 ? u2 : u0) + s0;
            float w1 = (c1 ? u3 : u1) + s1;
            bool c2 = lane & 4;
            float s2 = c2 ? w0 : w1;
            s2 = __shfl_xor_sync(0xffffffffu, s2, 4);
            vdot = (c2 ? w1 : w0) + s2;
            vdot += __shfl_xor_sync(0xffffffffu, vdot, 8);
            vdot += __shfl_xor_sync(0xffffffffu, vdot, 16);
        }
        float lg = fmaf(rs, vdot, fmaf(-w, C1s, C2s));
        float mx = lg;
        mx = fmaxf(mx, __shfl_xor_sync(0xffffffffu, mx, 1));
        mx = fmaxf(mx, __shfl_xor_sync(0xffffffffu, mx, 2));
        mx = fmaxf(mx, __shfl_xor_sync(0xffffffffu, mx, 4));
        float e = __expf(lg - mx);
        float sm = e;
        sm += __shfl_xor_sync(0xffffffffu, sm, 1);
        sm += __shfl_xor_sync(0xffffffffu, sm, 2);
        sm += __shfl_xor_sync(0xffffffffu, sm, 4);
        float a = __fdividef(e, sm);
        SAl += a;
        SWl = fmaf(a, w, SWl);
        if (last && lane < 8)
            out_attn[(size_t)(r8 + slane) * N_ + n] = a;

        int gbase = lane & 24;
        float ak[8];
        ak[0] = __shfl_sync(0xffffffffu, a, gbase | 0);
        ak[1] = __shfl_sync(0xffffffffu, a, gbase | 4);
        ak[2] = __shfl_sync(0xffffffffu, a, gbase | 2);
        ak[3] = __shfl_sync(0xffffffffu, a, gbase | 6);
        ak[4] = __shfl_sync(0xffffffffu, a, gbase | 1);
        ak[5] = __shfl_sync(0xffffffffu, a, gbase | 5);
        ak[6] = __shfl_sync(0xffffffffu, a, gbase | 3);
        ak[7] = __shfl_sync(0xffffffffu, a, gbase | 7);

        #pragma unroll
        for (int k = 0; k < 8; k++) {
            float ar = ak[k] * rs;
            u64 ap = pk2(ar, ar);
            fma2(P[k][0], ap, x01); fma2(P[k][1], ap, x23);
            fma2(P[k][2], ap, x45); fma2(P[k][3], ap, x67);
        }
        a0 = b0v; a1 = b1v;
    }

    // flush: block-level smem reduction, then atomics (reuse sGQ as scratch + extra)
    __shared__ float sP[4][8][256];
    __shared__ float sSA[4][8], sSW[4][8];
    #pragma unroll
    for (int k = 0; k < 8; k++) {
        float x, y;
        upk2(P[k][0], x, y); sP[warp][k][4 * lane] = x;       sP[warp][k][4 * lane + 1] = y;
        upk2(P[k][1], x, y); sP[warp][k][4 * lane + 2] = x;   sP[warp][k][4 * lane + 3] = y;
        upk2(P[k][2], x, y); sP[warp][k][128 + 4 * lane] = x; sP[warp][k][128 + 4 * lane + 1] = y;
        upk2(P[k][3], x, y); sP[warp][k][128 + 4 * lane + 2] = x; sP[warp][k][128 + 4 * lane + 3] = y;
    }
    if (lane < 8) { sSA[warp][slane] = SAl; sSW[warp][slane] = SWl; }
    __syncthreads();
    for (int t = threadIdx.x; t < 2048; t += 128) {
        int k = t >> 8, d = t & 255;
        float v = (sP[0][k][d] + sP[1][k][d]) + (sP[2][k][d] + sP[3][k][d]);
        atomicAdd(&g_P[(size_t)(r8 + k) * 256 + d], v);
    }
    if (threadIdx.x < 8) {
        int k = threadIdx.x;
        atomicAdd(&g_SA[r8 + k], (sSA[0][k] + sSA[1][k]) + (sSA[2][k] + sSA[3][k]));
    } else if (threadIdx.x < 16) {
        int k = threadIdx.x - 8;
        atomicAdd(&g_SW[r8 + k], (sSW[0][k] + sSW[1][k]) + (sSW[2][k] + sSW[3][k]));
    }
}

// =================== kSlotB ===================
__global__ void __launch_bounds__(1024) kSlotB(const float* __restrict__ gg, const float* __restrict__ gb,
                                               const float* __restrict__ bv,
                                               const float* __restrict__ b_ih, const float* __restrict__ b_hh,
                                               const float* __restrict__ lnf_g, const float* __restrict__ lnf_b,
                                               const float* __restrict__ b1, const float* __restrict__ b2,
                                               const float* __restrict__ ls_g, const float* __restrict__ ls_b,
                                               int last, float* __restrict__ out_slots) {
    __shared__ float sA[4][256];
    __shared__ float sB[4][256];
    __shared__ float sSL[4][256];
    __shared__ float sF1[4][512];
    __shared__ float sRed[4096];
    int j = threadIdx.x & 255, q = threadIdx.x >> 8;
    int r0 = blockIdx.x * 4;
    int row = r0 + q;

    float snorm;
    {
        float SA = g_SA[row], SW = g_SW[row];
        float inv = 1.0f / (SA + EPSA);
        float Pv = g_P[(size_t)row * 256 + j];
        sA[q][j] = (gg[j] * (Pv - SW) + gb[j] * SA) * inv;
        sSL[q][j] = g_slots[(size_t)row * 256 + j];
        snorm = SA * inv;
    }
    __syncthreads();

    {
        float acc[4] = {0.f, 0.f, 0.f, 0.f};
        gemvPart(g_WvT, 256, 64, &sA[0][0], 256, j, 64 * q, acc);
        float x = reduceWave(acc, sRed, q, j);
        sB[q][j] = fmaf(snorm, bv[j], x);
    }
    __syncthreads();

    float ir, iz, inn;
    {
        float pir[4] = {}, piz[4] = {}, pin[4] = {};
        const float* pw = g_WihT + (size_t)(64 * q) * 768 + j;
        #pragma unroll 4
        for (int kk = 0; kk < 64; kk += 2) {
            float wr0 = pw[0],   wz0 = pw[256],       wn0 = pw[512];
            float wr1 = pw[768], wz1 = pw[768 + 256], wn1 = pw[768 + 512];
            pw += 1536;
            #pragma unroll
            for (int r = 0; r < 4; r++) {
                float2 x = *(const float2*)(&sB[r][64 * q + kk]);
                pir[r] = fmaf(x.x, wr0, fmaf(x.y, wr1, pir[r]));
                piz[r] = fmaf(x.x, wz0, fmaf(x.y, wz1, piz[r]));
                pin[r] = fmaf(x.x, wn0, fmaf(x.y, wn1, pin[r]));
            }
        }
        ir  = reduceWave(pir, sRed, q, j);
        iz  = reduceWave(piz, sRed, q, j);
        inn = reduceWave(pin, sRed, q, j);
    }
    float hr, hz, hn;
    {
        float phr[4] = {}, phz[4] = {}, phn[4] = {};
        const float* pw = g_WhhT + (size_t)(64 * q) * 768 + j;
        #pragma unroll 4
        for (int kk = 0; kk < 64; kk += 2) {
            float vr0 = pw[0],   vz0 = pw[256],       vn0 = pw[512];
            float vr1 = pw[768], vz1 = pw[768 + 256], vn1 = pw[768 + 512];
            pw += 1536;
            #pragma unroll
            for (int r = 0; r < 4; r++) {
                float2 x = *(const float2*)(&sSL[r][64 * q + kk]);
                phr[r] = fmaf(x.x, vr0, fmaf(x.y, vr1, phr[r]));
                phz[r] = fmaf(x.x, vz0, fmaf(x.y, vz1, phz[r]));
                phn[r] = fmaf(x.x, vn0, fmaf(x.y, vn1, phn[r]));
            }
        }
        hr = reduceWave(phr, sRed, q, j);
        hz = reduceWave(phz, sRed, q, j);
        hn = reduceWave(phn, sRed, q, j);
    }

    float h_reg;
    {
        float rr = 1.0f / (1.0f + __expf(-(ir + b_ih[j] + hr + b_hh[j])));
        float zz = 1.0f / (1.0f + __expf(-(iz + b_ih[256 + j] + hz + b_hh[256 + j])));
        float nn = tanhf(inn + b_ih[512 + j] + rr * (hn + b_hh[512 + j]));
        float h = (1.0f - zz) * nn + zz * sSL[q][j];
        h_reg = h;
        float a = h, bb = h * h;
        grpReduce2(a, bb);
        float m = a * (1.0f / 256.0f);
        float var = bb * (1.0f / 256.0f) - m * m;
        float rs = rsqrtf(var + EPSLN);
        __syncthreads();
        sA[q][j] = (h - m) * rs * lnf_g[j] + lnf_b[j];
    }
    __syncthreads();

    {
        float f0[4] = {}, f1v[4] = {};
        const float* p1 = g_W1T + (size_t)(64 * q) * 512 + j;
        #pragma unroll 4
        for (int kk = 0; kk < 64; kk += 2) {
            float wa0 = p1[0],   wb0 = p1[256];
            float wa1 = p1[512], wb1 = p1[512 + 256];
            p1 += 1024;
            #pragma unroll
            for (int r = 0; r < 4; r++) {
                float2 x = *(const float2*)(&sA[r][64 * q + kk]);
                f0[r]  = fmaf(x.x, wa0, fmaf(x.y, wa1, f0[r]));
                f1v[r] = fmaf(x.x, wb0, fmaf(x.y, wb1, f1v[r]));
            }
        }
        float h0 = reduceWave(f0, sRed, q, j);
        float h1 = reduceWave(f1v, sRed, q, j);
        sF1[q][j]       = fmaxf(h0 + b1[j], 0.f);
        sF1[q][256 + j] = fmaxf(h1 + b1[256 + j], 0.f);
    }
    __syncthreads();

    float ns;
    {
        float o[4] = {0.f, 0.f, 0.f, 0.f};
        gemvPart(g_W2T, 256, 128, &sF1[0][0], 512, j, 128 * q, o);
        float oo = reduceWave(o, sRed, q, j);
        ns = h_reg + oo + b2[j];
        g_slots[(size_t)row * 256 + j] = ns;
        if (last) out_slots[(size_t)row * 256 + j] = ns;
    }

    if (!last) {
        float a = ns, bb = ns * ns;
        grpReduce2(a, bb);
        float m = a * (1.0f / 256.0f);
        float var = bb * (1.0f / 256.0f) - m * m;
        float rs = rsqrtf(var + EPSLN);
        __syncthreads();
        sB[q][j] = (ns - m) * rs * ls_g[j] + ls_b[j];
        __syncthreads();
        slotABody((const float (*)[256])sB, sRed, r0, q, j, gg, gb);
    }
}

// ---------------- launch ----------------
extern "C" void kernel_launch(void* const* d_in, const int* in_sizes, int n_in,
                              void* d_out, int out_size) {
    (void)in_sizes; (void)n_in; (void)out_size;
    const float* inputs  = (const float*)d_in[0];
    const float* noise   = (const float*)d_in[1];
    const float* slot_mu = (const float*)d_in[2];
    const float* slot_ls = (const float*)d_in[3];
    const float* Wq      = (const float*)d_in[4];
    const float* bq      = (const float*)d_in[5];
    const float* Wk      = (const float*)d_in[6];
    const float* bk      = (const float*)d_in[7];
    const float* Wv      = (const float*)d_in[8];
    const float* bv      = (const float*)d_in[9];
    const float* W_ih    = (const float*)d_in[10];
    const float* b_ih    = (const float*)d_in[11];
    const float* W_hh    = (const float*)d_in[12];
    const float* b_hh    = (const float*)d_in[13];
    const float* ln_in_g = (const float*)d_in[14];
    const float* ln_in_b = (const float*)d_in[15];
    const float* ln_s_g  = (const float*)d_in[16];
    const float* ln_s_b  = (const float*)d_in[17];
    const float* ln_ff_g = (const float*)d_in[18];
    const float* ln_ff_b = (const float*)d_in[19];
    const float* W1      = (const float*)d_in[20];
    const float* b1      = (const float*)d_in[21];
    const float* W2      = (const float*)d_in[22];
    const float* b2      = (const float*)d_in[23];

    float* out = (float*)d_out;
    float* out_slots = out;
    float* out_attn  = out + BK_ * D_;

    kSetup<<<1475, 256>>>(W_ih, W_hh, Wv, W1, W2, noise, slot_mu, slot_ls, Wq, Wk, bq, bk);
    kSlotA<<<128, 1024>>>(ln_s_g, ln_s_b, ln_in_g, ln_in_b);

    for (int it = 0; it < 3; it++) {
        int last = (it == 2);
        kFA<<<dim3(16, 64), 128>>>(inputs, last, out_attn);
        kSlotB<<<128, 1024>>>(ln_in_g, ln_in_b, bv, b_ih, b_hh,
                              ln_ff_g, ln_ff_b, b1, b2, ln_s_g, ln_s_b,
                              last, out_slots);
    }
}

// round 11
// speedup vs baseline: 1.8286x; 1.0195x over previous
#include <cuda_runtime.h>
#include <math.h>
#include <stdint.h>
#include <stddef.h>

// ---------------- problem dims ----------------
#define B_    64
#define N_    4096
#define DIN_  256
#define K_    8
#define D_    256
#define H_    512
#define BK_   512
#define SCALE_ 0.0625f
#define EPSLN 1e-5f
#define EPSA  1e-8f

typedef unsigned long long u64;

// ---------------- device scratch ----------------
__device__ __align__(16) float g_slots[BK_ * D_];
__device__ __align__(16) float g_gq[BK_ * D_];      // g ⊙ qt
__device__ float g_C1[BK_];
__device__ float g_C2[BK_];
__device__ __align__(16) float g_P[BK_ * D_];       // Σ a*rs*v
__device__ float g_SA[BK_];
__device__ float g_SW[BK_];
__device__ __align__(16) float g_Wqk[D_ * D_];
__device__ float g_bqk[D_];
__device__ float g_wb[D_];
__device__ float g_c0;
__device__ __align__(16) float g_WihT[D_ * 3 * D_];
__device__ __align__(16) float g_WhhT[D_ * 3 * D_];
__device__ __align__(16) float g_WvT[D_ * D_];
__device__ __align__(16) float g_W1T[D_ * H_];
__device__ __align__(16) float g_W2T[H_ * D_];

// ---------------- f32x2 packed helpers ----------------
__device__ __forceinline__ u64 pk2(float x, float y) {
    u64 r; asm("mov.b64 %0, {%1, %2};" : "=l"(r) : "f"(x), "f"(y)); return r;
}
__device__ __forceinline__ void upk2(u64 v, float& x, float& y) {
    asm("mov.b64 {%0, %1}, %2;" : "=f"(x), "=f"(y) : "l"(v));
}
__device__ __forceinline__ void fma2(u64& d, u64 a, u64 b) {
    asm("fma.rn.f32x2 %0, %1, %2, %0;" : "+l"(d) : "l"(a), "l"(b));
}
__device__ __forceinline__ u64 add2(u64 a, u64 b) {
    u64 r; asm("add.rn.f32x2 %0, %1, %2;" : "=l"(r) : "l"(a), "l"(b)); return r;
}
__device__ __forceinline__ u64 mul2(u64 a, u64 b) {
    u64 r; asm("mul.rn.f32x2 %0, %1, %2;" : "=l"(r) : "l"(a), "l"(b)); return r;
}

// ---------------- block reduce (2 values, 256-thread kernels) ----------------
__device__ __forceinline__ void blockReduce2(float& a, float& b) {
    #pragma unroll
    for (int o = 16; o; o >>= 1) {
        a += __shfl_xor_sync(0xffffffffu, a, o);
        b += __shfl_xor_sync(0xffffffffu, b, o);
    }
    __shared__ float sa[8], sb[8];
    __syncthreads();
    int w = threadIdx.x >> 5;
    if ((threadIdx.x & 31) == 0) { sa[w] = a; sb[w] = b; }
    __syncthreads();
    a = sa[threadIdx.x & 7];
    b = sb[threadIdx.x & 7];
    #pragma unroll
    for (int o = 4; o; o >>= 1) {
        a += __shfl_xor_sync(0xffffffffu, a, o);
        b += __shfl_xor_sync(0xffffffffu, b, o);
    }
}

// ---------------- group reduce: 1024 threads, 4 independent groups of 256 ----------------
__device__ __forceinline__ void grpReduce2(float& a, float& b) {
    #pragma unroll
    for (int o = 16; o; o >>= 1) {
        a += __shfl_xor_sync(0xffffffffu, a, o);
        b += __shfl_xor_sync(0xffffffffu, b, o);
    }
    __shared__ float sa[32], sb[32];
    int w = threadIdx.x >> 5;
    __syncthreads();
    if ((threadIdx.x & 31) == 0) { sa[w] = a; sb[w] = b; }
    __syncthreads();
    int g8 = (threadIdx.x >> 8) << 3;
    float ra = 0.f, rb = 0.f;
    #pragma unroll
    for (int i = 0; i < 8; i++) { ra += sa[g8 + i]; rb += sb[g8 + i]; }
    a = ra; b = rb;
}

// ---------------- partial-k GEMV ----------------
__device__ __forceinline__ void gemvPart(const float* __restrict__ W, int rstride, int L,
                                         const float* s_in, int in_stride, int j, int kbase,
                                         float acc[4]) {
    const float* p = W + (size_t)kbase * rstride + j;
    #pragma unroll 4
    for (int kk = 0; kk < L; kk += 4) {
        float w0 = p[0];
        float w1 = p[rstride];
        float w2 = p[2 * rstride];
        float w3 = p[3 * rstride];
        p += 4 * rstride;
        #pragma unroll
        for (int r = 0; r < 4; r++) {
            float4 x = *(const float4*)(s_in + r * in_stride + kbase + kk);
            acc[r] = fmaf(x.x, w0, fmaf(x.y, w1, fmaf(x.z, w2, fmaf(x.w, w3, acc[r]))));
        }
    }
}

// ---------------- reduction wave ----------------
__device__ __forceinline__ float reduceWave(const float part[4], float* sRed, int q, int j) {
    __syncthreads();
    #pragma unroll
    for (int r = 0; r < 4; r++) sRed[((q << 2) + r) * 256 + j] = part[r];
    __syncthreads();
    return (sRed[(0 + q) * 256 + j] + sRed[(4 + q) * 256 + j]) +
           (sRed[(8 + q) * 256 + j] + sRed[(12 + q) * 256 + j]);
}

// ---------------- slot-A body (1024 threads) ----------------
__device__ __forceinline__ void slotABody(const float (*s_sn)[256], float* sRed,
                                          int r0, int q, int j,
                                          const float* __restrict__ gg, const float* __restrict__ gb) {
    float acc[4] = {0.f, 0.f, 0.f, 0.f};
    gemvPart(g_Wqk, 256, 64, &s_sn[0][0], 256, j, 64 * q, acc);
    float qt = reduceWave(acc, sRed, q, j) + g_bqk[j];
    int row = r0 + q;
    float gq = gg[j] * qt;
    g_gq[(size_t)row * 256 + j] = gq;
    float c1 = gq;
    float c2 = fmaf(qt, gb[j], s_sn[q][j] * g_wb[j]);
    grpReduce2(c1, c2);
    if (j == 0) { g_C1[row] = c1; g_C2[row] = c2 + g_c0; }
    g_P[(size_t)row * 256 + j] = 0.f;
    if (j == 0) { g_SA[row] = 0.f; g_SW[row] = 0.f; }
}

// =================== SETUP ===================
__device__ __forceinline__ void tTile(const float* __restrict__ src, float* __restrict__ dst,
                                      int R, int C, int bx, int by) {
    __shared__ float t[32][33];
    int tx = threadIdx.x & 31, ty = threadIdx.x >> 5;
    int c = bx * 32 + tx;
    int r = by * 32 + ty;
    #pragma unroll
    for (int k = 0; k < 32; k += 8)
        t[ty + k][tx] = src[(size_t)(r + k) * C + c];
    __syncthreads();
    int cc = bx * 32 + ty;
    int rr = by * 32 + tx;
    #pragma unroll
    for (int k = 0; k < 32; k += 8)
        dst[(size_t)(cc + k) * R + rr] = t[tx][ty + k];
}

__global__ void __launch_bounds__(256) kSetup(const float* __restrict__ W_ih, const float* __restrict__ W_hh,
                                              const float* __restrict__ Wv, const float* __restrict__ W1,
                                              const float* __restrict__ W2, const float* __restrict__ noise,
                                              const float* __restrict__ mu, const float* __restrict__ ls,
                                              const float* __restrict__ Wq, const float* __restrict__ Wk,
                                              const float* __restrict__ bq, const float* __restrict__ bk) {
    int t = blockIdx.x;
    int i = threadIdx.x;
    if (t < 192)       tTile(W_ih, g_WihT, 768, 256, t & 7, t >> 3);
    else if (t < 384)  { int u = t - 192; tTile(W_hh, g_WhhT, 768, 256, u & 7, u >> 3); }
    else if (t < 448)  { int u = t - 384; tTile(Wv,   g_WvT,  256, 256, u & 7, u >> 3); }
    else if (t < 576)  { int u = t - 448; tTile(W1,   g_W1T,  512, 256, u & 7, u >> 3); }
    else if (t < 704)  { int u = t - 576; tTile(W2,   g_W2T,  256, 512, u & 15, u >> 4); }
    else if (t < 1216) {
        int idx = (t - 704) * 256 + i;
        int d = idx & 255;
        g_slots[idx] = mu[d] + __expf(ls[d]) * noise[idx];
    } else if (t < 1472) {
        int jj = t - 1216;
        float acc[8] = {0.f,0.f,0.f,0.f,0.f,0.f,0.f,0.f};
        #pragma unroll 4
        for (int d = 0; d < 256; d += 8) {
            #pragma unroll
            for (int u = 0; u < 8; u++)
                acc[u] = fmaf(Wq[(d + u) * 256 + jj], Wk[(d + u) * 256 + i], acc[u]);
        }
        g_Wqk[jj * 256 + i] =
            (((acc[0] + acc[1]) + (acc[2] + acc[3])) + ((acc[4] + acc[5]) + (acc[6] + acc[7]))) * SCALE_;
    } else if (t == 1472) {
        float a = 0.f;
        #pragma unroll 8
        for (int d = 0; d < 256; d++) a = fmaf(bq[d], Wk[d * 256 + i], a);
        g_bqk[i] = a * SCALE_;
    } else if (t == 1473) {
        float a = 0.f;
        #pragma unroll 8
        for (int d = 0; d < 256; d++) a = fmaf(Wq[d * 256 + i], bk[d], a);
        g_wb[i] = a * SCALE_;
    } else {
        float a = bq[i] * bk[i], dm = 0.f;
        blockReduce2(a, dm);
        if (i == 0) g_c0 = a * SCALE_;
    }
}

// =================== kSlotA (iteration 0 only) ===================
__global__ void __launch_bounds__(1024) kSlotA(const float* __restrict__ ls_g, const float* __restrict__ ls_b,
                                               const float* __restrict__ gg, const float* __restrict__ gb) {
    __shared__ float sSN[4][256];
    __shared__ float sRed[4096];
    int j = threadIdx.x & 255, q = threadIdx.x >> 8;
    int r0 = blockIdx.x * 4;
    float v = g_slots[(size_t)(r0 + q) * 256 + j];
    float a = v, b = v * v;
    grpReduce2(a, b);
    float m = a * (1.0f / 256.0f);
    float var = b * (1.0f / 256.0f) - m * m;
    float rs = rsqrtf(var + EPSLN);
    sSN[q][j] = (v - m) * rs * ls_g[j] + ls_b[j];
    __syncthreads();
    slotABody(sSN, sRed, r0, q, j, gg, gb);
}

// ============ kFA: LN + dots + softmax + P/SA/SW accumulation ============
// grid (16, 64), block 128 (4 warps), each warp 64 rows.
// Row data held as u64 (f32x2) from the load onward -> no pk2 copies -> regs < 128, no spills.
__global__ void __launch_bounds__(128, 4) kFA(const float* __restrict__ inputs,
                                              int last, float* __restrict__ out_attn) {
    int b = blockIdx.y;
    int warp = threadIdx.x >> 5, lane = threadIdx.x & 31;
    int row0 = blockIdx.x * 256 + warp * 64;
    int r8 = b * 8;
    int slane = ((lane & 1) << 2) | (lane & 2) | ((lane >> 2) & 1);

    __shared__ __align__(16) float sGQ[8][256];    // 8KB
    {
        const float4* src = (const float4*)(g_gq + (size_t)r8 * 256);
        #pragma unroll
        for (int e = threadIdx.x; e < 512; e += 128)
            ((float4*)sGQ)[e] = src[e];
    }
    float C1s = g_C1[r8 + slane], C2s = g_C2[r8 + slane];
    __syncthreads();

    u64 zero2 = pk2(0.f, 0.f);
    u64 P[8][4];
    #pragma unroll
    for (int k = 0; k < 8; k++) { P[k][0] = zero2; P[k][1] = zero2; P[k][2] = zero2; P[k][3] = zero2; }
    float SAl = 0.f, SWl = 0.f;

    // row = 64 ulonglong2; lane owns elements [lane] and [lane+32]
    const ulonglong2* vp = (const ulonglong2*)(inputs + ((size_t)b * N_ + row0) * 256);
    ulonglong2 A0 = vp[lane], A1 = vp[lane + 32];

    #pragma unroll 1
    for (int r = 0; r < 64; r++) {
        int n = row0 + r;
        ulonglong2 B0, B1;
        if (r < 63) {
            const ulonglong2* vn = vp + (size_t)(r + 1) * 64;
            B0 = vn[lane]; B1 = vn[lane + 32];
        }
        // LN stats via packed f32x2
        float s, ss;
        {
            u64 s2  = add2(add2(A0.x, A0.y), add2(A1.x, A1.y));
            u64 ss2 = mul2(A0.x, A0.x);
            fma2(ss2, A0.y, A0.y); fma2(ss2, A1.x, A1.x); fma2(ss2, A1.y, A1.y);
            float lo, hi;
            upk2(s2, lo, hi);  s  = lo + hi;
            upk2(ss2, lo, hi); ss = lo + hi;
        }
        {
            bool odd = lane & 1;
            float send = odd ? s : ss;
            float rcv = __shfl_xor_sync(0xffffffffu, send, 1);
            float v = odd ? (ss + rcv) : (s + rcv);
            v += __shfl_xor_sync(0xffffffffu, v, 2);
            v += __shfl_xor_sync(0xffffffffu, v, 4);
            v += __shfl_xor_sync(0xffffffffu, v, 8);
            v += __shfl_xor_sync(0xffffffffu, v, 16);
            float o = __shfl_xor_sync(0xffffffffu, v, 1);
            s  = odd ? o : v;
            ss = odd ? v : o;
        }
        float m   = s * (1.0f / 256.0f);
        float var = fmaf(ss, 1.0f / 256.0f, -m * m);
        float rs  = rsqrtf(var + EPSLN);
        float w   = m * rs;

        // dots: gq from shared, x straight from A0/A1 (u64-native)
        float dt[8];
        #pragma unroll
        for (int k = 0; k < 8; k++) {
            ulonglong2 qa = *(const ulonglong2*)(&sGQ[k][4 * lane]);
            ulonglong2 qb = *(const ulonglong2*)(&sGQ[k][128 + 4 * lane]);
            u64 d2 = mul2(A0.x, qa.x);
            fma2(d2, A0.y, qa.y);
            fma2(d2, A1.x, qb.x);
            fma2(d2, A1.y, qb.y);
            float lo, hi; upk2(d2, lo, hi);
            dt[k] = lo + hi;
        }
        float vdot;
        {
            bool c0 = lane & 1;
            float t0 = c0 ? dt[0] : dt[4];
            float t1 = c0 ? dt[1] : dt[5];
            float t2 = c0 ? dt[2] : dt[6];
            float t3 = c0 ? dt[3] : dt[7];
            t0 = __shfl_xor_sync(0xffffffffu, t0, 1);
            t1 = __shfl_xor_sync(0xffffffffu, t1, 1);
            t2 = __shfl_xor_sync(0xffffffffu, t2, 1);
            t3 = __shfl_xor_sync(0xffffffffu, t3, 1);
            float u0 = (c0 ? dt[4] : dt[0]) + t0;
            float u1 = (c0 ? dt[5] : dt[1]) + t1;
            float u2 = (c0 ? dt[6] : dt[2]) + t2;
            float u3 = (c0 ? dt[7] : dt[3]) + t3;
            bool c1 = lane & 2;
            float s0 = c1 ? u0 : u2;
            float s1 = c1 ? u1 : u3;
            s0 = __shfl_xor_sync(0xffffffffu, s0, 2);
            s1 = __shfl_xor_sync(0xffffffffu, s1, 2);
            float w0 = (c1 ? u2 : u0) + s0;
            float w1 = (c1 ? u3 : u1) + s1;
            bool c2 = lane & 4;
            float s2 = c2 ? w0 : w1;
            s2 = __shfl_xor_sync(0xffffffffu, s2, 4);
            vdot = (c2 ? w1 : w0) + s2;
            vdot += __shfl_xor_sync(0xffffffffu, vdot, 8);
            vdot += __shfl_xor_sync(0xffffffffu, vdot, 16);
        }
        float lg = fmaf(rs, vdot, fmaf(-w, C1s, C2s));
        float mx = lg;
        mx = fmaxf(mx, __shfl_xor_sync(0xffffffffu, mx, 1));
        mx = fmaxf(mx, __shfl_xor_sync(0xffffffffu, mx, 2));
        mx = fmaxf(mx, __shfl_xor_sync(0xffffffffu, mx, 4));
        float e = __expf(lg - mx);
        float sm = e;
        sm += __shfl_xor_sync(0xffffffffu, sm, 1);
        sm += __shfl_xor_sync(0xffffffffu, sm, 2);
        sm += __shfl_xor_sync(0xffffffffu, sm, 4);
        float a = __fdividef(e, sm);
        SAl += a;
        SWl = fmaf(a, w, SWl);
        if (last && lane < 8)
            out_attn[(size_t)(r8 + slane) * N_ + n] = a;

        int gbase = lane & 24;
        float ak[8];
        ak[0] = __shfl_sync(0xffffffffu, a, gbase | 0);
        ak[1] = __shfl_sync(0xffffffffu, a, gbase | 4);
        ak[2] = __shfl_sync(0xffffffffu, a, gbase | 2);
        ak[3] = __shfl_sync(0xffffffffu, a, gbase | 6);
        ak[4] = __shfl_sync(0xffffffffu, a, gbase | 1);
        ak[5] = __shfl_sync(0xffffffffu, a, gbase | 5);
        ak[6] = __shfl_sync(0xffffffffu, a, gbase | 3);
        ak[7] = __shfl_sync(0xffffffffu, a, gbase | 7);

        #pragma unroll
        for (int k = 0; k < 8; k++) {
            float ar = ak[k] * rs;
            u64 ap = pk2(ar, ar);
            fma2(P[k][0], ap, A0.x); fma2(P[k][1], ap, A0.y);
            fma2(P[k][2], ap, A1.x); fma2(P[k][3], ap, A1.y);
        }
        A0 = B0; A1 = B1;
    }

    __shared__ float sP[4][8][256];
    __shared__ float sSA[4][8], sSW[4][8];
    #pragma unroll
    for (int k = 0; k < 8; k++) {
        float x, y;
        upk2(P[k][0], x, y); sP[warp][k][4 * lane] = x;       sP[warp][k][4 * lane + 1] = y;
        upk2(P[k][1], x, y); sP[warp][k][4 * lane + 2] = x;   sP[warp][k][4 * lane + 3] = y;
        upk2(P[k][2], x, y); sP[warp][k][128 + 4 * lane] = x; sP[warp][k][128 + 4 * lane + 1] = y;
        upk2(P[k][3], x, y); sP[warp][k][128 + 4 * lane + 2] = x; sP[warp][k][128 + 4 * lane + 3] = y;
    }
    if (lane < 8) { sSA[warp][slane] = SAl; sSW[warp][slane] = SWl; }
    __syncthreads();
    for (int t = threadIdx.x; t < 2048; t += 128) {
        int k = t >> 8, d = t & 255;
        float v = (sP[0][k][d] + sP[1][k][d]) + (sP[2][k][d] + sP[3][k][d]);
        atomicAdd(&g_P[(size_t)(r8 + k) * 256 + d], v);
    }
    if (threadIdx.x < 8) {
        int k = threadIdx.x;
        atomicAdd(&g_SA[r8 + k], (sSA[0][k] + sSA[1][k]) + (sSA[2][k] + sSA[3][k]));
    } else if (threadIdx.x < 16) {
        int k = threadIdx.x - 8;
        atomicAdd(&g_SW[r8 + k], (sSW[0][k] + sSW[1][k]) + (sSW[2][k] + sSW[3][k]));
    }
}

// =================== kSlotB ===================
__global__ void __launch_bounds__(1024) kSlotB(const float* __restrict__ gg, const float* __restrict__ gb,
                                               const float* __restrict__ bv,
                                               const float* __restrict__ b_ih, const float* __restrict__ b_hh,
                                               const float* __restrict__ lnf_g, const float* __restrict__ lnf_b,
                                               const float* __restrict__ b1, const float* __restrict__ b2,
                                               const float* __restrict__ ls_g, const float* __restrict__ ls_b,
                                               int last, float* __restrict__ out_slots) {
    __shared__ float sA[4][256];
    __shared__ float sB[4][256];
    __shared__ float sSL[4][256];
    __shared__ float sF1[4][512];
    __shared__ float sRed[4096];
    int j = threadIdx.x & 255, q = threadIdx.x >> 8;
    int r0 = blockIdx.x * 4;
    int row = r0 + q;

    float snorm;
    {
        float SA = g_SA[row], SW = g_SW[row];
        float inv = 1.0f / (SA + EPSA);
        float Pv = g_P[(size_t)row * 256 + j];
        sA[q][j] = (gg[j] * (Pv - SW) + gb[j] * SA) * inv;
        sSL[q][j] = g_slots[(size_t)row * 256 + j];
        snorm = SA * inv;
    }
    __syncthreads();

    {
        float acc[4] = {0.f, 0.f, 0.f, 0.f};
        gemvPart(g_WvT, 256, 64, &sA[0][0], 256, j, 64 * q, acc);
        float x = reduceWave(acc, sRed, q, j);
        sB[q][j] = fmaf(snorm, bv[j], x);
    }
    __syncthreads();

    float ir, iz, inn;
    {
        float pir[4] = {}, piz[4] = {}, pin[4] = {};
        const float* pw = g_WihT + (size_t)(64 * q) * 768 + j;
        #pragma unroll 4
        for (int kk = 0; kk < 64; kk += 2) {
            float wr0 = pw[0],   wz0 = pw[256],       wn0 = pw[512];
            float wr1 = pw[768], wz1 = pw[768 + 256], wn1 = pw[768 + 512];
            pw += 1536;
            #pragma unroll
            for (int r = 0; r < 4; r++) {
                float2 x = *(const float2*)(&sB[r][64 * q + kk]);
                pir[r] = fmaf(x.x, wr0, fmaf(x.y, wr1, pir[r]));
                piz[r] = fmaf(x.x, wz0, fmaf(x.y, wz1, piz[r]));
                pin[r] = fmaf(x.x, wn0, fmaf(x.y, wn1, pin[r]));
            }
        }
        ir  = reduceWave(pir, sRed, q, j);
        iz  = reduceWave(piz, sRed, q, j);
        inn = reduceWave(pin, sRed, q, j);
    }
    float hr, hz, hn;
    {
        float phr[4] = {}, phz[4] = {}, phn[4] = {};
        const float* pw = g_WhhT + (size_t)(64 * q) * 768 + j;
        #pragma unroll 4
        for (int kk = 0; kk < 64; kk += 2) {
            float vr0 = pw[0],   vz0 = pw[256],       vn0 = pw[512];
            float vr1 = pw[768], vz1 = pw[768 + 256], vn1 = pw[768 + 512];
            pw += 1536;
            #pragma unroll
            for (int r = 0; r < 4; r++) {
                float2 x = *(const float2*)(&sSL[r][64 * q + kk]);
                phr[r] = fmaf(x.x, vr0, fmaf(x.y, vr1, phr[r]));
                phz[r] = fmaf(x.x, vz0, fmaf(x.y, vz1, phz[r]));
                phn[r] = fmaf(x.x, vn0, fmaf(x.y, vn1, phn[r]));
            }
        }
        hr = reduceWave(phr, sRed, q, j);
        hz = reduceWave(phz, sRed, q, j);
        hn = reduceWave(phn, sRed, q, j);
    }

    float h_reg;
    {
        float rr = 1.0f / (1.0f + __expf(-(ir + b_ih[j] + hr + b_hh[j])));
        float zz = 1.0f / (1.0f + __expf(-(iz + b_ih[256 + j] + hz + b_hh[256 + j])));
        float nn = tanhf(inn + b_ih[512 + j] + rr * (hn + b_hh[512 + j]));
        float h = (1.0f - zz) * nn + zz * sSL[q][j];
        h_reg = h;
        float a = h, bb = h * h;
        grpReduce2(a, bb);
        float m = a * (1.0f / 256.0f);
        float var = bb * (1.0f / 256.0f) - m * m;
        float rs = rsqrtf(var + EPSLN);
        __syncthreads();
        sA[q][j] = (h - m) * rs * lnf_g[j] + lnf_b[j];
    }
    __syncthreads();

    {
        float f0[4] = {}, f1v[4] = {};
        const float* p1 = g_W1T + (size_t)(64 * q) * 512 + j;
        #pragma unroll 4
        for (int kk = 0; kk < 64; kk += 2) {
            float wa0 = p1[0],   wb0 = p1[256];
            float wa1 = p1[512], wb1 = p1[512 + 256];
            p1 += 1024;
            #pragma unroll
            for (int r = 0; r < 4; r++) {
                float2 x = *(const float2*)(&sA[r][64 * q + kk]);
                f0[r]  = fmaf(x.x, wa0, fmaf(x.y, wa1, f0[r]));
                f1v[r] = fmaf(x.x, wb0, fmaf(x.y, wb1, f1v[r]));
            }
        }
        float h0 = reduceWave(f0, sRed, q, j);
        float h1 = reduceWave(f1v, sRed, q, j);
        sF1[q][j]       = fmaxf(h0 + b1[j], 0.f);
        sF1[q][256 + j] = fmaxf(h1 + b1[256 + j], 0.f);
    }
    __syncthreads();

    float ns;
    {
        float o[4] = {0.f, 0.f, 0.f, 0.f};
        gemvPart(g_W2T, 256, 128, &sF1[0][0], 512, j, 128 * q, o);
        float oo = reduceWave(o, sRed, q, j);
        ns = h_reg + oo + b2[j];
        g_slots[(size_t)row * 256 + j] = ns;
        if (last) out_slots[(size_t)row * 256 + j] = ns;
    }

    if (!last) {
        float a = ns, bb = ns * ns;
        grpReduce2(a, bb);
        float m = a * (1.0f / 256.0f);
        float var = bb * (1.0f / 256.0f) - m * m;
        float rs = rsqrtf(var + EPSLN);
        __syncthreads();
        sB[q][j] = (ns - m) * rs * ls_g[j] + ls_b[j];
        __syncthreads();
        slotABody((const float (*)[256])sB, sRed, r0, q, j, gg, gb);
    }
}

// ---------------- launch ----------------
extern "C" void kernel_launch(void* const* d_in, const int* in_sizes, int n_in,
                              void* d_out, int out_size) {
    (void)in_sizes; (void)n_in; (void)out_size;
    const float* inputs  = (const float*)d_in[0];
    const float* noise   = (const float*)d_in[1];
    const float* slot_mu = (const float*)d_in[2];
    const float* slot_ls = (const float*)d_in[3];
    const float* Wq      = (const float*)d_in[4];
    const float* bq      = (const float*)d_in[5];
    const float* Wk      = (const float*)d_in[6];
    const float* bk      = (const float*)d_in[7];
    const float* Wv      = (const float*)d_in[8];
    const float* bv      = (const float*)d_in[9];
    const float* W_ih    = (const float*)d_in[10];
    const float* b_ih    = (const float*)d_in[11];
    const float* W_hh    = (const float*)d_in[12];
    const float* b_hh    = (const float*)d_in[13];
    const float* ln_in_g = (const float*)d_in[14];
    const float* ln_in_b = (const float*)d_in[15];
    const float* ln_s_g  = (const float*)d_in[16];
    const float* ln_s_b  = (const float*)d_in[17];
    const float* ln_ff_g = (const float*)d_in[18];
    const float* ln_ff_b = (const float*)d_in[19];
    const float* W1      = (const float*)d_in[20];
    const float* b1      = (const float*)d_in[21];
    const float* W2      = (const float*)d_in[22];
    const float* b2      = (const float*)d_in[23];

    float* out = (float*)d_out;
    float* out_slots = out;
    float* out_attn  = out + BK_ * D_;

    kSetup<<<1475, 256>>>(W_ih, W_hh, Wv, W1, W2, noise, slot_mu, slot_ls, Wq, Wk, bq, bk);
    kSlotA<<<128, 1024>>>(ln_s_g, ln_s_b, ln_in_g, ln_in_b);

    for (int it = 0; it < 3; it++) {
        int last = (it == 2);
        kFA<<<dim3(16, 64), 128>>>(inputs, last, out_attn);
        kSlotB<<<128, 1024>>>(ln_in_g, ln_in_b, bv, b_ih, b_hh,
                              ln_ff_g, ln_ff_b, b1, b2, ln_s_g, ln_s_b,
                              last, out_slots);
    }
}

// round 12
// speedup vs baseline: 1.9691x; 1.0768x over previous
#include <cuda_runtime.h>
#include <math.h>
#include <stdint.h>
#include <stddef.h>

// ---------------- problem dims ----------------
#define B_    64
#define N_    4096
#define DIN_  256
#define K_    8
#define D_    256
#define H_    512
#define BK_   512
#define SCALE_ 0.0625f
#define EPSLN 1e-5f
#define EPSA  1e-8f

typedef unsigned long long u64;

// ---------------- device scratch ----------------
__device__ __align__(16) float g_slots[BK_ * D_];
__device__ __align__(16) float g_gq[BK_ * D_];
__device__ float g_C1[BK_];
__device__ float g_C2[BK_];
__device__ __align__(16) float g_P[BK_ * D_];
__device__ float g_SA[BK_];
__device__ float g_SW[BK_];
__device__ float g_bqk[D_];
__device__ float g_wb[D_];
__device__ float g_c0;
// packed weights: Wp[(kb * Nout + o)*4 + t] = W[o][4*kb + t]  (float4 per (kb,o))
__device__ __align__(16) float g_WqkP[D_ * D_];
__device__ __align__(16) float g_WihP[3 * D_ * D_];
__device__ __align__(16) float g_WhhP[3 * D_ * D_];
__device__ __align__(16) float g_WvP[D_ * D_];
__device__ __align__(16) float g_W1P[H_ * D_];
__device__ __align__(16) float g_W2P[D_ * H_];

// ---------------- f32x2 packed helpers ----------------
__device__ __forceinline__ u64 pk2(float x, float y) {
    u64 r; asm("mov.b64 %0, {%1, %2};" : "=l"(r) : "f"(x), "f"(y)); return r;
}
__device__ __forceinline__ void upk2(u64 v, float& x, float& y) {
    asm("mov.b64 {%0, %1}, %2;" : "=f"(x), "=f"(y) : "l"(v));
}
__device__ __forceinline__ void fma2(u64& d, u64 a, u64 b) {
    asm("fma.rn.f32x2 %0, %1, %2, %0;" : "+l"(d) : "l"(a), "l"(b));
}
__device__ __forceinline__ u64 add2(u64 a, u64 b) {
    u64 r; asm("add.rn.f32x2 %0, %1, %2;" : "=l"(r) : "l"(a), "l"(b)); return r;
}
__device__ __forceinline__ u64 mul2(u64 a, u64 b) {
    u64 r; asm("mul.rn.f32x2 %0, %1, %2;" : "=l"(r) : "l"(a), "l"(b)); return r;
}

// ---------------- block reduce ----------------
__device__ __forceinline__ void blockReduce2(float& a, float& b) {
    #pragma unroll
    for (int o = 16; o; o >>= 1) {
        a += __shfl_xor_sync(0xffffffffu, a, o);
        b += __shfl_xor_sync(0xffffffffu, b, o);
    }
    __shared__ float sa[8], sb[8];
    __syncthreads();
    int w = threadIdx.x >> 5;
    if ((threadIdx.x & 31) == 0) { sa[w] = a; sb[w] = b; }
    __syncthreads();
    a = sa[threadIdx.x & 7];
    b = sb[threadIdx.x & 7];
    #pragma unroll
    for (int o = 4; o; o >>= 1) {
        a += __shfl_xor_sync(0xffffffffu, a, o);
        b += __shfl_xor_sync(0xffffffffu, b, o);
    }
}

// ---------------- group reduce: 1024 threads, 4 groups of 256 ----------------
__device__ __forceinline__ void grpReduce2(float& a, float& b) {
    #pragma unroll
    for (int o = 16; o; o >>= 1) {
        a += __shfl_xor_sync(0xffffffffu, a, o);
        b += __shfl_xor_sync(0xffffffffu, b, o);
    }
    __shared__ float sa[32], sb[32];
    int w = threadIdx.x >> 5;
    __syncthreads();
    if ((threadIdx.x & 31) == 0) { sa[w] = a; sb[w] = b; }
    __syncthreads();
    int g8 = (threadIdx.x >> 8) << 3;
    float ra = 0.f, rb = 0.f;
    #pragma unroll
    for (int i = 0; i < 8; i++) { ra += sa[g8 + i]; rb += sb[g8 + i]; }
    a = ra; b = rb;
}

// ---------------- packed GEMV: acc[r] += sum_{kb in [kb0,kb0+nblk)} x4 . Wp[kb][j] ----------------
__device__ __forceinline__ void gemvPQ(const float* __restrict__ Wp, int Nout, int nblk, int kb0,
                                       const float* s_in, int in_stride, int j, float acc[4]) {
    const float4* p = (const float4*)Wp + (size_t)kb0 * Nout + j;
    #pragma unroll 4
    for (int b = 0; b < nblk; b++) {
        float4 w = p[(size_t)b * Nout];
        #pragma unroll
        for (int r = 0; r < 4; r++) {
            float4 x = *(const float4*)(s_in + r * in_stride + (kb0 + b) * 4);
            acc[r] = fmaf(x.x, w.x, fmaf(x.y, w.y, fmaf(x.z, w.z, fmaf(x.w, w.w, acc[r]))));
        }
    }
}

// ---------------- reduction wave ----------------
__device__ __forceinline__ float reduceWave(const float part[4], float* sRed, int q, int j) {
    __syncthreads();
    #pragma unroll
    for (int r = 0; r < 4; r++) sRed[((q << 2) + r) * 256 + j] = part[r];
    __syncthreads();
    return (sRed[(0 + q) * 256 + j] + sRed[(4 + q) * 256 + j]) +
           (sRed[(8 + q) * 256 + j] + sRed[(12 + q) * 256 + j]);
}

// ---------------- slot-A body (1024 threads) ----------------
__device__ __forceinline__ void slotABody(const float (*s_sn)[256], float* sRed,
                                          int r0, int q, int j,
                                          const float* __restrict__ gg, const float* __restrict__ gb) {
    float acc[4] = {0.f, 0.f, 0.f, 0.f};
    gemvPQ(g_WqkP, 256, 16, 16 * q, &s_sn[0][0], 256, j, acc);
    float qt = reduceWave(acc, sRed, q, j) + g_bqk[j];
    int row = r0 + q;
    float gq = gg[j] * qt;
    g_gq[(size_t)row * 256 + j] = gq;
    float c1 = gq;
    float c2 = fmaf(qt, gb[j], s_sn[q][j] * g_wb[j]);
    grpReduce2(c1, c2);
    if (j == 0) { g_C1[row] = c1; g_C2[row] = c2 + g_c0; }
    g_P[(size_t)row * 256 + j] = 0.f;
    if (j == 0) { g_SA[row] = 0.f; g_SW[row] = 0.f; }
}

// =================== SETUP: pack weights + slot init + Wqk/bqk/wb/c0 ===================
// pack: dst[(kb*Nout + o)*4+t] = src[o][4kb+t]. One block = 256 float4s.
__device__ __forceinline__ void packTile(const float* __restrict__ src, float* __restrict__ dst,
                                         int Nout, int Kb, int blk) {
    int e = blk * 256 + threadIdx.x;
    int o = e / Kb, kb = e - o * Kb;
    float4 v = *(const float4*)(src + (size_t)o * Kb * 4 + (size_t)kb * 4);
    *(float4*)(dst + ((size_t)kb * Nout + o) * 4) = v;
}

__global__ void __launch_bounds__(256) kSetup(const float* __restrict__ W_ih, const float* __restrict__ W_hh,
                                              const float* __restrict__ Wv, const float* __restrict__ W1,
                                              const float* __restrict__ W2, const float* __restrict__ noise,
                                              const float* __restrict__ mu, const float* __restrict__ ls,
                                              const float* __restrict__ Wq, const float* __restrict__ Wk,
                                              const float* __restrict__ bq, const float* __restrict__ bk) {
    int t = blockIdx.x;
    int i = threadIdx.x;
    if (t < 192)       packTile(W_ih, g_WihP, 768, 64, t);
    else if (t < 384)  packTile(W_hh, g_WhhP, 768, 64, t - 192);
    else if (t < 448)  packTile(Wv,   g_WvP,  256, 64, t - 384);
    else if (t < 576)  packTile(W1,   g_W1P,  512, 64, t - 448);
    else if (t < 704)  packTile(W2,   g_W2P,  256, 128, t - 576);
    else if (t < 1216) {
        int idx = (t - 704) * 256 + i;
        int d = idx & 255;
        g_slots[idx] = mu[d] + __expf(ls[d]) * noise[idx];
    } else if (t < 1472) {
        int jj = t - 1216;     // k index of Wqk row
        float acc[8] = {0.f,0.f,0.f,0.f,0.f,0.f,0.f,0.f};
        #pragma unroll 4
        for (int d = 0; d < 256; d += 8) {
            #pragma unroll
            for (int u = 0; u < 8; u++)
                acc[u] = fmaf(Wq[(d + u) * 256 + jj], Wk[(d + u) * 256 + i], acc[u]);
        }
        float v = (((acc[0] + acc[1]) + (acc[2] + acc[3])) + ((acc[4] + acc[5]) + (acc[6] + acc[7]))) * SCALE_;
        // packed store: Wqk[k=jj][col=i] -> g_WqkP[((jj>>2)*256 + i)*4 + (jj&3)]
        g_WqkP[(((size_t)(jj >> 2)) * 256 + i) * 4 + (jj & 3)] = v;
    } else if (t == 1472) {
        float a = 0.f;
        #pragma unroll 8
        for (int d = 0; d < 256; d++) a = fmaf(bq[d], Wk[d * 256 + i], a);
        g_bqk[i] = a * SCALE_;
    } else if (t == 1473) {
        float a = 0.f;
        #pragma unroll 8
        for (int d = 0; d < 256; d++) a = fmaf(Wq[d * 256 + i], bk[d], a);
        g_wb[i] = a * SCALE_;
    } else {
        float a = bq[i] * bk[i], dm = 0.f;
        blockReduce2(a, dm);
        if (i == 0) g_c0 = a * SCALE_;
    }
}

// =================== kSlotA (iteration 0 only) ===================
__global__ void __launch_bounds__(1024) kSlotA(const float* __restrict__ ls_g, const float* __restrict__ ls_b,
                                               const float* __restrict__ gg, const float* __restrict__ gb) {
    __shared__ float sSN[4][256];
    __shared__ float sRed[4096];
    int j = threadIdx.x & 255, q = threadIdx.x >> 8;
    int r0 = blockIdx.x * 4;
    float v = g_slots[(size_t)(r0 + q) * 256 + j];
    float a = v, b = v * v;
    grpReduce2(a, b);
    float m = a * (1.0f / 256.0f);
    float var = b * (1.0f / 256.0f) - m * m;
    float rs = rsqrtf(var + EPSLN);
    sSN[q][j] = (v - m) * rs * ls_g[j] + ls_b[j];
    __syncthreads();
    slotABody(sSN, sRed, r0, q, j, gg, gb);
}

// ============ kFA: LN + dots + softmax + P/SA/SW accumulation ============
// grid (8, 64): single wave at 4 blocks/SM. block 128 (4 warps), each warp 128 rows.
__global__ void __launch_bounds__(128, 4) kFA(const float* __restrict__ inputs,
                                              int last, float* __restrict__ out_attn) {
    int b = blockIdx.y;
    int warp = threadIdx.x >> 5, lane = threadIdx.x & 31;
    int row0 = blockIdx.x * 512 + warp * 128;
    int r8 = b * 8;
    int slane = ((lane & 1) << 2) | (lane & 2) | ((lane >> 2) & 1);

    __shared__ __align__(16) float sGQ[8][256];
    {
        const float4* src = (const float4*)(g_gq + (size_t)r8 * 256);
        #pragma unroll
        for (int e = threadIdx.x; e < 512; e += 128)
            ((float4*)sGQ)[e] = src[e];
    }
    float C1s = g_C1[r8 + slane], C2s = g_C2[r8 + slane];
    __syncthreads();

    u64 zero2 = pk2(0.f, 0.f);
    u64 P[8][4];
    #pragma unroll
    for (int k = 0; k < 8; k++) { P[k][0] = zero2; P[k][1] = zero2; P[k][2] = zero2; P[k][3] = zero2; }
    float SAl = 0.f, SWl = 0.f;

    const ulonglong2* vp = (const ulonglong2*)(inputs + ((size_t)b * N_ + row0) * 256);
    ulonglong2 A0 = vp[lane], A1 = vp[lane + 32];

    #pragma unroll 1
    for (int r = 0; r < 128; r++) {
        int n = row0 + r;
        ulonglong2 B0, B1;
        if (r < 127) {
            const ulonglong2* vn = vp + (size_t)(r + 1) * 64;
            B0 = vn[lane]; B1 = vn[lane + 32];
        }
        float s, ss;
        {
            u64 s2  = add2(add2(A0.x, A0.y), add2(A1.x, A1.y));
            u64 ss2 = mul2(A0.x, A0.x);
            fma2(ss2, A0.y, A0.y); fma2(ss2, A1.x, A1.x); fma2(ss2, A1.y, A1.y);
            float lo, hi;
            upk2(s2, lo, hi);  s  = lo + hi;
            upk2(ss2, lo, hi); ss = lo + hi;
        }
        {
            bool odd = lane & 1;
            float send = odd ? s : ss;
            float rcv = __shfl_xor_sync(0xffffffffu, send, 1);
            float v = odd ? (ss + rcv) : (s + rcv);
            v += __shfl_xor_sync(0xffffffffu, v, 2);
            v += __shfl_xor_sync(0xffffffffu, v, 4);
            v += __shfl_xor_sync(0xffffffffu, v, 8);
            v += __shfl_xor_sync(0xffffffffu, v, 16);
            float o = __shfl_xor_sync(0xffffffffu, v, 1);
            s  = odd ? o : v;
            ss = odd ? v : o;
        }
        float m   = s * (1.0f / 256.0f);
        float var = fmaf(ss, 1.0f / 256.0f, -m * m);
        float rs  = rsqrtf(var + EPSLN);
        float w   = m * rs;

        float dt[8];
        #pragma unroll
        for (int k = 0; k < 8; k++) {
            ulonglong2 qa = *(const ulonglong2*)(&sGQ[k][4 * lane]);
            ulonglong2 qb = *(const ulonglong2*)(&sGQ[k][128 + 4 * lane]);
            u64 d2 = mul2(A0.x, qa.x);
            fma2(d2, A0.y, qa.y);
            fma2(d2, A1.x, qb.x);
            fma2(d2, A1.y, qb.y);
            float lo, hi; upk2(d2, lo, hi);
            dt[k] = lo + hi;
        }
        float vdot;
        {
            bool c0 = lane & 1;
            float t0 = c0 ? dt[0] : dt[4];
            float t1 = c0 ? dt[1] : dt[5];
            float t2 = c0 ? dt[2] : dt[6];
            float t3 = c0 ? dt[3] : dt[7];
            t0 = __shfl_xor_sync(0xffffffffu, t0, 1);
            t1 = __shfl_xor_sync(0xffffffffu, t1, 1);
            t2 = __shfl_xor_sync(0xffffffffu, t2, 1);
            t3 = __shfl_xor_sync(0xffffffffu, t3, 1);
            float u0 = (c0 ? dt[4] : dt[0]) + t0;
            float u1 = (c0 ? dt[5] : dt[1]) + t1;
            float u2 = (c0 ? dt[6] : dt[2]) + t2;
            float u3 = (c0 ? dt[7] : dt[3]) + t3;
            bool c1 = lane & 2;
            float s0 = c1 ? u0 : u2;
            float s1 = c1 ? u1 : u3;
            s0 = __shfl_xor_sync(0xffffffffu, s0, 2);
            s1 = __shfl_xor_sync(0xffffffffu, s1, 2);
            float w0 = (c1 ? u2 : u0) + s0;
            float w1 = (c1 ? u3 : u1) + s1;
            bool c2 = lane & 4;
            float s2 = c2 ? w0 : w1;
            s2 = __shfl_xor_sync(0xffffffffu, s2, 4);
            vdot = (c2 ? w1 : w0) + s2;
            vdot += __shfl_xor_sync(0xffffffffu, vdot, 8);
            vdot += __shfl_xor_sync(0xffffffffu, vdot, 16);
        }
        float lg = fmaf(rs, vdot, fmaf(-w, C1s, C2s));
        float mx = lg;
        mx = fmaxf(mx, __shfl_xor_sync(0xffffffffu, mx, 1));
        mx = fmaxf(mx, __shfl_xor_sync(0xffffffffu, mx, 2));
        mx = fmaxf(mx, __shfl_xor_sync(0xffffffffu, mx, 4));
        float e = __expf(lg - mx);
        float sm = e;
        sm += __shfl_xor_sync(0xffffffffu, sm, 1);
        sm += __shfl_xor_sync(0xffffffffu, sm, 2);
        sm += __shfl_xor_sync(0xffffffffu, sm, 4);
        float a = __fdividef(e, sm);
        SAl += a;
        SWl = fmaf(a, w, SWl);
        if (last && lane < 8)
            out_attn[(size_t)(r8 + slane) * N_ + n] = a;

        int gbase = lane & 24;
        float ak[8];
        ak[0] = __shfl_sync(0xffffffffu, a, gbase | 0);
        ak[1] = __shfl_sync(0xffffffffu, a, gbase | 4);
        ak[2] = __shfl_sync(0xffffffffu, a, gbase | 2);
        ak[3] = __shfl_sync(0xffffffffu, a, gbase | 6);
        ak[4] = __shfl_sync(0xffffffffu, a, gbase | 1);
        ak[5] = __shfl_sync(0xffffffffu, a, gbase | 5);
        ak[6] = __shfl_sync(0xffffffffu, a, gbase | 3);
        ak[7] = __shfl_sync(0xffffffffu, a, gbase | 7);

        #pragma unroll
        for (int k = 0; k < 8; k++) {
            float ar = ak[k] * rs;
            u64 ap = pk2(ar, ar);
            fma2(P[k][0], ap, A0.x); fma2(P[k][1], ap, A0.y);
            fma2(P[k][2], ap, A1.x); fma2(P[k][3], ap, A1.y);
        }
        A0 = B0; A1 = B1;
    }

    __shared__ float sP[4][8][256];
    __shared__ float sSA[4][8], sSW[4][8];
    #pragma unroll
    for (int k = 0; k < 8; k++) {
        float x, y;
        upk2(P[k][0], x, y); sP[warp][k][4 * lane] = x;       sP[warp][k][4 * lane + 1] = y;
        upk2(P[k][1], x, y); sP[warp][k][4 * lane + 2] = x;   sP[warp][k][4 * lane + 3] = y;
        upk2(P[k][2], x, y); sP[warp][k][128 + 4 * lane] = x; sP[warp][k][128 + 4 * lane + 1] = y;
        upk2(P[k][3], x, y); sP[warp][k][128 + 4 * lane + 2] = x; sP[warp][k][128 + 4 * lane + 3] = y;
    }
    if (lane < 8) { sSA[warp][slane] = SAl; sSW[warp][slane] = SWl; }
    __syncthreads();
    for (int t = threadIdx.x; t < 2048; t += 128) {
        int k = t >> 8, d = t & 255;
        float v = (sP[0][k][d] + sP[1][k][d]) + (sP[2][k][d] + sP[3][k][d]);
        atomicAdd(&g_P[(size_t)(r8 + k) * 256 + d], v);
    }
    if (threadIdx.x < 8) {
        int k = threadIdx.x;
        atomicAdd(&g_SA[r8 + k], (sSA[0][k] + sSA[1][k]) + (sSA[2][k] + sSA[3][k]));
    } else if (threadIdx.x < 16) {
        int k = threadIdx.x - 8;
        atomicAdd(&g_SW[r8 + k], (sSW[0][k] + sSW[1][k]) + (sSW[2][k] + sSW[3][k]));
    }
}

// =================== kSlotB: packed-weight GEMV stages ===================
__global__ void __launch_bounds__(1024) kSlotB(const float* __restrict__ gg, const float* __restrict__ gb,
                                               const float* __restrict__ bv,
                                               const float* __restrict__ b_ih, const float* __restrict__ b_hh,
                                               const float* __restrict__ lnf_g, const float* __restrict__ lnf_b,
                                               const float* __restrict__ b1, const float* __restrict__ b2,
                                               const float* __restrict__ ls_g, const float* __restrict__ ls_b,
                                               int last, float* __restrict__ out_slots) {
    __shared__ float sA[4][256];
    __shared__ float sB[4][256];
    __shared__ float sSL[4][256];
    __shared__ float sF1[4][512];
    __shared__ float sRed[4096];
    int j = threadIdx.x & 255, q = threadIdx.x >> 8;
    int r0 = blockIdx.x * 4;
    int row = r0 + q;

    float snorm;
    {
        float SA = g_SA[row], SW = g_SW[row];
        float inv = 1.0f / (SA + EPSA);
        float Pv = g_P[(size_t)row * 256 + j];
        sA[q][j] = (gg[j] * (Pv - SW) + gb[j] * SA) * inv;
        sSL[q][j] = g_slots[(size_t)row * 256 + j];
        snorm = SA * inv;
    }
    __syncthreads();

    // stage 2: x = un @ WvT + snorm*bv
    {
        float acc[4] = {0.f, 0.f, 0.f, 0.f};
        gemvPQ(g_WvP, 256, 16, 16 * q, &sA[0][0], 256, j, acc);
        float x = reduceWave(acc, sRed, q, j);
        sB[q][j] = fmaf(snorm, bv[j], x);
    }
    __syncthreads();

    // stage 3a: input gates (packed, 3 gates per k-block)
    float ir, iz, inn;
    {
        float pir[4] = {}, piz[4] = {}, pin[4] = {};
        const float4* pw = (const float4*)g_WihP + (size_t)(16 * q) * 768 + j;
        #pragma unroll 2
        for (int bq_ = 0; bq_ < 16; bq_++) {
            float4 wr = pw[(size_t)bq_ * 768];
            float4 wz = pw[(size_t)bq_ * 768 + 256];
            float4 wn = pw[(size_t)bq_ * 768 + 512];
            #pragma unroll
            for (int r = 0; r < 4; r++) {
                float4 x = *(const float4*)(&sB[r][64 * q + 4 * bq_]);
                pir[r] = fmaf(x.x, wr.x, fmaf(x.y, wr.y, fmaf(x.z, wr.z, fmaf(x.w, wr.w, pir[r]))));
                piz[r] = fmaf(x.x, wz.x, fmaf(x.y, wz.y, fmaf(x.z, wz.z, fmaf(x.w, wz.w, piz[r]))));
                pin[r] = fmaf(x.x, wn.x, fmaf(x.y, wn.y, fmaf(x.z, wn.z, fmaf(x.w, wn.w, pin[r]))));
            }
        }
        ir  = reduceWave(pir, sRed, q, j);
        iz  = reduceWave(piz, sRed, q, j);
        inn = reduceWave(pin, sRed, q, j);
    }
    // stage 3b: hidden gates
    float hr, hz, hn;
    {
        float phr[4] = {}, phz[4] = {}, phn[4] = {};
        const float4* pw = (const float4*)g_WhhP + (size_t)(16 * q) * 768 + j;
        #pragma unroll 2
        for (int bq_ = 0; bq_ < 16; bq_++) {
            float4 wr = pw[(size_t)bq_ * 768];
            float4 wz = pw[(size_t)bq_ * 768 + 256];
            float4 wn = pw[(size_t)bq_ * 768 + 512];
            #pragma unroll
            for (int r = 0; r < 4; r++) {
                float4 x = *(const float4*)(&sSL[r][64 * q + 4 * bq_]);
                phr[r] = fmaf(x.x, wr.x, fmaf(x.y, wr.y, fmaf(x.z, wr.z, fmaf(x.w, wr.w, phr[r]))));
                phz[r] = fmaf(x.x, wz.x, fmaf(x.y, wz.y, fmaf(x.z, wz.z, fmaf(x.w, wz.w, phz[r]))));
                phn[r] = fmaf(x.x, wn.x, fmaf(x.y, wn.y, fmaf(x.z, wn.z, fmaf(x.w, wn.w, phn[r]))));
            }
        }
        hr = reduceWave(phr, sRed, q, j);
        hz = reduceWave(phz, sRed, q, j);
        hn = reduceWave(phn, sRed, q, j);
    }

    // stage 4: GRU combine + ln_ff
    float h_reg;
    {
        float rr = 1.0f / (1.0f + __expf(-(ir + b_ih[j] + hr + b_hh[j])));
        float zz = 1.0f / (1.0f + __expf(-(iz + b_ih[256 + j] + hz + b_hh[256 + j])));
        float nn = tanhf(inn + b_ih[512 + j] + rr * (hn + b_hh[512 + j]));
        float h = (1.0f - zz) * nn + zz * sSL[q][j];
        h_reg = h;
        float a = h, bb = h * h;
        grpReduce2(a, bb);
        float m = a * (1.0f / 256.0f);
        float var = bb * (1.0f / 256.0f) - m * m;
        float rs = rsqrtf(var + EPSLN);
        __syncthreads();
        sA[q][j] = (h - m) * rs * lnf_g[j] + lnf_b[j];
    }
    __syncthreads();

    // stage 5: f1 = relu(ff @ W1T + b1)
    {
        float f0[4] = {}, f1v[4] = {};
        const float4* p1 = (const float4*)g_W1P + (size_t)(16 * q) * 512 + j;
        #pragma unroll 2
        for (int bq_ = 0; bq_ < 16; bq_++) {
            float4 wa = p1[(size_t)bq_ * 512];
            float4 wb4 = p1[(size_t)bq_ * 512 + 256];
            #pragma unroll
            for (int r = 0; r < 4; r++) {
                float4 x = *(const float4*)(&sA[r][64 * q + 4 * bq_]);
                f0[r]  = fmaf(x.x, wa.x,  fmaf(x.y, wa.y,  fmaf(x.z, wa.z,  fmaf(x.w, wa.w,  f0[r]))));
                f1v[r] = fmaf(x.x, wb4.x, fmaf(x.y, wb4.y, fmaf(x.z, wb4.z, fmaf(x.w, wb4.w, f1v[r]))));
            }
        }
        float h0 = reduceWave(f0, sRed, q, j);
        float h1 = reduceWave(f1v, sRed, q, j);
        sF1[q][j]       = fmaxf(h0 + b1[j], 0.f);
        sF1[q][256 + j] = fmaxf(h1 + b1[256 + j], 0.f);
    }
    __syncthreads();

    // stage 6: new slots = h + f1 @ W2T + b2
    float ns;
    {
        float o[4] = {0.f, 0.f, 0.f, 0.f};
        gemvPQ(g_W2P, 256, 32, 32 * q, &sF1[0][0], 512, j, o);
        float oo = reduceWave(o, sRed, q, j);
        ns = h_reg + oo + b2[j];
        g_slots[(size_t)row * 256 + j] = ns;
        if (last) out_slots[(size_t)row * 256 + j] = ns;
    }

    if (!last) {
        float a = ns, bb = ns * ns;
        grpReduce2(a, bb);
        float m = a * (1.0f / 256.0f);
        float var = bb * (1.0f / 256.0f) - m * m;
        float rs = rsqrtf(var + EPSLN);
        __syncthreads();
        sB[q][j] = (ns - m) * rs * ls_g[j] + ls_b[j];
        __syncthreads();
        slotABody((const float (*)[256])sB, sRed, r0, q, j, gg, gb);
    }
}

// ---------------- launch ----------------
extern "C" void kernel_launch(void* const* d_in, const int* in_sizes, int n_in,
                              void* d_out, int out_size) {
    (void)in_sizes; (void)n_in; (void)out_size;
    const float* inputs  = (const float*)d_in[0];
    const float* noise   = (const float*)d_in[1];
    const float* slot_mu = (const float*)d_in[2];
    const float* slot_ls = (const float*)d_in[3];
    const float* Wq      = (const float*)d_in[4];
    const float* bq      = (const float*)d_in[5];
    const float* Wk      = (const float*)d_in[6];
    const float* bk      = (const float*)d_in[7];
    const float* Wv      = (const float*)d_in[8];
    const float* bv      = (const float*)d_in[9];
    const float* W_ih    = (const float*)d_in[10];
    const float* b_ih    = (const float*)d_in[11];
    const float* W_hh    = (const float*)d_in[12];
    const float* b_hh    = (const float*)d_in[13];
    const float* ln_in_g = (const float*)d_in[14];
    const float* ln_in_b = (const float*)d_in[15];
    const float* ln_s_g  = (const float*)d_in[16];
    const float* ln_s_b  = (const float*)d_in[17];
    const float* ln_ff_g = (const float*)d_in[18];
    const float* ln_ff_b = (const float*)d_in[19];
    const float* W1      = (const float*)d_in[20];
    const float* b1      = (const float*)d_in[21];
    const float* W2      = (const float*)d_in[22];
    const float* b2      = (const float*)d_in[23];

    float* out = (float*)d_out;
    float* out_slots = out;
    float* out_attn  = out + BK_ * D_;

    kSetup<<<1475, 256>>>(W_ih, W_hh, Wv, W1, W2, noise, slot_mu, slot_ls, Wq, Wk, bq, bk);
    kSlotA<<<128, 1024>>>(ln_s_g, ln_s_b, ln_in_g, ln_in_b);

    for (int it = 0; it < 3; it++) {
        int last = (it == 2);
        kFA<<<dim3(8, 64), 128>>>(inputs, last, out_attn);
        kSlotB<<<128, 1024>>>(ln_in_g, ln_in_b, bv, b_ih, b_hh,
                              ln_ff_g, ln_ff_b, b1, b2, ln_s_g, ln_s_b,
                              last, out_slots);
    }
}

// round 13
// speedup vs baseline: 2.3760x; 1.2066x over previous
#include <cuda_runtime.h>
#include <math.h>
#include <stdint.h>
#include <stddef.h>

// ---------------- problem dims ----------------
#define B_    64
#define N_    4096
#define DIN_  256
#define K_    8
#define D_    256
#define H_    512
#define BK_   512
#define SCALE_ 0.0625f
#define EPSLN 1e-5f
#define EPSA  1e-8f

typedef unsigned long long u64;

// ---------------- device scratch ----------------
__device__ __align__(16) float g_slots[BK_ * D_];
__device__ __align__(16) float g_gq[BK_ * D_];
__device__ float g_C1[BK_];
__device__ float g_C2[BK_];
__device__ __align__(16) float g_P[BK_ * D_];
__device__ float g_SA[BK_];
__device__ float g_SW[BK_];
__device__ float g_bqk[D_];
__device__ float g_wb[D_];
__device__ float g_c0;
// packed weights: Wp[(kb * Nout + o)*4 + t] = W[o][4*kb + t]
__device__ __align__(16) float g_WqkP[D_ * D_];
__device__ __align__(16) float g_WihP[3 * D_ * D_];
__device__ __align__(16) float g_WhhP[3 * D_ * D_];
__device__ __align__(16) float g_WvP[D_ * D_];
__device__ __align__(16) float g_W1P[H_ * D_];
__device__ __align__(16) float g_W2P[D_ * H_];

// ---------------- f32x2 packed helpers ----------------
__device__ __forceinline__ u64 pk2(float x, float y) {
    u64 r; asm("mov.b64 %0, {%1, %2};" : "=l"(r) : "f"(x), "f"(y)); return r;
}
__device__ __forceinline__ void upk2(u64 v, float& x, float& y) {
    asm("mov.b64 {%0, %1}, %2;" : "=f"(x), "=f"(y) : "l"(v));
}
__device__ __forceinline__ void fma2(u64& d, u64 a, u64 b) {
    asm("fma.rn.f32x2 %0, %1, %2, %0;" : "+l"(d) : "l"(a), "l"(b));
}
__device__ __forceinline__ u64 add2(u64 a, u64 b) {
    u64 r; asm("add.rn.f32x2 %0, %1, %2;" : "=l"(r) : "l"(a), "l"(b)); return r;
}
__device__ __forceinline__ u64 mul2(u64 a, u64 b) {
    u64 r; asm("mul.rn.f32x2 %0, %1, %2;" : "=l"(r) : "l"(a), "l"(b)); return r;
}

// ---------------- block reduce ----------------
__device__ __forceinline__ void blockReduce2(float& a, float& b) {
    #pragma unroll
    for (int o = 16; o; o >>= 1) {
        a += __shfl_xor_sync(0xffffffffu, a, o);
        b += __shfl_xor_sync(0xffffffffu, b, o);
    }
    __shared__ float sa[8], sb[8];
    __syncthreads();
    int w = threadIdx.x >> 5;
    if ((threadIdx.x & 31) == 0) { sa[w] = a; sb[w] = b; }
    __syncthreads();
    a = sa[threadIdx.x & 7];
    b = sb[threadIdx.x & 7];
    #pragma unroll
    for (int o = 4; o; o >>= 1) {
        a += __shfl_xor_sync(0xffffffffu, a, o);
        b += __shfl_xor_sync(0xffffffffu, b, o);
    }
}

// ---------------- group reduce: 1024 threads, 4 groups of 256 ----------------
__device__ __forceinline__ void grpReduce2(float& a, float& b) {
    #pragma unroll
    for (int o = 16; o; o >>= 1) {
        a += __shfl_xor_sync(0xffffffffu, a, o);
        b += __shfl_xor_sync(0xffffffffu, b, o);
    }
    __shared__ float sa[32], sb[32];
    int w = threadIdx.x >> 5;
    __syncthreads();
    if ((threadIdx.x & 31) == 0) { sa[w] = a; sb[w] = b; }
    __syncthreads();
    int g8 = (threadIdx.x >> 8) << 3;
    float ra = 0.f, rb = 0.f;
    #pragma unroll
    for (int i = 0; i < 8; i++) { ra += sa[g8 + i]; rb += sb[g8 + i]; }
    a = ra; b = rb;
}

// ---------------- packed GEMV ----------------
__device__ __forceinline__ void gemvPQ(const float* __restrict__ Wp, int Nout, int nblk, int kb0,
                                       const float* s_in, int in_stride, int j, float acc[4]) {
    const float4* p = (const float4*)Wp + (size_t)kb0 * Nout + j;
    #pragma unroll 4
    for (int b = 0; b < nblk; b++) {
        float4 w = p[(size_t)b * Nout];
        #pragma unroll
        for (int r = 0; r < 4; r++) {
            float4 x = *(const float4*)(s_in + r * in_stride + (kb0 + b) * 4);
            acc[r] = fmaf(x.x, w.x, fmaf(x.y, w.y, fmaf(x.z, w.z, fmaf(x.w, w.w, acc[r]))));
        }
    }
}

// ---------------- reduction wave ----------------
__device__ __forceinline__ float reduceWave(const float part[4], float* sRed, int q, int j) {
    __syncthreads();
    #pragma unroll
    for (int r = 0; r < 4; r++) sRed[((q << 2) + r) * 256 + j] = part[r];
    __syncthreads();
    return (sRed[(0 + q) * 256 + j] + sRed[(4 + q) * 256 + j]) +
           (sRed[(8 + q) * 256 + j] + sRed[(12 + q) * 256 + j]);
}

// ---------------- slot-A body ----------------
__device__ __forceinline__ void slotABody(const float (*s_sn)[256], float* sRed,
                                          int r0, int q, int j,
                                          const float* __restrict__ gg, const float* __restrict__ gb) {
    float acc[4] = {0.f, 0.f, 0.f, 0.f};
    gemvPQ(g_WqkP, 256, 16, 16 * q, &s_sn[0][0], 256, j, acc);
    float qt = reduceWave(acc, sRed, q, j) + g_bqk[j];
    int row = r0 + q;
    float gq = gg[j] * qt;
    g_gq[(size_t)row * 256 + j] = gq;
    float c1 = gq;
    float c2 = fmaf(qt, gb[j], s_sn[q][j] * g_wb[j]);
    grpReduce2(c1, c2);
    if (j == 0) { g_C1[row] = c1; g_C2[row] = c2 + g_c0; }
    g_P[(size_t)row * 256 + j] = 0.f;
    if (j == 0) { g_SA[row] = 0.f; g_SW[row] = 0.f; }
}

// =================== SETUP ===================
__device__ __forceinline__ void packTile(const float* __restrict__ src, float* __restrict__ dst,
                                         int Nout, int Kb, int blk) {
    int e = blk * 256 + threadIdx.x;
    int o = e / Kb, kb = e - o * Kb;
    float4 v = *(const float4*)(src + (size_t)o * Kb * 4 + (size_t)kb * 4);
    *(float4*)(dst + ((size_t)kb * Nout + o) * 4) = v;
}

__global__ void __launch_bounds__(256) kSetup(const float* __restrict__ W_ih, const float* __restrict__ W_hh,
                                              const float* __restrict__ Wv, const float* __restrict__ W1,
                                              const float* __restrict__ W2, const float* __restrict__ noise,
                                              const float* __restrict__ mu, const float* __restrict__ ls,
                                              const float* __restrict__ Wq, const float* __restrict__ Wk,
                                              const float* __restrict__ bq, const float* __restrict__ bk) {
    int t = blockIdx.x;
    int i = threadIdx.x;
    if (t < 192)       packTile(W_ih, g_WihP, 768, 64, t);
    else if (t < 384)  packTile(W_hh, g_WhhP, 768, 64, t - 192);
    else if (t < 448)  packTile(Wv,   g_WvP,  256, 64, t - 384);
    else if (t < 576)  packTile(W1,   g_W1P,  512, 64, t - 448);
    else if (t < 704)  packTile(W2,   g_W2P,  256, 128, t - 576);
    else if (t < 1216) {
        int idx = (t - 704) * 256 + i;
        int d = idx & 255;
        g_slots[idx] = mu[d] + __expf(ls[d]) * noise[idx];
    } else if (t < 1472) {
        int jj = t - 1216;
        float acc[8] = {0.f,0.f,0.f,0.f,0.f,0.f,0.f,0.f};
        #pragma unroll 4
        for (int d = 0; d < 256; d += 8) {
            #pragma unroll
            for (int u = 0; u < 8; u++)
                acc[u] = fmaf(Wq[(d + u) * 256 + jj], Wk[(d + u) * 256 + i], acc[u]);
        }
        float v = (((acc[0] + acc[1]) + (acc[2] + acc[3])) + ((acc[4] + acc[5]) + (acc[6] + acc[7]))) * SCALE_;
        g_WqkP[(((size_t)(jj >> 2)) * 256 + i) * 4 + (jj & 3)] = v;
    } else if (t == 1472) {
        float a = 0.f;
        #pragma unroll 8
        for (int d = 0; d < 256; d++) a = fmaf(bq[d], Wk[d * 256 + i], a);
        g_bqk[i] = a * SCALE_;
    } else if (t == 1473) {
        float a = 0.f;
        #pragma unroll 8
        for (int d = 0; d < 256; d++) a = fmaf(Wq[d * 256 + i], bk[d], a);
        g_wb[i] = a * SCALE_;
    } else {
        float a = bq[i] * bk[i], dm = 0.f;
        blockReduce2(a, dm);
        if (i == 0) g_c0 = a * SCALE_;
    }
}

// =================== kSlotA (iteration 0 only) ===================
__global__ void __launch_bounds__(1024) kSlotA(const float* __restrict__ ls_g, const float* __restrict__ ls_b,
                                               const float* __restrict__ gg, const float* __restrict__ gb) {
    __shared__ float sSN[4][256];
    __shared__ float sRed[4096];
    int j = threadIdx.x & 255, q = threadIdx.x >> 8;
    int r0 = blockIdx.x * 4;
    float v = g_slots[(size_t)(r0 + q) * 256 + j];
    float a = v, b = v * v;
    grpReduce2(a, b);
    float m = a * (1.0f / 256.0f);
    float var = b * (1.0f / 256.0f) - m * m;
    float rs = rsqrtf(var + EPSLN);
    sSN[q][j] = (v - m) * rs * ls_g[j] + ls_b[j];
    __syncthreads();
    slotABody(sSN, sRed, r0, q, j, gg, gb);
}

// ============ kFA: 2-row interleaved LN + dots + softmax + P/SA/SW ============
// grid (8, 64), block 128 (4 warps), each warp 128 rows processed in pairs.
__global__ void __launch_bounds__(128, 4) kFA(const float* __restrict__ inputs,
                                              int last, float* __restrict__ out_attn) {
    int b = blockIdx.y;
    int warp = threadIdx.x >> 5, lane = threadIdx.x & 31;
    int row0 = blockIdx.x * 512 + warp * 128;
    int r8 = b * 8;
    int slane = ((lane & 1) << 2) | (lane & 2) | ((lane >> 2) & 1);

    __shared__ __align__(16) float sGQ[8][256];
    {
        const float4* src = (const float4*)(g_gq + (size_t)r8 * 256);
        #pragma unroll
        for (int e = threadIdx.x; e < 512; e += 128)
            ((float4*)sGQ)[e] = src[e];
    }
    float C1s = g_C1[r8 + slane], C2s = g_C2[r8 + slane];
    __syncthreads();

    u64 zero2 = pk2(0.f, 0.f);
    u64 P[8][4];
    #pragma unroll
    for (int k = 0; k < 8; k++) { P[k][0] = zero2; P[k][1] = zero2; P[k][2] = zero2; P[k][3] = zero2; }
    float SAl = 0.f, SWl = 0.f;

    const ulonglong2* vp = (const ulonglong2*)(inputs + ((size_t)b * N_ + row0) * 256);

    #pragma unroll 1
    for (int r = 0; r < 128; r += 2) {
        // two independent rows, chains interleave
        const ulonglong2* v0 = vp + (size_t)r * 64;
        const ulonglong2* v1 = v0 + 64;
        ulonglong2 X0 = v0[lane], X1 = v0[lane + 32];
        ulonglong2 Y0 = v1[lane], Y1 = v1[lane + 32];

        // ---- LN stats, both rows ----
        float sX, ssX, sY, ssY;
        {
            u64 s2  = add2(add2(X0.x, X0.y), add2(X1.x, X1.y));
            u64 ss2 = mul2(X0.x, X0.x);
            fma2(ss2, X0.y, X0.y); fma2(ss2, X1.x, X1.x); fma2(ss2, X1.y, X1.y);
            float lo, hi;
            upk2(s2, lo, hi);  sX  = lo + hi;
            upk2(ss2, lo, hi); ssX = lo + hi;
        }
        {
            u64 s2  = add2(add2(Y0.x, Y0.y), add2(Y1.x, Y1.y));
            u64 ss2 = mul2(Y0.x, Y0.x);
            fma2(ss2, Y0.y, Y0.y); fma2(ss2, Y1.x, Y1.x); fma2(ss2, Y1.y, Y1.y);
            float lo, hi;
            upk2(s2, lo, hi);  sY  = lo + hi;
            upk2(ss2, lo, hi); ssY = lo + hi;
        }
        bool odd = lane & 1;
        {
            float sendX = odd ? sX : ssX;
            float sendY = odd ? sY : ssY;
            float rcvX = __shfl_xor_sync(0xffffffffu, sendX, 1);
            float rcvY = __shfl_xor_sync(0xffffffffu, sendY, 1);
            float vX = odd ? (ssX + rcvX) : (sX + rcvX);
            float vY = odd ? (ssY + rcvY) : (sY + rcvY);
            vX += __shfl_xor_sync(0xffffffffu, vX, 2);
            vY += __shfl_xor_sync(0xffffffffu, vY, 2);
            vX += __shfl_xor_sync(0xffffffffu, vX, 4);
            vY += __shfl_xor_sync(0xffffffffu, vY, 4);
            vX += __shfl_xor_sync(0xffffffffu, vX, 8);
            vY += __shfl_xor_sync(0xffffffffu, vY, 8);
            vX += __shfl_xor_sync(0xffffffffu, vX, 16);
            vY += __shfl_xor_sync(0xffffffffu, vY, 16);
            float oX = __shfl_xor_sync(0xffffffffu, vX, 1);
            float oY = __shfl_xor_sync(0xffffffffu, vY, 1);
            sX  = odd ? oX : vX;  ssX = odd ? vX : oX;
            sY  = odd ? oY : vY;  ssY = odd ? vY : oY;
        }
        float mX   = sX * (1.0f / 256.0f);
        float mY   = sY * (1.0f / 256.0f);
        float rsX  = rsqrtf(fmaf(ssX, 1.0f / 256.0f, -mX * mX) + EPSLN);
        float rsY  = rsqrtf(fmaf(ssY, 1.0f / 256.0f, -mY * mY) + EPSLN);
        float wX   = mX * rsX;
        float wY   = mY * rsY;

        // ---- dots, both rows ----
        float dtX[8], dtY[8];
        #pragma unroll
        for (int k = 0; k < 8; k++) {
            ulonglong2 qa = *(const ulonglong2*)(&sGQ[k][4 * lane]);
            ulonglong2 qb = *(const ulonglong2*)(&sGQ[k][128 + 4 * lane]);
            u64 dX = mul2(X0.x, qa.x);
            u64 dY = mul2(Y0.x, qa.x);
            fma2(dX, X0.y, qa.y); fma2(dY, Y0.y, qa.y);
            fma2(dX, X1.x, qb.x); fma2(dY, Y1.x, qb.x);
            fma2(dX, X1.y, qb.y); fma2(dY, Y1.y, qb.y);
            float lo, hi;
            upk2(dX, lo, hi); dtX[k] = lo + hi;
            upk2(dY, lo, hi); dtY[k] = lo + hi;
        }
        // ---- distributed butterfly reduce, both rows interleaved ----
        float vdX, vdY;
        {
            bool c0 = lane & 1;
            float x0 = c0 ? dtX[0] : dtX[4], y0 = c0 ? dtY[0] : dtY[4];
            float x1 = c0 ? dtX[1] : dtX[5], y1 = c0 ? dtY[1] : dtY[5];
            float x2 = c0 ? dtX[2] : dtX[6], y2 = c0 ? dtY[2] : dtY[6];
            float x3 = c0 ? dtX[3] : dtX[7], y3 = c0 ? dtY[3] : dtY[7];
            x0 = __shfl_xor_sync(0xffffffffu, x0, 1); y0 = __shfl_xor_sync(0xffffffffu, y0, 1);
            x1 = __shfl_xor_sync(0xffffffffu, x1, 1); y1 = __shfl_xor_sync(0xffffffffu, y1, 1);
            x2 = __shfl_xor_sync(0xffffffffu, x2, 1); y2 = __shfl_xor_sync(0xffffffffu, y2, 1);
            x3 = __shfl_xor_sync(0xffffffffu, x3, 1); y3 = __shfl_xor_sync(0xffffffffu, y3, 1);
            float uX0 = (c0 ? dtX[4] : dtX[0]) + x0, uY0 = (c0 ? dtY[4] : dtY[0]) + y0;
            float uX1 = (c0 ? dtX[5] : dtX[1]) + x1, uY1 = (c0 ? dtY[5] : dtY[1]) + y1;
            float uX2 = (c0 ? dtX[6] : dtX[2]) + x2, uY2 = (c0 ? dtY[6] : dtY[2]) + y2;
            float uX3 = (c0 ? dtX[7] : dtX[3]) + x3, uY3 = (c0 ? dtY[7] : dtY[3]) + y3;
            bool c1 = lane & 2;
            float aX0 = c1 ? uX0 : uX2, aY0 = c1 ? uY0 : uY2;
            float aX1 = c1 ? uX1 : uX3, aY1 = c1 ? uY1 : uY3;
            aX0 = __shfl_xor_sync(0xffffffffu, aX0, 2); aY0 = __shfl_xor_sync(0xffffffffu, aY0, 2);
            aX1 = __shfl_xor_sync(0xffffffffu, aX1, 2); aY1 = __shfl_xor_sync(0xffffffffu, aY1, 2);
            float wX0 = (c1 ? uX2 : uX0) + aX0, wY0 = (c1 ? uY2 : uY0) + aY0;
            float wX1 = (c1 ? uX3 : uX1) + aX1, wY1 = (c1 ? uY3 : uY1) + aY1;
            bool c2 = lane & 4;
            float bX = c2 ? wX0 : wX1, bY = c2 ? wY0 : wY1;
            bX = __shfl_xor_sync(0xffffffffu, bX, 4); bY = __shfl_xor_sync(0xffffffffu, bY, 4);
            vdX = (c2 ? wX1 : wX0) + bX;
            vdY = (c2 ? wY1 : wY0) + bY;
            vdX += __shfl_xor_sync(0xffffffffu, vdX, 8);
            vdY += __shfl_xor_sync(0xffffffffu, vdY, 8);
            vdX += __shfl_xor_sync(0xffffffffu, vdX, 16);
            vdY += __shfl_xor_sync(0xffffffffu, vdY, 16);
        }
        // ---- softmax, both rows ----
        float lgX = fmaf(rsX, vdX, fmaf(-wX, C1s, C2s));
        float lgY = fmaf(rsY, vdY, fmaf(-wY, C1s, C2s));
        float mxX = lgX, mxY = lgY;
        mxX = fmaxf(mxX, __shfl_xor_sync(0xffffffffu, mxX, 1));
        mxY = fmaxf(mxY, __shfl_xor_sync(0xffffffffu, mxY, 1));
        mxX = fmaxf(mxX, __shfl_xor_sync(0xffffffffu, mxX, 2));
        mxY = fmaxf(mxY, __shfl_xor_sync(0xffffffffu, mxY, 2));
        mxX = fmaxf(mxX, __shfl_xor_sync(0xffffffffu, mxX, 4));
        mxY = fmaxf(mxY, __shfl_xor_sync(0xffffffffu, mxY, 4));
        float eX = __expf(lgX - mxX);
        float eY = __expf(lgY - mxY);
        float smXv = eX, smYv = eY;
        smXv += __shfl_xor_sync(0xffffffffu, smXv, 1);
        smYv += __shfl_xor_sync(0xffffffffu, smYv, 1);
        smXv += __shfl_xor_sync(0xffffffffu, smXv, 2);
        smYv += __shfl_xor_sync(0xffffffffu, smYv, 2);
        smXv += __shfl_xor_sync(0xffffffffu, smXv, 4);
        smYv += __shfl_xor_sync(0xffffffffu, smYv, 4);
        float aX = __fdividef(eX, smXv);
        float aY = __fdividef(eY, smYv);
        SAl += aX + aY;
        SWl = fmaf(aX, wX, fmaf(aY, wY, SWl));
        if (last && lane < 8) {
            size_t base = (size_t)(r8 + slane) * N_ + row0 + r;
            out_attn[base] = aX;
            out_attn[base + 1] = aY;
        }

        // ---- broadcast + P update, row X then row Y ----
        int gbase = lane & 24;
        {
            float ak[8];
            ak[0] = __shfl_sync(0xffffffffu, aX, gbase | 0);
            ak[1] = __shfl_sync(0xffffffffu, aX, gbase | 4);
            ak[2] = __shfl_sync(0xffffffffu, aX, gbase | 2);
            ak[3] = __shfl_sync(0xffffffffu, aX, gbase | 6);
            ak[4] = __shfl_sync(0xffffffffu, aX, gbase | 1);
            ak[5] = __shfl_sync(0xffffffffu, aX, gbase | 5);
            ak[6] = __shfl_sync(0xffffffffu, aX, gbase | 3);
            ak[7] = __shfl_sync(0xffffffffu, aX, gbase | 7);
            #pragma unroll
            for (int k = 0; k < 8; k++) {
                float ar = ak[k] * rsX;
                u64 ap = pk2(ar, ar);
                fma2(P[k][0], ap, X0.x); fma2(P[k][1], ap, X0.y);
                fma2(P[k][2], ap, X1.x); fma2(P[k][3], ap, X1.y);
            }
        }
        {
            float ak[8];
            ak[0] = __shfl_sync(0xffffffffu, aY, gbase | 0);
            ak[1] = __shfl_sync(0xffffffffu, aY, gbase | 4);
            ak[2] = __shfl_sync(0xffffffffu, aY, gbase | 2);
            ak[3] = __shfl_sync(0xffffffffu, aY, gbase | 6);
            ak[4] = __shfl_sync(0xffffffffu, aY, gbase | 1);
            ak[5] = __shfl_sync(0xffffffffu, aY, gbase | 5);
            ak[6] = __shfl_sync(0xffffffffu, aY, gbase | 3);
            ak[7] = __shfl_sync(0xffffffffu, aY, gbase | 7);
            #pragma unroll
            for (int k = 0; k < 8; k++) {
                float ar = ak[k] * rsY;
                u64 ap = pk2(ar, ar);
                fma2(P[k][0], ap, Y0.x); fma2(P[k][1], ap, Y0.y);
                fma2(P[k][2], ap, Y1.x); fma2(P[k][3], ap, Y1.y);
            }
        }
    }

    __shared__ float sP[4][8][256];
    __shared__ float sSA[4][8], sSW[4][8];
    #pragma unroll
    for (int k = 0; k < 8; k++) {
        float x, y;
        upk2(P[k][0], x, y); sP[warp][k][4 * lane] = x;       sP[warp][k][4 * lane + 1] = y;
        upk2(P[k][1], x, y); sP[warp][k][4 * lane + 2] = x;   sP[warp][k][4 * lane + 3] = y;
        upk2(P[k][2], x, y); sP[warp][k][128 + 4 * lane] = x; sP[warp][k][128 + 4 * lane + 1] = y;
        upk2(P[k][3], x, y); sP[warp][k][128 + 4 * lane + 2] = x; sP[warp][k][128 + 4 * lane + 3] = y;
    }
    if (lane < 8) { sSA[warp][slane] = SAl; sSW[warp][slane] = SWl; }
    __syncthreads();
    for (int t = threadIdx.x; t < 2048; t += 128) {
        int k = t >> 8, d = t & 255;
        float v = (sP[0][k][d] + sP[1][k][d]) + (sP[2][k][d] + sP[3][k][d]);
        atomicAdd(&g_P[(size_t)(r8 + k) * 256 + d], v);
    }
    if (threadIdx.x < 8) {
        int k = threadIdx.x;
        atomicAdd(&g_SA[r8 + k], (sSA[0][k] + sSA[1][k]) + (sSA[2][k] + sSA[3][k]));
    } else if (threadIdx.x < 16) {
        int k = threadIdx.x - 8;
        atomicAdd(&g_SW[r8 + k], (sSW[0][k] + sSW[1][k]) + (sSW[2][k] + sSW[3][k]));
    }
}

// =================== kSlotB: packed-weight GEMV stages ===================
__global__ void __launch_bounds__(1024) kSlotB(const float* __restrict__ gg, const float* __restrict__ gb,
                                               const float* __restrict__ bv,
                                               const float* __restrict__ b_ih, const float* __restrict__ b_hh,
                                               const float* __restrict__ lnf_g, const float* __restrict__ lnf_b,
                                               const float* __restrict__ b1, const float* __restrict__ b2,
                                               const float* __restrict__ ls_g, const float* __restrict__ ls_b,
                                               int last, float* __restrict__ out_slots) {
    __shared__ float sA[4][256];
    __shared__ float sB[4][256];
    __shared__ float sSL[4][256];
    __shared__ float sF1[4][512];
    __shared__ float sRed[4096];
    int j = threadIdx.x & 255, q = threadIdx.x >> 8;
    int r0 = blockIdx.x * 4;
    int row = r0 + q;

    float snorm;
    {
        float SA = g_SA[row], SW = g_SW[row];
        float inv = 1.0f / (SA + EPSA);
        float Pv = g_P[(size_t)row * 256 + j];
        sA[q][j] = (gg[j] * (Pv - SW) + gb[j] * SA) * inv;
        sSL[q][j] = g_slots[(size_t)row * 256 + j];
        snorm = SA * inv;
    }
    __syncthreads();

    {
        float acc[4] = {0.f, 0.f, 0.f, 0.f};
        gemvPQ(g_WvP, 256, 16, 16 * q, &sA[0][0], 256, j, acc);
        float x = reduceWave(acc, sRed, q, j);
        sB[q][j] = fmaf(snorm, bv[j], x);
    }
    __syncthreads();

    float ir, iz, inn;
    {
        float pir[4] = {}, piz[4] = {}, pin[4] = {};
        const float4* pw = (const float4*)g_WihP + (size_t)(16 * q) * 768 + j;
        #pragma unroll 2
        for (int bq_ = 0; bq_ < 16; bq_++) {
            float4 wr = pw[(size_t)bq_ * 768];
            float4 wz = pw[(size_t)bq_ * 768 + 256];
            float4 wn = pw[(size_t)bq_ * 768 + 512];
            #pragma unroll
            for (int r = 0; r < 4; r++) {
                float4 x = *(const float4*)(&sB[r][64 * q + 4 * bq_]);
                pir[r] = fmaf(x.x, wr.x, fmaf(x.y, wr.y, fmaf(x.z, wr.z, fmaf(x.w, wr.w, pir[r]))));
                piz[r] = fmaf(x.x, wz.x, fmaf(x.y, wz.y, fmaf(x.z, wz.z, fmaf(x.w, wz.w, piz[r]))));
                pin[r] = fmaf(x.x, wn.x, fmaf(x.y, wn.y, fmaf(x.z, wn.z, fmaf(x.w, wn.w, pin[r]))));
            }
        }
        ir  = reduceWave(pir, sRed, q, j);
        iz  = reduceWave(piz, sRed, q, j);
        inn = reduceWave(pin, sRed, q, j);
    }
    float hr, hz, hn;
    {
        float phr[4] = {}, phz[4] = {}, phn[4] = {};
        const float4* pw = (const float4*)g_WhhP + (size_t)(16 * q) * 768 + j;
        #pragma unroll 2
        for (int bq_ = 0; bq_ < 16; bq_++) {
            float4 wr = pw[(size_t)bq_ * 768];
            float4 wz = pw[(size_t)bq_ * 768 + 256];
            float4 wn = pw[(size_t)bq_ * 768 + 512];
            #pragma unroll
            for (int r = 0; r < 4; r++) {
                float4 x = *(const float4*)(&sSL[r][64 * q + 4 * bq_]);
                phr[r] = fmaf(x.x, wr.x, fmaf(x.y, wr.y, fmaf(x.z, wr.z, fmaf(x.w, wr.w, phr[r]))));
                phz[r] = fmaf(x.x, wz.x, fmaf(x.y, wz.y, fmaf(x.z, wz.z, fmaf(x.w, wz.w, phz[r]))));
                phn[r] = fmaf(x.x, wn.x, fmaf(x.y, wn.y, fmaf(x.z, wn.z, fmaf(x.w, wn.w, phn[r]))));
            }
        }
        hr = reduceWave(phr, sRed, q, j);
        hz = reduceWave(phz, sRed, q, j);
        hn = reduceWave(phn, sRed, q, j);
    }

    float h_reg;
    {
        float rr = 1.0f / (1.0f + __expf(-(ir + b_ih[j] + hr + b_hh[j])));
        float zz = 1.0f / (1.0f + __expf(-(iz + b_ih[256 + j] + hz + b_hh[256 + j])));
        float nn = tanhf(inn + b_ih[512 + j] + rr * (hn + b_hh[512 + j]));
        float h = (1.0f - zz) * nn + zz * sSL[q][j];
        h_reg = h;
        float a = h, bb = h * h;
        grpReduce2(a, bb);
        float m = a * (1.0f / 256.0f);
        float var = bb * (1.0f / 256.0f) - m * m;
        float rs = rsqrtf(var + EPSLN);
        __syncthreads();
        sA[q][j] = (h - m) * rs * lnf_g[j] + lnf_b[j];
    }
    __syncthreads();

    {
        float f0[4] = {}, f1v[4] = {};
        const float4* p1 = (const float4*)g_W1P + (size_t)(16 * q) * 512 + j;
        #pragma unroll 2
        for (int bq_ = 0; bq_ < 16; bq_++) {
            float4 wa = p1[(size_t)bq_ * 512];
            float4 wb4 = p1[(size_t)bq_ * 512 + 256];
            #pragma unroll
            for (int r = 0; r < 4; r++) {
                float4 x = *(const float4*)(&sA[r][64 * q + 4 * bq_]);
                f0[r]  = fmaf(x.x, wa.x,  fmaf(x.y, wa.y,  fmaf(x.z, wa.z,  fmaf(x.w, wa.w,  f0[r]))));
                f1v[r] = fmaf(x.x, wb4.x, fmaf(x.y, wb4.y, fmaf(x.z, wb4.z, fmaf(x.w, wb4.w, f1v[r]))));
            }
        }
        float h0 = reduceWave(f0, sRed, q, j);
        float h1 = reduceWave(f1v, sRed, q, j);
        sF1[q][j]       = fmaxf(h0 + b1[j], 0.f);
        sF1[q][256 + j] = fmaxf(h1 + b1[256 + j], 0.f);
    }
    __syncthreads();

    float ns;
    {
        float o[4] = {0.f, 0.f, 0.f, 0.f};
        gemvPQ(g_W2P, 256, 32, 32 * q, &sF1[0][0], 512, j, o);
        float oo = reduceWave(o, sRed, q, j);
        ns = h_reg + oo + b2[j];
        g_slots[(size_t)row * 256 + j] = ns;
        if (last) out_slots[(size_t)row * 256 + j] = ns;
    }

    if (!last) {
        float a = ns, bb = ns * ns;
        grpReduce2(a, bb);
        float m = a * (1.0f / 256.0f);
        float var = bb * (1.0f / 256.0f) - m * m;
        float rs = rsqrtf(var + EPSLN);
        __syncthreads();
        sB[q][j] = (ns - m) * rs * ls_g[j] + ls_b[j];
        __syncthreads();
        slotABody((const float (*)[256])sB, sRed, r0, q, j, gg, gb);
    }
}

// ---------------- launch ----------------
extern "C" void kernel_launch(void* const* d_in, const int* in_sizes, int n_in,
                              void* d_out, int out_size) {
    (void)in_sizes; (void)n_in; (void)out_size;
    const float* inputs  = (const float*)d_in[0];
    const float* noise   = (const float*)d_in[1];
    const float* slot_mu = (const float*)d_in[2];
    const float* slot_ls = (const float*)d_in[3];
    const float* Wq      = (const float*)d_in[4];
    const float* bq      = (const float*)d_in[5];
    const float* Wk      = (const float*)d_in[6];
    const float* bk      = (const float*)d_in[7];
    const float* Wv      = (const float*)d_in[8];
    const float* bv      = (const float*)d_in[9];
    const float* W_ih    = (const float*)d_in[10];
    const float* b_ih    = (const float*)d_in[11];
    const float* W_hh    = (const float*)d_in[12];
    const float* b_hh    = (const float*)d_in[13];
    const float* ln_in_g = (const float*)d_in[14];
    const float* ln_in_b = (const float*)d_in[15];
    const float* ln_s_g  = (const float*)d_in[16];
    const float* ln_s_b  = (const float*)d_in[17];
    const float* ln_ff_g = (const float*)d_in[18];
    const float* ln_ff_b = (const float*)d_in[19];
    const float* W1      = (const float*)d_in[20];
    const float* b1      = (const float*)d_in[21];
    const float* W2      = (const float*)d_in[22];
    const float* b2      = (const float*)d_in[23];

    float* out = (float*)d_out;
    float* out_slots = out;
    float* out_attn  = out + BK_ * D_;

    kSetup<<<1475, 256>>>(W_ih, W_hh, Wv, W1, W2, noise, slot_mu, slot_ls, Wq, Wk, bq, bk);
    kSlotA<<<128, 1024>>>(ln_s_g, ln_s_b, ln_in_g, ln_in_b);

    for (int it = 0; it < 3; it++) {
        int last = (it == 2);
        kFA<<<dim3(8, 64), 128>>>(inputs, last, out_attn);
        kSlotB<<<128, 1024>>>(ln_in_g, ln_in_b, bv, b_ih, b_hh,
                              ln_ff_g, ln_ff_b, b1, b2, ln_s_g, ln_s_b,
                              last, out_slots);
    }
}

// round 14
// speedup vs baseline: 2.4882x; 1.0472x over previous
#include <cuda_runtime.h>
#include <math.h>
#include <stdint.h>
#include <stddef.h>

// ---------------- problem dims ----------------
#define B_    64
#define N_    4096
#define DIN_  256
#define K_    8
#define D_    256
#define H_    512
#define BK_   512
#define SCALE_ 0.0625f
#define EPSLN 1e-5f
#define EPSA  1e-8f

typedef unsigned long long u64;

// ---------------- device scratch ----------------
__device__ __align__(16) float g_slots[BK_ * D_];
__device__ __align__(16) float g_gq[BK_ * D_];
__device__ float g_C1[BK_];
__device__ float g_C2[BK_];
__device__ __align__(16) float g_P[BK_ * D_];
__device__ float g_SA[BK_];
__device__ float g_SW[BK_];
__device__ float g_bqk[D_];
__device__ float g_wb[D_];
__device__ float g_c0;
// packed weights: Wp[(kb * Nout + o)*4 + t] = W[o][4*kb + t]
__device__ __align__(16) float g_WqkP[D_ * D_];
__device__ __align__(16) float g_WihP[3 * D_ * D_];
__device__ __align__(16) float g_WhhP[3 * D_ * D_];
__device__ __align__(16) float g_WvP[D_ * D_];
__device__ __align__(16) float g_W1P[H_ * D_];
__device__ __align__(16) float g_W2P[D_ * H_];

// ---------------- f32x2 packed helpers ----------------
__device__ __forceinline__ u64 pk2(float x, float y) {
    u64 r; asm("mov.b64 %0, {%1, %2};" : "=l"(r) : "f"(x), "f"(y)); return r;
}
__device__ __forceinline__ void upk2(u64 v, float& x, float& y) {
    asm("mov.b64 {%0, %1}, %2;" : "=f"(x), "=f"(y) : "l"(v));
}
__device__ __forceinline__ void fma2(u64& d, u64 a, u64 b) {
    asm("fma.rn.f32x2 %0, %1, %2, %0;" : "+l"(d) : "l"(a), "l"(b));
}
__device__ __forceinline__ u64 add2(u64 a, u64 b) {
    u64 r; asm("add.rn.f32x2 %0, %1, %2;" : "=l"(r) : "l"(a), "l"(b)); return r;
}
__device__ __forceinline__ u64 mul2(u64 a, u64 b) {
    u64 r; asm("mul.rn.f32x2 %0, %1, %2;" : "=l"(r) : "l"(a), "l"(b)); return r;
}

// ---------------- cp.async helpers ----------------
__device__ __forceinline__ void cpasync16(uint32_t saddr, const void* gptr) {
    asm volatile("cp.async.cg.shared.global [%0], [%1], 16;" :: "r"(saddr), "l"(gptr) : "memory");
}
#define CP_COMMIT() asm volatile("cp.async.commit_group;" ::: "memory")
#define CP_WAIT1()  asm volatile("cp.async.wait_group 1;" ::: "memory")
#define CP_WAIT0()  asm volatile("cp.async.wait_group 0;" ::: "memory")

// ---------------- block reduce ----------------
__device__ __forceinline__ void blockReduce2(float& a, float& b) {
    #pragma unroll
    for (int o = 16; o; o >>= 1) {
        a += __shfl_xor_sync(0xffffffffu, a, o);
        b += __shfl_xor_sync(0xffffffffu, b, o);
    }
    __shared__ float sa[8], sb[8];
    __syncthreads();
    int w = threadIdx.x >> 5;
    if ((threadIdx.x & 31) == 0) { sa[w] = a; sb[w] = b; }
    __syncthreads();
    a = sa[threadIdx.x & 7];
    b = sb[threadIdx.x & 7];
    #pragma unroll
    for (int o = 4; o; o >>= 1) {
        a += __shfl_xor_sync(0xffffffffu, a, o);
        b += __shfl_xor_sync(0xffffffffu, b, o);
    }
}

// ---------------- group reduce: 1024 threads, 4 groups of 256 ----------------
__device__ __forceinline__ void grpReduce2(float& a, float& b) {
    #pragma unroll
    for (int o = 16; o; o >>= 1) {
        a += __shfl_xor_sync(0xffffffffu, a, o);
        b += __shfl_xor_sync(0xffffffffu, b, o);
    }
    __shared__ float sa[32], sb[32];
    int w = threadIdx.x >> 5;
    __syncthreads();
    if ((threadIdx.x & 31) == 0) { sa[w] = a; sb[w] = b; }
    __syncthreads();
    int g8 = (threadIdx.x >> 8) << 3;
    float ra = 0.f, rb = 0.f;
    #pragma unroll
    for (int i = 0; i < 8; i++) { ra += sa[g8 + i]; rb += sb[g8 + i]; }
    a = ra; b = rb;
}

// ---------------- packed GEMV ----------------
__device__ __forceinline__ void gemvPQ(const float* __restrict__ Wp, int Nout, int nblk, int kb0,
                                       const float* s_in, int in_stride, int j, float acc[4]) {
    const float4* p = (const float4*)Wp + (size_t)kb0 * Nout + j;
    #pragma unroll 4
    for (int b = 0; b < nblk; b++) {
        float4 w = p[(size_t)b * Nout];
        #pragma unroll
        for (int r = 0; r < 4; r++) {
            float4 x = *(const float4*)(s_in + r * in_stride + (kb0 + b) * 4);
            acc[r] = fmaf(x.x, w.x, fmaf(x.y, w.y, fmaf(x.z, w.z, fmaf(x.w, w.w, acc[r]))));
        }
    }
}

// ---------------- reduction wave ----------------
__device__ __forceinline__ float reduceWave(const float part[4], float* sRed, int q, int j) {
    __syncthreads();
    #pragma unroll
    for (int r = 0; r < 4; r++) sRed[((q << 2) + r) * 256 + j] = part[r];
    __syncthreads();
    return (sRed[(0 + q) * 256 + j] + sRed[(4 + q) * 256 + j]) +
           (sRed[(8 + q) * 256 + j] + sRed[(12 + q) * 256 + j]);
}

// ---------------- slot-A body ----------------
__device__ __forceinline__ void slotABody(const float (*s_sn)[256], float* sRed,
                                          int r0, int q, int j,
                                          const float* __restrict__ gg, const float* __restrict__ gb) {
    float acc[4] = {0.f, 0.f, 0.f, 0.f};
    gemvPQ(g_WqkP, 256, 16, 16 * q, &s_sn[0][0], 256, j, acc);
    float qt = reduceWave(acc, sRed, q, j) + g_bqk[j];
    int row = r0 + q;
    float gq = gg[j] * qt;
    g_gq[(size_t)row * 256 + j] = gq;
    float c1 = gq;
    float c2 = fmaf(qt, gb[j], s_sn[q][j] * g_wb[j]);
    grpReduce2(c1, c2);
    if (j == 0) { g_C1[row] = c1; g_C2[row] = c2 + g_c0; }
    g_P[(size_t)row * 256 + j] = 0.f;
    if (j == 0) { g_SA[row] = 0.f; g_SW[row] = 0.f; }
}

// =================== SETUP ===================
__device__ __forceinline__ void packTile(const float* __restrict__ src, float* __restrict__ dst,
                                         int Nout, int Kb, int blk) {
    int e = blk * 256 + threadIdx.x;
    int o = e / Kb, kb = e - o * Kb;
    float4 v = *(const float4*)(src + (size_t)o * Kb * 4 + (size_t)kb * 4);
    *(float4*)(dst + ((size_t)kb * Nout + o) * 4) = v;
}

__global__ void __launch_bounds__(256) kSetup(const float* __restrict__ W_ih, const float* __restrict__ W_hh,
                                              const float* __restrict__ Wv, const float* __restrict__ W1,
                                              const float* __restrict__ W2, const float* __restrict__ noise,
                                              const float* __restrict__ mu, const float* __restrict__ ls,
                                              const float* __restrict__ Wq, const float* __restrict__ Wk,
                                              const float* __restrict__ bq, const float* __restrict__ bk) {
    int t = blockIdx.x;
    int i = threadIdx.x;
    if (t < 192)       packTile(W_ih, g_WihP, 768, 64, t);
    else if (t < 384)  packTile(W_hh, g_WhhP, 768, 64, t - 192);
    else if (t < 448)  packTile(Wv,   g_WvP,  256, 64, t - 384);
    else if (t < 576)  packTile(W1,   g_W1P,  512, 64, t - 448);
    else if (t < 704)  packTile(W2,   g_W2P,  256, 128, t - 576);
    else if (t < 1216) {
        int idx = (t - 704) * 256 + i;
        int d = idx & 255;
        g_slots[idx] = mu[d] + __expf(ls[d]) * noise[idx];
    } else if (t < 1472) {
        int jj = t - 1216;
        float acc[8] = {0.f,0.f,0.f,0.f,0.f,0.f,0.f,0.f};
        #pragma unroll 4
        for (int d = 0; d < 256; d += 8) {
            #pragma unroll
            for (int u = 0; u < 8; u++)
                acc[u] = fmaf(Wq[(d + u) * 256 + jj], Wk[(d + u) * 256 + i], acc[u]);
        }
        float v = (((acc[0] + acc[1]) + (acc[2] + acc[3])) + ((acc[4] + acc[5]) + (acc[6] + acc[7]))) * SCALE_;
        g_WqkP[(((size_t)(jj >> 2)) * 256 + i) * 4 + (jj & 3)] = v;
    } else if (t == 1472) {
        float a = 0.f;
        #pragma unroll 8
        for (int d = 0; d < 256; d++) a = fmaf(bq[d], Wk[d * 256 + i], a);
        g_bqk[i] = a * SCALE_;
    } else if (t == 1473) {
        float a = 0.f;
        #pragma unroll 8
        for (int d = 0; d < 256; d++) a = fmaf(Wq[d * 256 + i], bk[d], a);
        g_wb[i] = a * SCALE_;
    } else {
        float a = bq[i] * bk[i], dm = 0.f;
        blockReduce2(a, dm);
        if (i == 0) g_c0 = a * SCALE_;
    }
}

// =================== kSlotA (iteration 0 only) ===================
__global__ void __launch_bounds__(1024) kSlotA(const float* __restrict__ ls_g, const float* __restrict__ ls_b,
                                               const float* __restrict__ gg, const float* __restrict__ gb) {
    __shared__ float sSN[4][256];
    __shared__ float sRed[4096];
    int j = threadIdx.x & 255, q = threadIdx.x >> 8;
    int r0 = blockIdx.x * 4;
    float v = g_slots[(size_t)(r0 + q) * 256 + j];
    float a = v, b = v * v;
    grpReduce2(a, b);
    float m = a * (1.0f / 256.0f);
    float var = b * (1.0f / 256.0f) - m * m;
    float rs = rsqrtf(var + EPSLN);
    sSN[q][j] = (v - m) * rs * ls_g[j] + ls_b[j];
    __syncthreads();
    slotABody(sSN, sRed, r0, q, j, gg, gb);
}

// ============ kFA: cp.async-pipelined 2-row interleaved attention pass ============
// grid (8, 64), block 128 (4 warps), each warp 128 rows in 64 pairs through a 3-buf smem ring.
__global__ void __launch_bounds__(128, 4) kFA(const float* __restrict__ inputs,
                                              int last, float* __restrict__ out_attn) {
    int b = blockIdx.y;
    int warp = threadIdx.x >> 5, lane = threadIdx.x & 31;
    int row0 = blockIdx.x * 512 + warp * 128;
    int r8 = b * 8;
    int slane = ((lane & 1) << 2) | (lane & 2) | ((lane >> 2) & 1);

    __shared__ __align__(16) float sGQ[8][256];   // 8KB
    __shared__ __align__(16) float sBuf[8192];    // 32KB: loop = 3-buf x ring (24KB); flush = sP
    __shared__ float sSA[4][8], sSW[4][8];

    {
        const float4* src = (const float4*)(g_gq + (size_t)r8 * 256);
        #pragma unroll
        for (int e = threadIdx.x; e < 512; e += 128)
            ((float4*)sGQ)[e] = src[e];
    }
    float C1s = g_C1[r8 + slane], C2s = g_C2[r8 + slane];
    __syncthreads();

    float* ring = sBuf + warp * 1536;                      // 3 bufs x 512 floats
    uint32_t ringAddr = (uint32_t)__cvta_generic_to_shared(ring);
    const float* gbase = inputs + ((size_t)b * N_ + row0) * 256;

    u64 P[8][4];
    #pragma unroll
    for (int k = 0; k < 8; k++) { P[k][0] = 0; P[k][1] = 0; P[k][2] = 0; P[k][3] = 0; }
    float SAl = 0.f, SWl = 0.f;

    // prefetch pairs 0,1
    #pragma unroll
    for (int pr = 0; pr < 2; pr++) {
        const float* gsrc = gbase + (size_t)pr * 512;
        uint32_t sdst = ringAddr + pr * 2048;
        #pragma unroll
        for (int c = 0; c < 4; c++)
            cpasync16(sdst + (c * 32 + lane) * 16, gsrc + (c * 32 + lane) * 4);
        CP_COMMIT();
    }

    #pragma unroll 1
    for (int p = 0; p < 64; p++) {
        CP_WAIT1();
        __syncwarp();
        const float* xb = ring + (p % 3) * 512;
        ulonglong2 X0 = *(const ulonglong2*)(xb + 4 * lane);
        ulonglong2 X1 = *(const ulonglong2*)(xb + 128 + 4 * lane);
        ulonglong2 Y0 = *(const ulonglong2*)(xb + 256 + 4 * lane);
        ulonglong2 Y1 = *(const ulonglong2*)(xb + 256 + 128 + 4 * lane);

        // prefetch pair p+2 into buf (p+2)%3 (distinct from read buf and in-flight buf)
        if (p < 62) {
            const float* gsrc = gbase + (size_t)(p + 2) * 512;
            uint32_t sdst = ringAddr + ((p + 2) % 3) * 2048;
            #pragma unroll
            for (int c = 0; c < 4; c++)
                cpasync16(sdst + (c * 32 + lane) * 16, gsrc + (c * 32 + lane) * 4);
        }
        CP_COMMIT();   // always commit (possibly-empty group) so wait_group count is uniform

        // ---- LN stats, both rows ----
        float sX, ssX, sY, ssY;
        {
            u64 s2  = add2(add2(X0.x, X0.y), add2(X1.x, X1.y));
            u64 ss2 = mul2(X0.x, X0.x);
            fma2(ss2, X0.y, X0.y); fma2(ss2, X1.x, X1.x); fma2(ss2, X1.y, X1.y);
            float lo, hi;
            upk2(s2, lo, hi);  sX  = lo + hi;
            upk2(ss2, lo, hi); ssX = lo + hi;
        }
        {
            u64 s2  = add2(add2(Y0.x, Y0.y), add2(Y1.x, Y1.y));
            u64 ss2 = mul2(Y0.x, Y0.x);
            fma2(ss2, Y0.y, Y0.y); fma2(ss2, Y1.x, Y1.x); fma2(ss2, Y1.y, Y1.y);
            float lo, hi;
            upk2(s2, lo, hi);  sY  = lo + hi;
            upk2(ss2, lo, hi); ssY = lo + hi;
        }
        bool odd = lane & 1;
        {
            float sendX = odd ? sX : ssX;
            float sendY = odd ? sY : ssY;
            float rcvX = __shfl_xor_sync(0xffffffffu, sendX, 1);
            float rcvY = __shfl_xor_sync(0xffffffffu, sendY, 1);
            float vX = odd ? (ssX + rcvX) : (sX + rcvX);
            float vY = odd ? (ssY + rcvY) : (sY + rcvY);
            vX += __shfl_xor_sync(0xffffffffu, vX, 2);
            vY += __shfl_xor_sync(0xffffffffu, vY, 2);
            vX += __shfl_xor_sync(0xffffffffu, vX, 4);
            vY += __shfl_xor_sync(0xffffffffu, vY, 4);
            vX += __shfl_xor_sync(0xffffffffu, vX, 8);
            vY += __shfl_xor_sync(0xffffffffu, vY, 8);
            vX += __shfl_xor_sync(0xffffffffu, vX, 16);
            vY += __shfl_xor_sync(0xffffffffu, vY, 16);
            float oX = __shfl_xor_sync(0xffffffffu, vX, 1);
            float oY = __shfl_xor_sync(0xffffffffu, vY, 1);
            sX  = odd ? oX : vX;  ssX = odd ? vX : oX;
            sY  = odd ? oY : vY;  ssY = odd ? vY : oY;
        }
        float mX   = sX * (1.0f / 256.0f);
        float mY   = sY * (1.0f / 256.0f);
        float rsX  = rsqrtf(fmaf(ssX, 1.0f / 256.0f, -mX * mX) + EPSLN);
        float rsY  = rsqrtf(fmaf(ssY, 1.0f / 256.0f, -mY * mY) + EPSLN);
        float wX   = mX * rsX;
        float wY   = mY * rsY;

        // ---- dots, both rows ----
        float dtX[8], dtY[8];
        #pragma unroll
        for (int k = 0; k < 8; k++) {
            ulonglong2 qa = *(const ulonglong2*)(&sGQ[k][4 * lane]);
            ulonglong2 qb = *(const ulonglong2*)(&sGQ[k][128 + 4 * lane]);
            u64 dX = mul2(X0.x, qa.x);
            u64 dY = mul2(Y0.x, qa.x);
            fma2(dX, X0.y, qa.y); fma2(dY, Y0.y, qa.y);
            fma2(dX, X1.x, qb.x); fma2(dY, Y1.x, qb.x);
            fma2(dX, X1.y, qb.y); fma2(dY, Y1.y, qb.y);
            float lo, hi;
            upk2(dX, lo, hi); dtX[k] = lo + hi;
            upk2(dY, lo, hi); dtY[k] = lo + hi;
        }
        // ---- distributed butterfly reduce, both rows interleaved ----
        float vdX, vdY;
        {
            bool c0 = lane & 1;
            float x0 = c0 ? dtX[0] : dtX[4], y0 = c0 ? dtY[0] : dtY[4];
            float x1 = c0 ? dtX[1] : dtX[5], y1 = c0 ? dtY[1] : dtY[5];
            float x2 = c0 ? dtX[2] : dtX[6], y2 = c0 ? dtY[2] : dtY[6];
            float x3 = c0 ? dtX[3] : dtX[7], y3 = c0 ? dtY[3] : dtY[7];
            x0 = __shfl_xor_sync(0xffffffffu, x0, 1); y0 = __shfl_xor_sync(0xffffffffu, y0, 1);
            x1 = __shfl_xor_sync(0xffffffffu, x1, 1); y1 = __shfl_xor_sync(0xffffffffu, y1, 1);
            x2 = __shfl_xor_sync(0xffffffffu, x2, 1); y2 = __shfl_xor_sync(0xffffffffu, y2, 1);
            x3 = __shfl_xor_sync(0xffffffffu, x3, 1); y3 = __shfl_xor_sync(0xffffffffu, y3, 1);
            float uX0 = (c0 ? dtX[4] : dtX[0]) + x0, uY0 = (c0 ? dtY[4] : dtY[0]) + y0;
            float uX1 = (c0 ? dtX[5] : dtX[1]) + x1, uY1 = (c0 ? dtY[5] : dtY[1]) + y1;
            float uX2 = (c0 ? dtX[6] : dtX[2]) + x2, uY2 = (c0 ? dtY[6] : dtY[2]) + y2;
            float uX3 = (c0 ? dtX[7] : dtX[3]) + x3, uY3 = (c0 ? dtY[7] : dtY[3]) + y3;
            bool c1 = lane & 2;
            float aX0 = c1 ? uX0 : uX2, aY0 = c1 ? uY0 : uY2;
            float aX1 = c1 ? uX1 : uX3, aY1 = c1 ? uY1 : uY3;
            aX0 = __shfl_xor_sync(0xffffffffu, aX0, 2); aY0 = __shfl_xor_sync(0xffffffffu, aY0, 2);
            aX1 = __shfl_xor_sync(0xffffffffu, aX1, 2); aY1 = __shfl_xor_sync(0xffffffffu, aY1, 2);
            float wX0 = (c1 ? uX2 : uX0) + aX0, wY0 = (c1 ? uY2 : uY0) + aY0;
            float wX1 = (c1 ? uX3 : uX1) + aX1, wY1 = (c1 ? uY3 : uY1) + aY1;
            bool c2 = lane & 4;
            float bX = c2 ? wX0 : wX1, bY = c2 ? wY0 : wY1;
            bX = __shfl_xor_sync(0xffffffffu, bX, 4); bY = __shfl_xor_sync(0xffffffffu, bY, 4);
            vdX = (c2 ? wX1 : wX0) + bX;
            vdY = (c2 ? wY1 : wY0) + bY;
            vdX += __shfl_xor_sync(0xffffffffu, vdX, 8);
            vdY += __shfl_xor_sync(0xffffffffu, vdY, 8);
            vdX += __shfl_xor_sync(0xffffffffu, vdX, 16);
            vdY += __shfl_xor_sync(0xffffffffu, vdY, 16);
        }
        // ---- softmax, both rows ----
        float lgX = fmaf(rsX, vdX, fmaf(-wX, C1s, C2s));
        float lgY = fmaf(rsY, vdY, fmaf(-wY, C1s, C2s));
        float mxX = lgX, mxY = lgY;
        mxX = fmaxf(mxX, __shfl_xor_sync(0xffffffffu, mxX, 1));
        mxY = fmaxf(mxY, __shfl_xor_sync(0xffffffffu, mxY, 1));
        mxX = fmaxf(mxX, __shfl_xor_sync(0xffffffffu, mxX, 2));
        mxY = fmaxf(mxY, __shfl_xor_sync(0xffffffffu, mxY, 2));
        mxX = fmaxf(mxX, __shfl_xor_sync(0xffffffffu, mxX, 4));
        mxY = fmaxf(mxY, __shfl_xor_sync(0xffffffffu, mxY, 4));
        float eX = __expf(lgX - mxX);
        float eY = __expf(lgY - mxY);
        float smXv = eX, smYv = eY;
        smXv += __shfl_xor_sync(0xffffffffu, smXv, 1);
        smYv += __shfl_xor_sync(0xffffffffu, smYv, 1);
        smXv += __shfl_xor_sync(0xffffffffu, smXv, 2);
        smYv += __shfl_xor_sync(0xffffffffu, smYv, 2);
        smXv += __shfl_xor_sync(0xffffffffu, smXv, 4);
        smYv += __shfl_xor_sync(0xffffffffu, smYv, 4);
        float aX = __fdividef(eX, smXv);
        float aY = __fdividef(eY, smYv);
        SAl += aX + aY;
        SWl = fmaf(aX, wX, fmaf(aY, wY, SWl));
        if (last && lane < 8) {
            size_t base = (size_t)(r8 + slane) * N_ + row0 + 2 * p;
            out_attn[base] = aX;
            out_attn[base + 1] = aY;
        }

        // ---- broadcast pre-scaled (a*rs) + P update ----
        float arX = aX * rsX;
        float arY = aY * rsY;
        int gbase2 = lane & 24;
        {
            float ak[8];
            ak[0] = __shfl_sync(0xffffffffu, arX, gbase2 | 0);
            ak[1] = __shfl_sync(0xffffffffu, arX, gbase2 | 4);
            ak[2] = __shfl_sync(0xffffffffu, arX, gbase2 | 2);
            ak[3] = __shfl_sync(0xffffffffu, arX, gbase2 | 6);
            ak[4] = __shfl_sync(0xffffffffu, arX, gbase2 | 1);
            ak[5] = __shfl_sync(0xffffffffu, arX, gbase2 | 5);
            ak[6] = __shfl_sync(0xffffffffu, arX, gbase2 | 3);
            ak[7] = __shfl_sync(0xffffffffu, arX, gbase2 | 7);
            #pragma unroll
            for (int k = 0; k < 8; k++) {
                u64 ap = pk2(ak[k], ak[k]);
                fma2(P[k][0], ap, X0.x); fma2(P[k][1], ap, X0.y);
                fma2(P[k][2], ap, X1.x); fma2(P[k][3], ap, X1.y);
            }
        }
        {
            float ak[8];
            ak[0] = __shfl_sync(0xffffffffu, arY, gbase2 | 0);
            ak[1] = __shfl_sync(0xffffffffu, arY, gbase2 | 4);
            ak[2] = __shfl_sync(0xffffffffu, arY, gbase2 | 2);
            ak[3] = __shfl_sync(0xffffffffu, arY, gbase2 | 6);
            ak[4] = __shfl_sync(0xffffffffu, arY, gbase2 | 1);
            ak[5] = __shfl_sync(0xffffffffu, arY, gbase2 | 5);
            ak[6] = __shfl_sync(0xffffffffu, arY, gbase2 | 3);
            ak[7] = __shfl_sync(0xffffffffu, arY, gbase2 | 7);
            #pragma unroll
            for (int k = 0; k < 8; k++) {
                u64 ap = pk2(ak[k], ak[k]);
                fma2(P[k][0], ap, Y0.x); fma2(P[k][1], ap, Y0.y);
                fma2(P[k][2], ap, Y1.x); fma2(P[k][3], ap, Y1.y);
            }
        }
    }

    // flush: reuse sBuf as sP[4][8][256]
    CP_WAIT0();
    __syncthreads();
    float* sP = sBuf;   // sP(warp,k,d) = sBuf[warp*2048 + k*256 + d]
    #pragma unroll
    for (int k = 0; k < 8; k++) {
        float x, y;
        float* dst = sP + warp * 2048 + k * 256;
        upk2(P[k][0], x, y); dst[4 * lane] = x;       dst[4 * lane + 1] = y;
        upk2(P[k][1], x, y); dst[4 * lane + 2] = x;   dst[4 * lane + 3] = y;
        upk2(P[k][2], x, y); dst[128 + 4 * lane] = x; dst[128 + 4 * lane + 1] = y;
        upk2(P[k][3], x, y); dst[128 + 4 * lane + 2] = x; dst[128 + 4 * lane + 3] = y;
    }
    if (lane < 8) { sSA[warp][slane] = SAl; sSW[warp][slane] = SWl; }
    __syncthreads();
    for (int t = threadIdx.x; t < 2048; t += 128) {
        int k = t >> 8, d = t & 255;
        float v = (sP[0 * 2048 + k * 256 + d] + sP[1 * 2048 + k * 256 + d]) +
                  (sP[2 * 2048 + k * 256 + d] + sP[3 * 2048 + k * 256 + d]);
        atomicAdd(&g_P[(size_t)(r8 + k) * 256 + d], v);
    }
    if (threadIdx.x < 8) {
        int k = threadIdx.x;
        atomicAdd(&g_SA[r8 + k], (sSA[0][k] + sSA[1][k]) + (sSA[2][k] + sSA[3][k]));
    } else if (threadIdx.x < 16) {
        int k = threadIdx.x - 8;
        atomicAdd(&g_SW[r8 + k], (sSW[0][k] + sSW[1][k]) + (sSW[2][k] + sSW[3][k]));
    }
}

// =================== kSlotB: packed-weight GEMV stages ===================
__global__ void __launch_bounds__(1024) kSlotB(const float* __restrict__ gg, const float* __restrict__ gb,
                                               const float* __restrict__ bv,
                                               const float* __restrict__ b_ih, const float* __restrict__ b_hh,
                                               const float* __restrict__ lnf_g, const float* __restrict__ lnf_b,
                                               const float* __restrict__ b1, const float* __restrict__ b2,
                                               const float* __restrict__ ls_g, const float* __restrict__ ls_b,
                                               int last, float* __restrict__ out_slots) {
    __shared__ float sA[4][256];
    __shared__ float sB[4][256];
    __shared__ float sSL[4][256];
    __shared__ float sF1[4][512];
    __shared__ float sRed[4096];
    int j = threadIdx.x & 255, q = threadIdx.x >> 8;
    int r0 = blockIdx.x * 4;
    int row = r0 + q;

    float snorm;
    {
        float SA = g_SA[row], SW = g_SW[row];
        float inv = 1.0f / (SA + EPSA);
        float Pv = g_P[(size_t)row * 256 + j];
        sA[q][j] = (gg[j] * (Pv - SW) + gb[j] * SA) * inv;
        sSL[q][j] = g_slots[(size_t)row * 256 + j];
        snorm = SA * inv;
    }
    __syncthreads();

    {
        float acc[4] = {0.f, 0.f, 0.f, 0.f};
        gemvPQ(g_WvP, 256, 16, 16 * q, &sA[0][0], 256, j, acc);
        float x = reduceWave(acc, sRed, q, j);
        sB[q][j] = fmaf(snorm, bv[j], x);
    }
    __syncthreads();

    float ir, iz, inn;
    {
        float pir[4] = {}, piz[4] = {}, pin[4] = {};
        const float4* pw = (const float4*)g_WihP + (size_t)(16 * q) * 768 + j;
        #pragma unroll 2
        for (int bq_ = 0; bq_ < 16; bq_++) {
            float4 wr = pw[(size_t)bq_ * 768];
            float4 wz = pw[(size_t)bq_ * 768 + 256];
            float4 wn = pw[(size_t)bq_ * 768 + 512];
            #pragma unroll
            for (int r = 0; r < 4; r++) {
                float4 x = *(const float4*)(&sB[r][64 * q + 4 * bq_]);
                pir[r] = fmaf(x.x, wr.x, fmaf(x.y, wr.y, fmaf(x.z, wr.z, fmaf(x.w, wr.w, pir[r]))));
                piz[r] = fmaf(x.x, wz.x, fmaf(x.y, wz.y, fmaf(x.z, wz.z, fmaf(x.w, wz.w, piz[r]))));
                pin[r] = fmaf(x.x, wn.x, fmaf(x.y, wn.y, fmaf(x.z, wn.z, fmaf(x.w, wn.w, pin[r]))));
            }
        }
        ir  = reduceWave(pir, sRed, q, j);
        iz  = reduceWave(piz, sRed, q, j);
        inn = reduceWave(pin, sRed, q, j);
    }
    float hr, hz, hn;
    {
        float phr[4] = {}, phz[4] = {}, phn[4] = {};
        const float4* pw = (const float4*)g_WhhP + (size_t)(16 * q) * 768 + j;
        #pragma unroll 2
        for (int bq_ = 0; bq_ < 16; bq_++) {
            float4 wr = pw[(size_t)bq_ * 768];
            float4 wz = pw[(size_t)bq_ * 768 + 256];
            float4 wn = pw[(size_t)bq_ * 768 + 512];
            #pragma unroll
            for (int r = 0; r < 4; r++) {
                float4 x = *(const float4*)(&sSL[r][64 * q + 4 * bq_]);
                phr[r] = fmaf(x.x, wr.x, fmaf(x.y, wr.y, fmaf(x.z, wr.z, fmaf(x.w, wr.w, phr[r]))));
                phz[r] = fmaf(x.x, wz.x, fmaf(x.y, wz.y, fmaf(x.z, wz.z, fmaf(x.w, wz.w, phz[r]))));
                phn[r] = fmaf(x.x, wn.x, fmaf(x.y, wn.y, fmaf(x.z, wn.z, fmaf(x.w, wn.w, phn[r]))));
            }
        }
        hr = reduceWave(phr, sRed, q, j);
        hz = reduceWave(phz, sRed, q, j);
        hn = reduceWave(phn, sRed, q, j);
    }

    float h_reg;
    {
        float rr = 1.0f / (1.0f + __expf(-(ir + b_ih[j] + hr + b_hh[j])));
        float zz = 1.0f / (1.0f + __expf(-(iz + b_ih[256 + j] + hz + b_hh[256 + j])));
        float nn = tanhf(inn + b_ih[512 + j] + rr * (hn + b_hh[512 + j]));
        float h = (1.0f - zz) * nn + zz * sSL[q][j];
        h_reg = h;
        float a = h, bb = h * h;
        grpReduce2(a, bb);
        float m = a * (1.0f / 256.0f);
        float var = bb * (1.0f / 256.0f) - m * m;
        float rs = rsqrtf(var + EPSLN);
        __syncthreads();
        sA[q][j] = (h - m) * rs * lnf_g[j] + lnf_b[j];
    }
    __syncthreads();

    {
        float f0[4] = {}, f1v[4] = {};
        const float4* p1 = (const float4*)g_W1P + (size_t)(16 * q) * 512 + j;
        #pragma unroll 2
        for (int bq_ = 0; bq_ < 16; bq_++) {
            float4 wa = p1[(size_t)bq_ * 512];
            float4 wb4 = p1[(size_t)bq_ * 512 + 256];
            #pragma unroll
            for (int r = 0; r < 4; r++) {
                float4 x = *(const float4*)(&sA[r][64 * q + 4 * bq_]);
                f0[r]  = fmaf(x.x, wa.x,  fmaf(x.y, wa.y,  fmaf(x.z, wa.z,  fmaf(x.w, wa.w,  f0[r]))));
                f1v[r] = fmaf(x.x, wb4.x, fmaf(x.y, wb4.y, fmaf(x.z, wb4.z, fmaf(x.w, wb4.w, f1v[r]))));
            }
        }
        float h0 = reduceWave(f0, sRed, q, j);
        float h1 = reduceWave(f1v, sRed, q, j);
        sF1[q][j]       = fmaxf(h0 + b1[j], 0.f);
        sF1[q][256 + j] = fmaxf(h1 + b1[256 + j], 0.f);
    }
    __syncthreads();

    float ns;
    {
        float o[4] = {0.f, 0.f, 0.f, 0.f};
        gemvPQ(g_W2P, 256, 32, 32 * q, &sF1[0][0], 512, j, o);
        float oo = reduceWave(o, sRed, q, j);
        ns = h_reg + oo + b2[j];
        g_slots[(size_t)row * 256 + j] = ns;
        if (last) out_slots[(size_t)row * 256 + j] = ns;
    }

    if (!last) {
        float a = ns, bb = ns * ns;
        grpReduce2(a, bb);
        float m = a * (1.0f / 256.0f);
        float var = bb * (1.0f / 256.0f) - m * m;
        float rs = rsqrtf(var + EPSLN);
        __syncthreads();
        sB[q][j] = (ns - m) * rs * ls_g[j] + ls_b[j];
        __syncthreads();
        slotABody((const float (*)[256])sB, sRed, r0, q, j, gg, gb);
    }
}

// ---------------- launch ----------------
extern "C" void kernel_launch(void* const* d_in, const int* in_sizes, int n_in,
                              void* d_out, int out_size) {
    (void)in_sizes; (void)n_in; (void)out_size;
    const float* inputs  = (const float*)d_in[0];
    const float* noise   = (const float*)d_in[1];
    const float* slot_mu = (const float*)d_in[2];
    const float* slot_ls = (const float*)d_in[3];
    const float* Wq      = (const float*)d_in[4];
    const float* bq      = (const float*)d_in[5];
    const float* Wk      = (const float*)d_in[6];
    const float* bk      = (const float*)d_in[7];
    const float* Wv      = (const float*)d_in[8];
    const float* bv      = (const float*)d_in[9];
    const float* W_ih    = (const float*)d_in[10];
    const float* b_ih    = (const float*)d_in[11];
    const float* W_hh    = (const float*)d_in[12];
    const float* b_hh    = (const float*)d_in[13];
    const float* ln_in_g = (const float*)d_in[14];
    const float* ln_in_b = (const float*)d_in[15];
    const float* ln_s_g  = (const float*)d_in[16];
    const float* ln_s_b  = (const float*)d_in[17];
    const float* ln_ff_g = (const float*)d_in[18];
    const float* ln_ff_b = (const float*)d_in[19];
    const float* W1      = (const float*)d_in[20];
    const float* b1      = (const float*)d_in[21];
    const float* W2      = (const float*)d_in[22];
    const float* b2      = (const float*)d_in[23];

    float* out = (float*)d_out;
    float* out_slots = out;
    float* out_attn  = out + BK_ * D_;

    kSetup<<<1475, 256>>>(W_ih, W_hh, Wv, W1, W2, noise, slot_mu, slot_ls, Wq, Wk, bq, bk);
    kSlotA<<<128, 1024>>>(ln_s_g, ln_s_b, ln_in_g, ln_in_b);

    for (int it = 0; it < 3; it++) {
        int last = (it == 2);
        kFA<<<dim3(8, 64), 128>>>(inputs, last, out_attn);
        kSlotB<<<128, 1024>>>(ln_in_g, ln_in_b, bv, b_ih, b_hh,
                              ln_ff_g, ln_ff_b, b1, b2, ln_s_g, ln_s_b,
                              last, out_slots);
    }
}